// round 13
// baseline (speedup 1.0000x reference)
#include <cuda_runtime.h>
#include <cuda_fp16.h>
#include <math.h>
#include <stdint.h>

#define NN 50000
#define EE 800000
#define BB 256
#define DD 128
#define TT 8
#define KV_OFF (BB*TT*DD)

// ---------------- scratch (no allocations allowed) ----------------
__device__ __half g_h16[(size_t)NN*DD];     // post-attention node states (fp16)
__device__ __half g_KV16[2*BB*TT*DD];       // Kc then Vc (fp16)
__device__ float  g_lip[BB*9];              // lattice inner products
__device__ float  g_agg[(size_t)NN*DD];     // scatter sums (fp32 atomics)
__device__ int    g_cnt[NN];                // scatter counts
// pre-converted, pre-transposed fp16 weights [N][K]
__device__ __half g_ew1T[DD*288];           // K padded 272->288
__device__ __half g_ew2T[DD*DD];
__device__ __half g_nw1T[DD*256];
__device__ __half g_nw2T[DD*DD];
__device__ __half g_wqT[DD*DD];
__device__ __half g_woT[DD*DD];
__device__ __half g_sw1T[DD*32];            // K padded 24->32
__device__ __half g_sw2h[8*DD];             // sw2 transposed [8][128] fp16

__device__ __forceinline__ float silu_f(float x) {
    return __fdividef(x, 1.f + __expf(-x));
}

// fp16 mma, fp32 accumulate
__device__ __forceinline__ void mma_f16(float* c, const uint32_t* a, const uint32_t* b) {
    asm volatile(
        "mma.sync.aligned.m16n8k16.row.col.f32.f16.f16.f32 "
        "{%0,%1,%2,%3}, {%4,%5,%6,%7}, {%8,%9}, {%0,%1,%2,%3};\n"
        : "+f"(c[0]), "+f"(c[1]), "+f"(c[2]), "+f"(c[3])
        : "r"(a[0]), "r"(a[1]), "r"(a[2]), "r"(a[3]), "r"(b[0]), "r"(b[1]));
}

__device__ __forceinline__ void cpa16(void* dst, const void* src) {
    uint32_t d = (uint32_t)__cvta_generic_to_shared(dst);
    asm volatile("cp.async.cg.shared.global [%0], [%1], 16;" :: "r"(d), "l"(src));
}
#define CP_COMMIT asm volatile("cp.async.commit_group;" ::: "memory")
#define CP_WAIT0  asm volatile("cp.async.wait_group 0;" ::: "memory")

// ldmatrix x4
__device__ __forceinline__ void ldsm4(uint32_t* r, const __half* p) {
    uint32_t a = (uint32_t)__cvta_generic_to_shared(p);
    asm volatile("ldmatrix.sync.aligned.m8n8.x4.shared.b16 {%0,%1,%2,%3}, [%4];"
        : "=r"(r[0]), "=r"(r[1]), "=r"(r[2]), "=r"(r[3]) : "r"(a));
}
#define LDSMA(afr, base, SAx, rowbase, kg)                                        \
    ldsm4(afr, (base) + ((rowbase) + (lane & 15))*(SAx) + (kg) + ((lane >> 4) << 3))
#define LDSMB2(b4, bB, SBx, ncol, kk)                                             \
    ldsm4(b4, (bB) + ((ncol) + (lane & 7) + ((lane >> 4) << 3))*(SBx) + (kk) + (((lane >> 3) & 1) << 3))

// B buffer geometry (attn/node streamed path): 128 n-rows x (32 k + 8 pad)
#define SBh 40
#define BHB (128*SBh)

// ---------------- kernel 1: K/V projection + lattice gram ----------------
__global__ void prep_kernel(const float* __restrict__ cond,
                            const float* __restrict__ wk, const float* __restrict__ bk,
                            const float* __restrict__ wv, const float* __restrict__ bv,
                            const float* __restrict__ lat)
{
    int b = blockIdx.x;
    if (b < BB*TT) {
        __shared__ float s_c[DD];
        int d = threadIdx.x;
        s_c[d] = cond[b*DD + d];
        __syncthreads();
        float ka = bk[d], va = bv[d];
        #pragma unroll 8
        for (int k = 0; k < DD; k++) {
            float c = s_c[k];
            ka = fmaf(c, wk[k*DD + d], ka);
            va = fmaf(c, wv[k*DD + d], va);
        }
        g_KV16[b*DD + d] = __float2half(ka);
        g_KV16[KV_OFF + b*DD + d] = __float2half(va);
    } else {
        int bb = b - BB*TT;
        int t = threadIdx.x;
        if (t < 9) {
            int i = t / 3, k2 = t % 3;
            const float* L = lat + bb*9;
            g_lip[bb*9 + t] = L[i*3+0]*L[k2*3+0] + L[i*3+1]*L[k2*3+1] + L[i*3+2]*L[k2*3+2];
        }
    }
}

// ---------------- kernel 1b: convert+transpose weights ----------------
__global__ void convw_kernel(const float* __restrict__ ew1, const float* __restrict__ ew2,
                             const float* __restrict__ nw1, const float* __restrict__ nw2,
                             const float* __restrict__ wq,  const float* __restrict__ wo,
                             const float* __restrict__ sw1, const float* __restrict__ sw2)
{
    int idx = blockIdx.x * 256 + threadIdx.x;
    if (idx < 36864) {
        int n = idx / 288, k = idx % 288;
        g_ew1T[idx] = (k < 268) ? __float2half(ew1[k*DD + n]) : __half(0.f);
    } else if (idx < 53248) {
        int j = idx - 36864; int n = j / DD, k = j % DD;
        g_ew2T[j] = __float2half(ew2[k*DD + n]);
    } else if (idx < 86016) {
        int j = idx - 53248; int n = j / 256, k = j % 256;
        g_nw1T[j] = __float2half(nw1[k*DD + n]);
    } else if (idx < 102400) {
        int j = idx - 86016; int n = j / DD, k = j % DD;
        g_nw2T[j] = __float2half(nw2[k*DD + n]);
    } else if (idx < 118784) {
        int j = idx - 102400; int n = j / DD, k = j % DD;
        g_wqT[j] = __float2half(wq[k*DD + n]);
    } else if (idx < 135168) {
        int j = idx - 118784; int n = j / DD, k = j % DD;
        g_woT[j] = __float2half(wo[k*DD + n]);
    } else if (idx < 139264) {
        int j = idx - 135168; int n = j / 32, k = j % 32;
        g_sw1T[j] = (k < 24) ? __float2half(sw1[k*DD + n]) : __half(0.f);
    } else if (idx < 140288) {
        int j = idx - 139264; int t = j >> 7, k = j & 127;
        g_sw2h[j] = __float2half(sw2[k*8 + t]);
    }
}

// ---------------- kernel 2: zero scatter buffers ----------------
__global__ void zero_kernel()
{
    int idx = blockIdx.x * blockDim.x + threadIdx.x;
    if (idx < NN*DD) g_agg[idx] = 0.f;
    if (idx < NN)    g_cnt[idx] = 0;
}

// ---------------- kernel 3: cross-attention (unchanged from R12) ----------------
#define AT 64
#define SQh 136
#define SBW2 136

__global__ __launch_bounds__(256, 2)
void attn_kernel(const float* __restrict__ nfeat, const float* __restrict__ frac,
                 const int* __restrict__ n2g,
                 const float* __restrict__ bq, const float* __restrict__ bo,
                 const float* __restrict__ sb1, const float* __restrict__ sb2)
{
    extern __shared__ char smraw[];
    __half* s_h    = (__half*)smraw;
    __half* s_hid  = s_h + AT*SQh;
    __half* s_q    = s_hid + AT*SQh;
    __half* s_bsw  = s_q + AT*SQh;
    __half* s_bb   = s_bsw + 128*SBh;
    __half* s_enc  = s_bb + 2*BHB;
    __half* s_sw2h = s_enc + AT*40;
    float*  s_sb1 = (float*)(s_sw2h + 8*SBW2);
    float*  s_sb2 = s_sb1 + 128;
    float*  s_att = s_sb2 + 8;
    __shared__ int s_g[AT];

    int tid = threadIdx.x, lane = tid & 31, wid = tid >> 5;
    int wm = wid >> 2, wn = wid & 3;
    int n0 = blockIdx.x * AT;
    int bn = tid >> 1, bseg = (tid & 1) * 16;

    if (tid < AT) s_g[tid] = n2g[min(n0 + tid, NN - 1)];

    cpa16(s_bsw + bn*SBh + bseg,     g_sw1T + bn*32 + bseg);
    cpa16(s_bsw + bn*SBh + bseg + 8, g_sw1T + bn*32 + bseg + 8);
    if (tid < 128) {
        int row = tid >> 4, seg = (tid & 15) * 8;
        cpa16(s_sw2h + row*SBW2 + seg, g_sw2h + row*DD + seg);
    }
    if (tid < 32) cpa16(s_sb1 + tid*4, sb1 + tid*4);
    if (tid < 2)  cpa16(s_sb2 + tid*4, sb2 + tid*4);
    cpa16(s_bb + bn*SBh + bseg,     g_wqT + bn*DD + bseg);
    cpa16(s_bb + bn*SBh + bseg + 8, g_wqT + bn*DD + bseg + 8);
    CP_COMMIT;

    #pragma unroll
    for (int it = 0; it < 8; it++) {
        int idx = tid + it*256;
        int r = idx >> 5, c4 = (idx & 31) * 4;
        int n = min(n0 + r, NN - 1);
        float4 v = *(const float4*)(nfeat + (size_t)n*DD + c4);
        __half* dst = s_h + r*SQh + c4;
        *(__half2*)(dst)     = __floats2half2_rn(v.x, v.y);
        *(__half2*)(dst + 2) = __floats2half2_rn(v.z, v.w);
    }
    {
        int n = tid >> 2, sub = tid & 3;
        int nn = min(n0 + n, NN - 1);
        float f0 = frac[nn*3+0], f1 = frac[nn*3+1], f2 = frac[nn*3+2];
        #pragma unroll
        for (int k = sub; k < 24; k += 4) {
            int ii = k % 12, c = ii >> 2, j = ii & 3;
            float fv = (c == 0) ? f0 : ((c == 1) ? f1 : f2);
            float ph = fv * ((float)(1 << j) * 3.14159265358979323846f);
            s_enc[n*40 + k] = __float2half((k < 12) ? sinf(ph) : cosf(ph));
        }
        s_enc[n*40 + 24 + sub] = __half(0.f);
        s_enc[n*40 + 28 + sub] = __half(0.f);
    }
    CP_WAIT0;
    __syncthreads();

    float acc[2][4][4];
    #pragma unroll
    for (int mf = 0; mf < 2; mf++)
        #pragma unroll
        for (int nf = 0; nf < 4; nf++)
            #pragma unroll
            for (int u = 0; u < 4; u++) acc[mf][nf][u] = 0.f;

    #pragma unroll
    for (int kk = 0; kk < 32; kk += 16) {
        uint32_t afr[2][4];
        #pragma unroll
        for (int mf = 0; mf < 2; mf++) LDSMA(afr[mf], s_enc, 40, wm*32 + mf*16, kk);
        uint32_t bfr[4][2];
        LDSMB2(bfr[0], s_bsw, SBh, wn*32, kk);
        LDSMB2(bfr[2], s_bsw, SBh, wn*32 + 16, kk);
        #pragma unroll
        for (int mf = 0; mf < 2; mf++)
            #pragma unroll
            for (int nf = 0; nf < 4; nf++)
                mma_f16(acc[mf][nf], afr[mf], bfr[nf]);
    }
    #pragma unroll
    for (int mf = 0; mf < 2; mf++) {
        int r0 = wm*32 + mf*16 + (lane >> 2);
        #pragma unroll
        for (int nf = 0; nf < 4; nf++) {
            int n = wn*32 + nf*8 + (lane & 3)*2;
            float b0 = s_sb1[n], b1 = s_sb1[n + 1];
            *(__half2*)(s_hid + r0*SQh + n) =
                __floats2half2_rn(silu_f(acc[mf][nf][0] + b0), silu_f(acc[mf][nf][1] + b1));
            *(__half2*)(s_hid + (r0 + 8)*SQh + n) =
                __floats2half2_rn(silu_f(acc[mf][nf][2] + b0), silu_f(acc[mf][nf][3] + b1));
            #pragma unroll
            for (int u = 0; u < 4; u++) acc[mf][nf][u] = 0.f;
        }
    }

    for (int ct = 0; ct < 4; ct++) {
        __half* dbuf = s_bb + ((ct+1)&1)*BHB;
        const __half* src = (ct < 3) ? (g_wqT + (ct+1)*32) : g_woT;
        cpa16(dbuf + bn*SBh + bseg,     src + bn*DD + bseg);
        cpa16(dbuf + bn*SBh + bseg + 8, src + bn*DD + bseg + 8);
        CP_COMMIT;
        const __half* bB = s_bb + (ct & 1)*BHB;
        #pragma unroll
        for (int kk = 0; kk < 32; kk += 16) {
            int kg = ct*32 + kk;
            uint32_t afr[2][4];
            #pragma unroll
            for (int mf = 0; mf < 2; mf++) LDSMA(afr[mf], s_h, SQh, wm*32 + mf*16, kg);
            uint32_t bfr[4][2];
            LDSMB2(bfr[0], bB, SBh, wn*32, kk);
            LDSMB2(bfr[2], bB, SBh, wn*32 + 16, kk);
            #pragma unroll
            for (int mf = 0; mf < 2; mf++)
                #pragma unroll
                for (int nf = 0; nf < 4; nf++)
                    mma_f16(acc[mf][nf], afr[mf], bfr[nf]);
        }
        CP_WAIT0;
        __syncthreads();
    }
    #pragma unroll
    for (int mf = 0; mf < 2; mf++) {
        int r0 = wm*32 + mf*16 + (lane >> 2);
        #pragma unroll
        for (int nf = 0; nf < 4; nf++) {
            int n = wn*32 + nf*8 + (lane & 3)*2;
            float b0 = bq[n], b1 = bq[n + 1];
            *(__half2*)(s_q + r0*SQh + n) =
                __floats2half2_rn(acc[mf][nf][0] + b0, acc[mf][nf][1] + b1);
            *(__half2*)(s_q + (r0 + 8)*SQh + n) =
                __floats2half2_rn(acc[mf][nf][2] + b0, acc[mf][nf][3] + b1);
        }
    }
    __syncthreads();

    if (wid < 4) {
        float bacc[4] = {0.f, 0.f, 0.f, 0.f};
        #pragma unroll
        for (int kk = 0; kk < 128; kk += 16) {
            uint32_t afr[4];
            LDSMA(afr, s_hid, SQh, wid*16, kk);
            const __half* bp = s_sw2h + (lane >> 2)*SBW2 + kk + (lane & 3)*2;
            uint32_t bfr[2];
            bfr[0] = *(const uint32_t*)(bp);
            bfr[1] = *(const uint32_t*)(bp + 8);
            mma_f16(bacc, afr, bfr);
        }
        int r0 = wid*16 + (lane >> 2);
        int t = (lane & 3)*2;
        s_att[r0*8 + t]         = bacc[0];
        s_att[r0*8 + t + 1]     = bacc[1];
        s_att[(r0 + 8)*8 + t]     = bacc[2];
        s_att[(r0 + 8)*8 + t + 1] = bacc[3];
    }
    __syncthreads();

    {
        int n = tid >> 2, sub = tid & 3;
        int gg = s_g[n];
        int t0 = sub*2, t1 = t0 + 1;
        const __half2* K0 = (const __half2*)(g_KV16 + (size_t)(gg*TT + t0)*DD);
        const __half2* K1 = (const __half2*)(g_KV16 + (size_t)(gg*TT + t1)*DD);
        const __half2* qq = (const __half2*)(s_q + n*SQh);
        float sc0 = 0.f, sc1 = 0.f;
        #pragma unroll 8
        for (int k2 = 0; k2 < 64; k2++) {
            float2 q = __half22float2(qq[k2]);
            float2 a = __half22float2(K0[k2]);
            float2 b = __half22float2(K1[k2]);
            sc0 = fmaf(q.x, a.x, sc0); sc0 = fmaf(q.y, a.y, sc0);
            sc1 = fmaf(q.x, b.x, sc1); sc1 = fmaf(q.y, b.y, sc1);
        }
        float v0 = sc0 * 0.08838834764831845f + s_att[n*8 + t0] + s_sb2[t0];
        float v1 = sc1 * 0.08838834764831845f + s_att[n*8 + t1] + s_sb2[t1];
        float m = fmaxf(v0, v1);
        m = fmaxf(m, __shfl_xor_sync(0xffffffffu, m, 1, 4));
        m = fmaxf(m, __shfl_xor_sync(0xffffffffu, m, 2, 4));
        float e0 = __expf(v0 - m), e1 = __expf(v1 - m);
        float s = e0 + e1;
        s += __shfl_xor_sync(0xffffffffu, s, 1, 4);
        s += __shfl_xor_sync(0xffffffffu, s, 2, 4);
        float inv = __fdividef(1.f, s);
        s_att[n*8 + t0] = e0 * inv;
        s_att[n*8 + t1] = e1 * inv;
    }
    __syncthreads();

    #pragma unroll
    for (int it = 0; it < 16; it++) {
        int idx = tid + it*256;
        int n = idx >> 6, c = (idx & 63) * 2;
        const __half* Vr = g_KV16 + KV_OFF + (size_t)s_g[n]*TT*DD + c;
        const float* at = s_att + n*8;
        float a0 = 0.f, a1 = 0.f;
        #pragma unroll
        for (int t = 0; t < 8; t++) {
            float2 v = __half22float2(*(const __half2*)(Vr + t*DD));
            a0 = fmaf(at[t], v.x, a0);
            a1 = fmaf(at[t], v.y, a1);
        }
        *(__half2*)(s_q + n*SQh + c) = __floats2half2_rn(a0, a1);
    }
    __syncthreads();

    float acc2[2][4][4];
    #pragma unroll
    for (int mf = 0; mf < 2; mf++)
        #pragma unroll
        for (int nf = 0; nf < 4; nf++)
            #pragma unroll
            for (int u = 0; u < 4; u++) acc2[mf][nf][u] = 0.f;

    for (int c = 0; c < 4; c++) {
        if (c < 3) {
            __half* dbuf = s_bb + ((c+1)&1)*BHB;
            const __half* src = g_woT + (c+1)*32;
            cpa16(dbuf + bn*SBh + bseg,     src + bn*DD + bseg);
            cpa16(dbuf + bn*SBh + bseg + 8, src + bn*DD + bseg + 8);
            CP_COMMIT;
        }
        const __half* bB = s_bb + (c & 1)*BHB;
        #pragma unroll
        for (int kk = 0; kk < 32; kk += 16) {
            int kg = c*32 + kk;
            uint32_t afr[2][4];
            #pragma unroll
            for (int mf = 0; mf < 2; mf++) LDSMA(afr[mf], s_q, SQh, wm*32 + mf*16, kg);
            uint32_t bfr[4][2];
            LDSMB2(bfr[0], bB, SBh, wn*32, kk);
            LDSMB2(bfr[2], bB, SBh, wn*32 + 16, kk);
            #pragma unroll
            for (int mf = 0; mf < 2; mf++)
                #pragma unroll
                for (int nf = 0; nf < 4; nf++)
                    mma_f16(acc2[mf][nf], afr[mf], bfr[nf]);
        }
        if (c < 3) { CP_WAIT0; }
        __syncthreads();
    }

    #pragma unroll
    for (int mf = 0; mf < 2; mf++) {
        #pragma unroll
        for (int rr = 0; rr < 2; rr++) {
            int m = wm*32 + mf*16 + (lane >> 2) + rr*8;
            int n = n0 + m;
            if (n < NN) {
                __half* orow = g_h16 + (size_t)n*DD;
                const __half* hrow = s_h + m*SQh;
                #pragma unroll
                for (int nf = 0; nf < 4; nf++) {
                    int col = wn*32 + nf*8 + (lane & 3)*2;
                    float v0 = __half2float(hrow[col])     + acc2[mf][nf][rr*2 + 0] + bo[col];
                    float v1 = __half2float(hrow[col + 1]) + acc2[mf][nf][rr*2 + 1] + bo[col + 1];
                    *(__half2*)(orow + col) = __floats2half2_rn(v0, v1);
                }
            }
        }
    }
}

// ---------------- kernel 4: PERSISTENT edge MLP, weights resident in smem ----------------
// grid=148, 512 threads = 16 warps (4 wm x 4 wn), warp tile 32x32 (mf=2, nf=4).
// smem (halfs): w1[128][296] | w2[128][136] | a[128][296] | hid[128][136] = 221,184 B
#define TM 128
#define SAh 296
#define SHh 136
#define W1OFF 0
#define W2OFF 37888
#define AOFF  55296
#define HOFF  93184

__global__ __launch_bounds__(512, 1)
void edge_kernel(const float* __restrict__ frac,
                 const int* __restrict__ edges, const int* __restrict__ e2g,
                 const float* __restrict__ eb1, const float* __restrict__ eb2)
{
    extern __shared__ __half smh[];
    __half* s_w1  = smh + W1OFF;
    __half* s_w2  = smh + W2OFF;
    __half* s_a   = smh + AOFF;
    __half* s_hid = smh + HOFF;
    __shared__ int s_i[TM], s_j[TM];

    int tid  = threadIdx.x, lane = tid & 31, wid = tid >> 5;
    int wm = wid >> 2, wn = wid & 3;

    // resident weights (once): ew1T [128][288] -> stride 296, ew2T [128][128] -> stride 136
    for (int i = tid; i < 4608; i += 512) {
        int row = i / 36, seg = i % 36;
        cpa16(s_w1 + row*SAh + seg*8, g_ew1T + row*288 + seg*8);
    }
    for (int i = tid; i < 2048; i += 512) {
        int row = i >> 4, seg = i & 15;
        cpa16(s_w2 + row*SHh + seg*8, g_ew2T + row*DD + seg*8);
    }
    CP_COMMIT;

    for (int tile = blockIdx.x; tile < EE/TM; tile += gridDim.x) {
        int e0 = tile * TM;
        if (tid < TM) {
            s_i[tid] = edges[e0 + tid];
            s_j[tid] = edges[EE + e0 + tid];
        }
        __syncthreads();

        // gather A rows: 128 edges x 2 nodes x 16 segs = 4096 cpa16 over 512 threads
        #pragma unroll
        for (int it = 0; it < 8; it++) {
            int idx = tid + it*512;
            int r = idx >> 4, seg = idx & 15;
            int e = r >> 1, p = r & 1;
            int node = p ? s_j[e] : s_i[e];
            cpa16(s_a + e*SAh + p*DD + seg*8, g_h16 + (size_t)node*DD + seg*8);
        }
        CP_COMMIT;

        // tail cols 256..287 + counts
        if (tid < TM) {
            int e = tid;
            const float* lp = g_lip + e2g[e0 + e]*9;
            #pragma unroll
            for (int u = 0; u < 9; u++) s_a[e*SAh + 256 + u] = __float2half(lp[u]);
            int ii = s_i[e], jj = s_j[e];
            #pragma unroll
            for (int c = 0; c < 3; c++) {
                float dd = frac[jj*3 + c] - frac[ii*3 + c];
                dd -= floorf(dd);
                s_a[e*SAh + 265 + c] = __float2half(dd);
            }
            #pragma unroll
            for (int u = 268; u < 288; u++) s_a[e*SAh + u] = __half(0.f);
            atomicAdd(&g_cnt[ii], 1);
        }
        CP_WAIT0;
        __syncthreads();

        float acc[2][4][4];
        #pragma unroll
        for (int mf = 0; mf < 2; mf++)
            #pragma unroll
            for (int nf = 0; nf < 4; nf++)
                #pragma unroll
                for (int u = 0; u < 4; u++) acc[mf][nf][u] = 0.f;

        // ---- GEMM1: K=288, 18 uninterrupted k16 steps ----
        #pragma unroll 6
        for (int kg = 0; kg < 288; kg += 16) {
            uint32_t afr[2][4];
            #pragma unroll
            for (int mf = 0; mf < 2; mf++) LDSMA(afr[mf], s_a, SAh, wm*32 + mf*16, kg);
            uint32_t bfr[4][2];
            LDSMB2(bfr[0], s_w1, SAh, wn*32, kg);
            LDSMB2(bfr[2], s_w1, SAh, wn*32 + 16, kg);
            #pragma unroll
            for (int mf = 0; mf < 2; mf++)
                #pragma unroll
                for (int nf = 0; nf < 4; nf++)
                    mma_f16(acc[mf][nf], afr[mf], bfr[nf]);
        }

        // hidden = silu(acc + eb1) -> s_hid
        #pragma unroll
        for (int mf = 0; mf < 2; mf++) {
            int r0 = wm*32 + mf*16 + (lane >> 2);
            #pragma unroll
            for (int nf = 0; nf < 4; nf++) {
                int n = wn*32 + nf*8 + (lane & 3)*2;
                float b0 = eb1[n], b1 = eb1[n + 1];
                *(__half2*)(s_hid + r0*SHh + n) =
                    __floats2half2_rn(silu_f(acc[mf][nf][0] + b0), silu_f(acc[mf][nf][1] + b1));
                *(__half2*)(s_hid + (r0 + 8)*SHh + n) =
                    __floats2half2_rn(silu_f(acc[mf][nf][2] + b0), silu_f(acc[mf][nf][3] + b1));
                #pragma unroll
                for (int u = 0; u < 4; u++) acc[mf][nf][u] = 0.f;
            }
        }
        __syncthreads();

        // ---- GEMM2: K=128, 8 k16 steps ----
        #pragma unroll
        for (int kg = 0; kg < 128; kg += 16) {
            uint32_t afr[2][4];
            #pragma unroll
            for (int mf = 0; mf < 2; mf++) LDSMA(afr[mf], s_hid, SHh, wm*32 + mf*16, kg);
            uint32_t bfr[4][2];
            LDSMB2(bfr[0], s_w2, SHh, wn*32, kg);
            LDSMB2(bfr[2], s_w2, SHh, wn*32 + 16, kg);
            #pragma unroll
            for (int mf = 0; mf < 2; mf++)
                #pragma unroll
                for (int nf = 0; nf < 4; nf++)
                    mma_f16(acc[mf][nf], afr[mf], bfr[nf]);
        }

        // epilogue: silu + bias, red.v2 scatter into g_agg (fp32)
        #pragma unroll
        for (int mf = 0; mf < 2; mf++) {
            #pragma unroll
            for (int rr = 0; rr < 2; rr++) {
                int m = wm*32 + mf*16 + (lane >> 2) + rr*8;
                float* ap = g_agg + (size_t)s_i[m]*DD;
                #pragma unroll
                for (int nf = 0; nf < 4; nf++) {
                    int n = wn*32 + nf*8 + (lane & 3)*2;
                    float v0 = silu_f(acc[mf][nf][rr*2 + 0] + eb2[n]);
                    float v1 = silu_f(acc[mf][nf][rr*2 + 1] + eb2[n + 1]);
                    asm volatile("red.global.add.v2.f32 [%0], {%1, %2};"
                                 :: "l"(ap + n), "f"(v0), "f"(v1) : "memory");
                }
            }
        }
        __syncthreads();   // protect s_i/s_a before next tile
    }
}

// ---------------- kernel 5: node MLP (unchanged from R12) ----------------
#define TN 128
#define SAn 264

__global__ __launch_bounds__(256, 2)
void node_kernel(const float* __restrict__ nfeat,
                 const float* __restrict__ nb1, const float* __restrict__ nb2,
                 float* __restrict__ out)
{
    extern __shared__ __half smh[];
    __half* s_a  = smh;
    __half* s_bb = smh + TN*SAn;
    __shared__ float s_cnt[TN];

    int tid  = threadIdx.x, lane = tid & 31, wid = tid >> 5;
    int wm = wid >> 2, wn = wid & 3;
    int n0 = blockIdx.x * TN;
    int bn = tid >> 1, bseg = (tid & 1) * 16;

    if (tid < TN) {
        int n = min(n0 + tid, NN - 1);
        s_cnt[tid] = fmaxf((float)g_cnt[n], 1.f);
    }
    #pragma unroll
    for (int it = 0; it < 8; it++) {
        int idx = tid + it*256;
        int r = idx >> 4, seg = idx & 15;
        int n = min(n0 + r, NN - 1);
        cpa16(s_a + r*SAn + seg*8, g_h16 + (size_t)n*DD + seg*8);
    }
    cpa16(s_bb + bn*SBh + bseg,     g_nw1T + bn*256 + bseg);
    cpa16(s_bb + bn*SBh + bseg + 8, g_nw1T + bn*256 + bseg + 8);
    CP_COMMIT;
    __syncthreads();

    #pragma unroll
    for (int it = 0; it < 16; it++) {
        int idx = tid + it*256;
        int r = idx >> 5, c4 = (idx & 31) * 4;
        int n = min(n0 + r, NN - 1);
        float inv = __fdividef(1.f, s_cnt[r]);
        float4 v = *(const float4*)(g_agg + (size_t)n*DD + c4);
        __half* dst = s_a + r*SAn + DD + c4;
        *(__half2*)(dst)     = __floats2half2_rn(v.x * inv, v.y * inv);
        *(__half2*)(dst + 2) = __floats2half2_rn(v.z * inv, v.w * inv);
    }

    float acc[4][4][4];
    #pragma unroll
    for (int mf = 0; mf < 4; mf++)
        #pragma unroll
        for (int nf = 0; nf < 4; nf++)
            #pragma unroll
            for (int u = 0; u < 4; u++) acc[mf][nf][u] = 0.f;

    CP_WAIT0;
    __syncthreads();

    for (int ct = 0; ct < 8; ct++) {
        __half* dbuf = s_bb + ((ct+1)&1)*BHB;
        const __half* src; int rstr;
        if (ct < 7) { src = g_nw1T + (ct+1)*32; rstr = 256; }
        else        { src = g_nw2T;             rstr = 128; }
        cpa16(dbuf + bn*SBh + bseg,     src + (size_t)bn*rstr + bseg);
        cpa16(dbuf + bn*SBh + bseg + 8, src + (size_t)bn*rstr + bseg + 8);
        CP_COMMIT;
        const __half* bB = s_bb + (ct & 1)*BHB;
        #pragma unroll
        for (int kk = 0; kk < 32; kk += 16) {
            int kg = ct*32 + kk;
            uint32_t afr[4][4];
            #pragma unroll
            for (int mf = 0; mf < 4; mf++) LDSMA(afr[mf], s_a, SAn, wm*64 + mf*16, kg);
            uint32_t bfr[4][2];
            LDSMB2(bfr[0], bB, SBh, wn*32, kk);
            LDSMB2(bfr[2], bB, SBh, wn*32 + 16, kk);
            #pragma unroll
            for (int mf = 0; mf < 4; mf++)
                #pragma unroll
                for (int nf = 0; nf < 4; nf++)
                    mma_f16(acc[mf][nf], afr[mf], bfr[nf]);
        }
        CP_WAIT0;
        __syncthreads();
    }

    #pragma unroll
    for (int mf = 0; mf < 4; mf++) {
        int r0 = wm*64 + mf*16 + (lane >> 2);
        #pragma unroll
        for (int nf = 0; nf < 4; nf++) {
            int n = wn*32 + nf*8 + (lane & 3)*2;
            float b0 = nb1[n], b1 = nb1[n + 1];
            *(__half2*)(s_a + r0*SAn + n) =
                __floats2half2_rn(silu_f(acc[mf][nf][0] + b0), silu_f(acc[mf][nf][1] + b1));
            *(__half2*)(s_a + (r0 + 8)*SAn + n) =
                __floats2half2_rn(silu_f(acc[mf][nf][2] + b0), silu_f(acc[mf][nf][3] + b1));
            #pragma unroll
            for (int u = 0; u < 4; u++) acc[mf][nf][u] = 0.f;
        }
    }
    __syncthreads();

    for (int c = 0; c < 4; c++) {
        if (c < 3) {
            __half* dbuf = s_bb + ((c+1)&1)*BHB;
            const __half* src = g_nw2T + (c+1)*32;
            cpa16(dbuf + bn*SBh + bseg,     src + bn*DD + bseg);
            cpa16(dbuf + bn*SBh + bseg + 8, src + bn*DD + bseg + 8);
            CP_COMMIT;
        }
        const __half* bB = s_bb + (c & 1)*BHB;
        #pragma unroll
        for (int kk = 0; kk < 32; kk += 16) {
            int kg = c*32 + kk;
            uint32_t afr[4][4];
            #pragma unroll
            for (int mf = 0; mf < 4; mf++) LDSMA(afr[mf], s_a, SAn, wm*64 + mf*16, kg);
            uint32_t bfr[4][2];
            LDSMB2(bfr[0], bB, SBh, wn*32, kk);
            LDSMB2(bfr[2], bB, SBh, wn*32 + 16, kk);
            #pragma unroll
            for (int mf = 0; mf < 4; mf++)
                #pragma unroll
                for (int nf = 0; nf < 4; nf++)
                    mma_f16(acc[mf][nf], afr[mf], bfr[nf]);
        }
        if (c < 3) { CP_WAIT0; }
        __syncthreads();
    }

    #pragma unroll
    for (int mf = 0; mf < 4; mf++) {
        #pragma unroll
        for (int rr = 0; rr < 2; rr++) {
            int m = wm*64 + mf*16 + (lane >> 2) + rr*8;
            int n = n0 + m;
            if (n < NN) {
                const float* nfr = nfeat + (size_t)n*DD;
                float* orow = out + (size_t)n*DD;
                #pragma unroll
                for (int nf = 0; nf < 4; nf++) {
                    int col = wn*32 + nf*8 + (lane & 3)*2;
                    orow[col]     = nfr[col]     + silu_f(acc[mf][nf][rr*2 + 0] + nb2[col]);
                    orow[col + 1] = nfr[col + 1] + silu_f(acc[mf][nf][rr*2 + 1] + nb2[col + 1]);
                }
            }
        }
    }
}

// ---------------- launch ----------------
extern "C" void kernel_launch(void* const* d_in, const int* in_sizes, int n_in,
                              void* d_out, int out_size)
{
    const float* node_features = (const float*)d_in[0];
    const float* cond = (const float*)d_in[1];
    const int*   n2g  = (const int*)d_in[2];
    const float* frac = (const float*)d_in[3];
    const float* lat  = (const float*)d_in[4];
    const int*   edges= (const int*)d_in[5];
    const int*   e2g  = (const int*)d_in[6];
    const float* wq = (const float*)d_in[7];
    const float* bq = (const float*)d_in[8];
    const float* wk = (const float*)d_in[9];
    const float* bk = (const float*)d_in[10];
    const float* wv = (const float*)d_in[11];
    const float* bv = (const float*)d_in[12];
    const float* wo = (const float*)d_in[13];
    const float* bo = (const float*)d_in[14];
    const float* sw1= (const float*)d_in[15];
    const float* sb1= (const float*)d_in[16];
    const float* sw2= (const float*)d_in[17];
    const float* sb2= (const float*)d_in[18];
    const float* ew1= (const float*)d_in[19];
    const float* eb1= (const float*)d_in[20];
    const float* ew2= (const float*)d_in[21];
    const float* eb2= (const float*)d_in[22];
    const float* nw1= (const float*)d_in[23];
    const float* nb1= (const float*)d_in[24];
    const float* nw2= (const float*)d_in[25];
    const float* nb2= (const float*)d_in[26];
    float* out = (float*)d_out;

    const int attn_smem = (3*AT*SQh + 128*SBh + 2*BHB + AT*40 + 8*SBW2) * 2
                        + (128 + 8 + AT*8) * 4;
    const int edge_smem = (HOFF + TM*SHh) * 2;                       // 221,184 B
    const int node_smem = (TN*SAn + 2*BHB) * 2;
    cudaFuncSetAttribute(attn_kernel, cudaFuncAttributeMaxDynamicSharedMemorySize, attn_smem);
    cudaFuncSetAttribute(edge_kernel, cudaFuncAttributeMaxDynamicSharedMemorySize, edge_smem);
    cudaFuncSetAttribute(node_kernel, cudaFuncAttributeMaxDynamicSharedMemorySize, node_smem);

    prep_kernel<<<BB*TT + BB, 128>>>(cond, wk, bk, wv, bv, lat);
    convw_kernel<<<549, 256>>>(ew1, ew2, nw1, nw2, wq, wo, sw1, sw2);
    zero_kernel<<<(NN*DD + 255) / 256, 256>>>();
    attn_kernel<<<(NN + AT - 1) / AT, 256, attn_smem>>>(node_features, frac, n2g,
                                                        bq, bo, sb1, sb2);
    edge_kernel<<<148, 512, edge_smem>>>(frac, edges, e2g, eb1, eb2);
    node_kernel<<<(NN + TN - 1) / TN, 256, node_smem>>>(node_features, nb1, nb2, out);
}

// round 14
// speedup vs baseline: 1.2435x; 1.2435x over previous
#include <cuda_runtime.h>
#include <cuda_fp16.h>
#include <math.h>
#include <stdint.h>

#define NN 50000
#define EE 800000
#define BB 256
#define DD 128
#define TT 8
#define KV_OFF (BB*TT*DD)

// ---------------- scratch (no allocations allowed) ----------------
__device__ __half g_h16[(size_t)NN*DD];     // post-attention node states (fp16)
__device__ __half g_KV16[2*BB*TT*DD];       // Kc then Vc (fp16)
__device__ float  g_lip[BB*9];              // lattice inner products
__device__ float  g_agg[(size_t)NN*DD];     // scatter sums (fp32 atomics)
__device__ int    g_cnt[NN];                // scatter counts
// pre-converted, pre-transposed fp16 weights [N][K]
__device__ __half g_ew1T[DD*288];           // K padded 272->288
__device__ __half g_ew2T[DD*DD];
__device__ __half g_nw1T[DD*256];
__device__ __half g_nw2T[DD*DD];
__device__ __half g_wqT[DD*DD];
__device__ __half g_woT[DD*DD];
__device__ __half g_sw1T[DD*32];            // K padded 24->32
__device__ __half g_sw2h[8*DD];             // sw2 transposed [8][128] fp16

__device__ __forceinline__ float silu_f(float x) {
    return __fdividef(x, 1.f + __expf(-x));
}

// fp16 mma, fp32 accumulate
__device__ __forceinline__ void mma_f16(float* c, const uint32_t* a, const uint32_t* b) {
    asm volatile(
        "mma.sync.aligned.m16n8k16.row.col.f32.f16.f16.f32 "
        "{%0,%1,%2,%3}, {%4,%5,%6,%7}, {%8,%9}, {%0,%1,%2,%3};\n"
        : "+f"(c[0]), "+f"(c[1]), "+f"(c[2]), "+f"(c[3])
        : "r"(a[0]), "r"(a[1]), "r"(a[2]), "r"(a[3]), "r"(b[0]), "r"(b[1]));
}

__device__ __forceinline__ void cpa16(void* dst, const void* src) {
    uint32_t d = (uint32_t)__cvta_generic_to_shared(dst);
    asm volatile("cp.async.cg.shared.global [%0], [%1], 16;" :: "r"(d), "l"(src));
}
#define CP_COMMIT asm volatile("cp.async.commit_group;" ::: "memory")
#define CP_WAIT0  asm volatile("cp.async.wait_group 0;" ::: "memory")

// ldmatrix x4
__device__ __forceinline__ void ldsm4(uint32_t* r, const __half* p) {
    uint32_t a = (uint32_t)__cvta_generic_to_shared(p);
    asm volatile("ldmatrix.sync.aligned.m8n8.x4.shared.b16 {%0,%1,%2,%3}, [%4];"
        : "=r"(r[0]), "=r"(r[1]), "=r"(r[2]), "=r"(r[3]) : "r"(a));
}
#define LDSMA(afr, base, SAx, rowbase, kg)                                        \
    ldsm4(afr, (base) + ((rowbase) + (lane & 15))*(SAx) + (kg) + ((lane >> 4) << 3))
#define LDSMB2(b4, bB, SBx, ncol, kk)                                             \
    ldsm4(b4, (bB) + ((ncol) + (lane & 7) + ((lane >> 4) << 3))*(SBx) + (kk) + (((lane >> 3) & 1) << 3))

// attn B geometry: 128 n-rows x (32 k + 8 pad)
#define SBh 40
#define BHB (128*SBh)
// edge/node B geometry: 128 n-rows x (64 k + 8 pad)
#define SBK 72
#define BKB (128*SBK)

// ---------------- kernel 1: K/V projection + lattice gram ----------------
__global__ void prep_kernel(const float* __restrict__ cond,
                            const float* __restrict__ wk, const float* __restrict__ bk,
                            const float* __restrict__ wv, const float* __restrict__ bv,
                            const float* __restrict__ lat)
{
    int b = blockIdx.x;
    if (b < BB*TT) {
        __shared__ float s_c[DD];
        int d = threadIdx.x;
        s_c[d] = cond[b*DD + d];
        __syncthreads();
        float ka = bk[d], va = bv[d];
        #pragma unroll 8
        for (int k = 0; k < DD; k++) {
            float c = s_c[k];
            ka = fmaf(c, wk[k*DD + d], ka);
            va = fmaf(c, wv[k*DD + d], va);
        }
        g_KV16[b*DD + d] = __float2half(ka);
        g_KV16[KV_OFF + b*DD + d] = __float2half(va);
    } else {
        int bb = b - BB*TT;
        int t = threadIdx.x;
        if (t < 9) {
            int i = t / 3, k2 = t % 3;
            const float* L = lat + bb*9;
            g_lip[bb*9 + t] = L[i*3+0]*L[k2*3+0] + L[i*3+1]*L[k2*3+1] + L[i*3+2]*L[k2*3+2];
        }
    }
}

// ---------------- kernel 1b: convert+transpose weights ----------------
__global__ void convw_kernel(const float* __restrict__ ew1, const float* __restrict__ ew2,
                             const float* __restrict__ nw1, const float* __restrict__ nw2,
                             const float* __restrict__ wq,  const float* __restrict__ wo,
                             const float* __restrict__ sw1, const float* __restrict__ sw2)
{
    int idx = blockIdx.x * 256 + threadIdx.x;
    if (idx < 36864) {
        int n = idx / 288, k = idx % 288;
        g_ew1T[idx] = (k < 268) ? __float2half(ew1[k*DD + n]) : __half(0.f);
    } else if (idx < 53248) {
        int j = idx - 36864; int n = j / DD, k = j % DD;
        g_ew2T[j] = __float2half(ew2[k*DD + n]);
    } else if (idx < 86016) {
        int j = idx - 53248; int n = j / 256, k = j % 256;
        g_nw1T[j] = __float2half(nw1[k*DD + n]);
    } else if (idx < 102400) {
        int j = idx - 86016; int n = j / DD, k = j % DD;
        g_nw2T[j] = __float2half(nw2[k*DD + n]);
    } else if (idx < 118784) {
        int j = idx - 102400; int n = j / DD, k = j % DD;
        g_wqT[j] = __float2half(wq[k*DD + n]);
    } else if (idx < 135168) {
        int j = idx - 118784; int n = j / DD, k = j % DD;
        g_woT[j] = __float2half(wo[k*DD + n]);
    } else if (idx < 139264) {
        int j = idx - 135168; int n = j / 32, k = j % 32;
        g_sw1T[j] = (k < 24) ? __float2half(sw1[k*DD + n]) : __half(0.f);
    } else if (idx < 140288) {
        int j = idx - 139264; int t = j >> 7, k = j & 127;
        g_sw2h[j] = __float2half(sw2[k*8 + t]);
    }
}

// ---------------- kernel 2: zero scatter buffers ----------------
__global__ void zero_kernel()
{
    int idx = blockIdx.x * blockDim.x + threadIdx.x;
    if (idx < NN*DD) g_agg[idx] = 0.f;
    if (idx < NN)    g_cnt[idx] = 0;
}

// ---------------- kernel 3: cross-attention (unchanged from R12) ----------------
#define AT 64
#define SQh 136
#define SBW2 136

__global__ __launch_bounds__(256, 2)
void attn_kernel(const float* __restrict__ nfeat, const float* __restrict__ frac,
                 const int* __restrict__ n2g,
                 const float* __restrict__ bq, const float* __restrict__ bo,
                 const float* __restrict__ sb1, const float* __restrict__ sb2)
{
    extern __shared__ char smraw[];
    __half* s_h    = (__half*)smraw;
    __half* s_hid  = s_h + AT*SQh;
    __half* s_q    = s_hid + AT*SQh;
    __half* s_bsw  = s_q + AT*SQh;
    __half* s_bb   = s_bsw + 128*SBh;
    __half* s_enc  = s_bb + 2*BHB;
    __half* s_sw2h = s_enc + AT*40;
    float*  s_sb1 = (float*)(s_sw2h + 8*SBW2);
    float*  s_sb2 = s_sb1 + 128;
    float*  s_att = s_sb2 + 8;
    __shared__ int s_g[AT];

    int tid = threadIdx.x, lane = tid & 31, wid = tid >> 5;
    int wm = wid >> 2, wn = wid & 3;
    int n0 = blockIdx.x * AT;
    int bn = tid >> 1, bseg = (tid & 1) * 16;

    if (tid < AT) s_g[tid] = n2g[min(n0 + tid, NN - 1)];

    cpa16(s_bsw + bn*SBh + bseg,     g_sw1T + bn*32 + bseg);
    cpa16(s_bsw + bn*SBh + bseg + 8, g_sw1T + bn*32 + bseg + 8);
    if (tid < 128) {
        int row = tid >> 4, seg = (tid & 15) * 8;
        cpa16(s_sw2h + row*SBW2 + seg, g_sw2h + row*DD + seg);
    }
    if (tid < 32) cpa16(s_sb1 + tid*4, sb1 + tid*4);
    if (tid < 2)  cpa16(s_sb2 + tid*4, sb2 + tid*4);
    cpa16(s_bb + bn*SBh + bseg,     g_wqT + bn*DD + bseg);
    cpa16(s_bb + bn*SBh + bseg + 8, g_wqT + bn*DD + bseg + 8);
    CP_COMMIT;

    #pragma unroll
    for (int it = 0; it < 8; it++) {
        int idx = tid + it*256;
        int r = idx >> 5, c4 = (idx & 31) * 4;
        int n = min(n0 + r, NN - 1);
        float4 v = *(const float4*)(nfeat + (size_t)n*DD + c4);
        __half* dst = s_h + r*SQh + c4;
        *(__half2*)(dst)     = __floats2half2_rn(v.x, v.y);
        *(__half2*)(dst + 2) = __floats2half2_rn(v.z, v.w);
    }
    {
        int n = tid >> 2, sub = tid & 3;
        int nn = min(n0 + n, NN - 1);
        float f0 = frac[nn*3+0], f1 = frac[nn*3+1], f2 = frac[nn*3+2];
        #pragma unroll
        for (int k = sub; k < 24; k += 4) {
            int ii = k % 12, c = ii >> 2, j = ii & 3;
            float fv = (c == 0) ? f0 : ((c == 1) ? f1 : f2);
            float ph = fv * ((float)(1 << j) * 3.14159265358979323846f);
            s_enc[n*40 + k] = __float2half((k < 12) ? sinf(ph) : cosf(ph));
        }
        s_enc[n*40 + 24 + sub] = __half(0.f);
        s_enc[n*40 + 28 + sub] = __half(0.f);
    }
    CP_WAIT0;
    __syncthreads();

    float acc[2][4][4];
    #pragma unroll
    for (int mf = 0; mf < 2; mf++)
        #pragma unroll
        for (int nf = 0; nf < 4; nf++)
            #pragma unroll
            for (int u = 0; u < 4; u++) acc[mf][nf][u] = 0.f;

    #pragma unroll
    for (int kk = 0; kk < 32; kk += 16) {
        uint32_t afr[2][4];
        #pragma unroll
        for (int mf = 0; mf < 2; mf++) LDSMA(afr[mf], s_enc, 40, wm*32 + mf*16, kk);
        uint32_t bfr[4][2];
        LDSMB2(bfr[0], s_bsw, SBh, wn*32, kk);
        LDSMB2(bfr[2], s_bsw, SBh, wn*32 + 16, kk);
        #pragma unroll
        for (int mf = 0; mf < 2; mf++)
            #pragma unroll
            for (int nf = 0; nf < 4; nf++)
                mma_f16(acc[mf][nf], afr[mf], bfr[nf]);
    }
    #pragma unroll
    for (int mf = 0; mf < 2; mf++) {
        int r0 = wm*32 + mf*16 + (lane >> 2);
        #pragma unroll
        for (int nf = 0; nf < 4; nf++) {
            int n = wn*32 + nf*8 + (lane & 3)*2;
            float b0 = s_sb1[n], b1 = s_sb1[n + 1];
            *(__half2*)(s_hid + r0*SQh + n) =
                __floats2half2_rn(silu_f(acc[mf][nf][0] + b0), silu_f(acc[mf][nf][1] + b1));
            *(__half2*)(s_hid + (r0 + 8)*SQh + n) =
                __floats2half2_rn(silu_f(acc[mf][nf][2] + b0), silu_f(acc[mf][nf][3] + b1));
            #pragma unroll
            for (int u = 0; u < 4; u++) acc[mf][nf][u] = 0.f;
        }
    }

    for (int ct = 0; ct < 4; ct++) {
        __half* dbuf = s_bb + ((ct+1)&1)*BHB;
        const __half* src = (ct < 3) ? (g_wqT + (ct+1)*32) : g_woT;
        cpa16(dbuf + bn*SBh + bseg,     src + bn*DD + bseg);
        cpa16(dbuf + bn*SBh + bseg + 8, src + bn*DD + bseg + 8);
        CP_COMMIT;
        const __half* bB = s_bb + (ct & 1)*BHB;
        #pragma unroll
        for (int kk = 0; kk < 32; kk += 16) {
            int kg = ct*32 + kk;
            uint32_t afr[2][4];
            #pragma unroll
            for (int mf = 0; mf < 2; mf++) LDSMA(afr[mf], s_h, SQh, wm*32 + mf*16, kg);
            uint32_t bfr[4][2];
            LDSMB2(bfr[0], bB, SBh, wn*32, kk);
            LDSMB2(bfr[2], bB, SBh, wn*32 + 16, kk);
            #pragma unroll
            for (int mf = 0; mf < 2; mf++)
                #pragma unroll
                for (int nf = 0; nf < 4; nf++)
                    mma_f16(acc[mf][nf], afr[mf], bfr[nf]);
        }
        CP_WAIT0;
        __syncthreads();
    }
    #pragma unroll
    for (int mf = 0; mf < 2; mf++) {
        int r0 = wm*32 + mf*16 + (lane >> 2);
        #pragma unroll
        for (int nf = 0; nf < 4; nf++) {
            int n = wn*32 + nf*8 + (lane & 3)*2;
            float b0 = bq[n], b1 = bq[n + 1];
            *(__half2*)(s_q + r0*SQh + n) =
                __floats2half2_rn(acc[mf][nf][0] + b0, acc[mf][nf][1] + b1);
            *(__half2*)(s_q + (r0 + 8)*SQh + n) =
                __floats2half2_rn(acc[mf][nf][2] + b0, acc[mf][nf][3] + b1);
        }
    }
    __syncthreads();

    if (wid < 4) {
        float bacc[4] = {0.f, 0.f, 0.f, 0.f};
        #pragma unroll
        for (int kk = 0; kk < 128; kk += 16) {
            uint32_t afr[4];
            LDSMA(afr, s_hid, SQh, wid*16, kk);
            const __half* bp = s_sw2h + (lane >> 2)*SBW2 + kk + (lane & 3)*2;
            uint32_t bfr[2];
            bfr[0] = *(const uint32_t*)(bp);
            bfr[1] = *(const uint32_t*)(bp + 8);
            mma_f16(bacc, afr, bfr);
        }
        int r0 = wid*16 + (lane >> 2);
        int t = (lane & 3)*2;
        s_att[r0*8 + t]         = bacc[0];
        s_att[r0*8 + t + 1]     = bacc[1];
        s_att[(r0 + 8)*8 + t]     = bacc[2];
        s_att[(r0 + 8)*8 + t + 1] = bacc[3];
    }
    __syncthreads();

    {
        int n = tid >> 2, sub = tid & 3;
        int gg = s_g[n];
        int t0 = sub*2, t1 = t0 + 1;
        const __half2* K0 = (const __half2*)(g_KV16 + (size_t)(gg*TT + t0)*DD);
        const __half2* K1 = (const __half2*)(g_KV16 + (size_t)(gg*TT + t1)*DD);
        const __half2* qq = (const __half2*)(s_q + n*SQh);
        float sc0 = 0.f, sc1 = 0.f;
        #pragma unroll 8
        for (int k2 = 0; k2 < 64; k2++) {
            float2 q = __half22float2(qq[k2]);
            float2 a = __half22float2(K0[k2]);
            float2 b = __half22float2(K1[k2]);
            sc0 = fmaf(q.x, a.x, sc0); sc0 = fmaf(q.y, a.y, sc0);
            sc1 = fmaf(q.x, b.x, sc1); sc1 = fmaf(q.y, b.y, sc1);
        }
        float v0 = sc0 * 0.08838834764831845f + s_att[n*8 + t0] + s_sb2[t0];
        float v1 = sc1 * 0.08838834764831845f + s_att[n*8 + t1] + s_sb2[t1];
        float m = fmaxf(v0, v1);
        m = fmaxf(m, __shfl_xor_sync(0xffffffffu, m, 1, 4));
        m = fmaxf(m, __shfl_xor_sync(0xffffffffu, m, 2, 4));
        float e0 = __expf(v0 - m), e1 = __expf(v1 - m);
        float s = e0 + e1;
        s += __shfl_xor_sync(0xffffffffu, s, 1, 4);
        s += __shfl_xor_sync(0xffffffffu, s, 2, 4);
        float inv = __fdividef(1.f, s);
        s_att[n*8 + t0] = e0 * inv;
        s_att[n*8 + t1] = e1 * inv;
    }
    __syncthreads();

    #pragma unroll
    for (int it = 0; it < 16; it++) {
        int idx = tid + it*256;
        int n = idx >> 6, c = (idx & 63) * 2;
        const __half* Vr = g_KV16 + KV_OFF + (size_t)s_g[n]*TT*DD + c;
        const float* at = s_att + n*8;
        float a0 = 0.f, a1 = 0.f;
        #pragma unroll
        for (int t = 0; t < 8; t++) {
            float2 v = __half22float2(*(const __half2*)(Vr + t*DD));
            a0 = fmaf(at[t], v.x, a0);
            a1 = fmaf(at[t], v.y, a1);
        }
        *(__half2*)(s_q + n*SQh + c) = __floats2half2_rn(a0, a1);
    }
    __syncthreads();

    float acc2[2][4][4];
    #pragma unroll
    for (int mf = 0; mf < 2; mf++)
        #pragma unroll
        for (int nf = 0; nf < 4; nf++)
            #pragma unroll
            for (int u = 0; u < 4; u++) acc2[mf][nf][u] = 0.f;

    for (int c = 0; c < 4; c++) {
        if (c < 3) {
            __half* dbuf = s_bb + ((c+1)&1)*BHB;
            const __half* src = g_woT + (c+1)*32;
            cpa16(dbuf + bn*SBh + bseg,     src + bn*DD + bseg);
            cpa16(dbuf + bn*SBh + bseg + 8, src + bn*DD + bseg + 8);
            CP_COMMIT;
        }
        const __half* bB = s_bb + (c & 1)*BHB;
        #pragma unroll
        for (int kk = 0; kk < 32; kk += 16) {
            int kg = c*32 + kk;
            uint32_t afr[2][4];
            #pragma unroll
            for (int mf = 0; mf < 2; mf++) LDSMA(afr[mf], s_q, SQh, wm*32 + mf*16, kg);
            uint32_t bfr[4][2];
            LDSMB2(bfr[0], bB, SBh, wn*32, kk);
            LDSMB2(bfr[2], bB, SBh, wn*32 + 16, kk);
            #pragma unroll
            for (int mf = 0; mf < 2; mf++)
                #pragma unroll
                for (int nf = 0; nf < 4; nf++)
                    mma_f16(acc2[mf][nf], afr[mf], bfr[nf]);
        }
        if (c < 3) { CP_WAIT0; }
        __syncthreads();
    }

    #pragma unroll
    for (int mf = 0; mf < 2; mf++) {
        #pragma unroll
        for (int rr = 0; rr < 2; rr++) {
            int m = wm*32 + mf*16 + (lane >> 2) + rr*8;
            int n = n0 + m;
            if (n < NN) {
                __half* orow = g_h16 + (size_t)n*DD;
                const __half* hrow = s_h + m*SQh;
                #pragma unroll
                for (int nf = 0; nf < 4; nf++) {
                    int col = wn*32 + nf*8 + (lane & 3)*2;
                    float v0 = __half2float(hrow[col])     + acc2[mf][nf][rr*2 + 0] + bo[col];
                    float v1 = __half2float(hrow[col + 1]) + acc2[mf][nf][rr*2 + 1] + bo[col + 1];
                    *(__half2*)(orow + col) = __floats2half2_rn(v0, v1);
                }
            }
        }
    }
}

// ---------------- kernel 4: edge MLP, fp16 + ldmatrix, K=64 rounds ----------------
#define TM 128
#define SAh 296

__global__ __launch_bounds__(256, 2)
void edge_kernel(const float* __restrict__ frac,
                 const int* __restrict__ edges, const int* __restrict__ e2g,
                 const float* __restrict__ eb1, const float* __restrict__ eb2)
{
    extern __shared__ __half smh[];
    __half* s_a  = smh;               // TM*SAh (75,776 B)
    __half* s_bb = smh + TM*SAh;      // 2*BKB  (36,864 B)
    __shared__ int s_i[TM], s_j[TM];

    int tid  = threadIdx.x, lane = tid & 31, wid = tid >> 5;
    int wm = wid >> 2, wn = wid & 3;
    int e0 = blockIdx.x * TM;

    if (tid < TM) {
        s_i[tid] = edges[e0 + tid];
        s_j[tid] = edges[EE + e0 + tid];
    }
    __syncthreads();

    // gather A rows + ew1T chunk0 (k 0..63)
    #pragma unroll
    for (int it = 0; it < 16; it++) {
        int idx = tid + it*256;
        int r = idx >> 4, seg = idx & 15;
        int e = r >> 1, p = r & 1;
        int node = p ? s_j[e] : s_i[e];
        cpa16(s_a + e*SAh + p*DD + seg*8, g_h16 + (size_t)node*DD + seg*8);
    }
    #pragma unroll
    for (int it = 0; it < 4; it++) {
        int idx = tid + it*256;
        int row = idx >> 3, seg = idx & 7;
        cpa16(s_bb + row*SBK + seg*8, g_ew1T + row*288 + seg*8);
    }
    CP_COMMIT;

    // tail cols 256..287 + counts
    if (tid < TM) {
        int e = tid;
        const float* lp = g_lip + e2g[e0 + e]*9;
        #pragma unroll
        for (int u = 0; u < 9; u++) s_a[e*SAh + 256 + u] = __float2half(lp[u]);
        int ii = s_i[e], jj = s_j[e];
        #pragma unroll
        for (int c = 0; c < 3; c++) {
            float dd = frac[jj*3 + c] - frac[ii*3 + c];
            dd -= floorf(dd);
            s_a[e*SAh + 265 + c] = __float2half(dd);
        }
        #pragma unroll
        for (int u = 268; u < 288; u++) s_a[e*SAh + u] = __half(0.f);
        atomicAdd(&g_cnt[ii], 1);
    }

    float acc[4][4][4];
    #pragma unroll
    for (int mf = 0; mf < 4; mf++)
        #pragma unroll
        for (int nf = 0; nf < 4; nf++)
            #pragma unroll
            for (int u = 0; u < 4; u++) acc[mf][nf][u] = 0.f;

    CP_WAIT0;
    __syncthreads();

    // ---- GEMM1 main: 4 rounds of K=64 (k 0..255) ----
    for (int ct = 0; ct < 4; ct++) {
        __half* dbuf = s_bb + ((ct+1)&1)*BKB;
        if (ct < 3) {
            #pragma unroll
            for (int it = 0; it < 4; it++) {
                int idx = tid + it*256;
                int row = idx >> 3, seg = idx & 7;
                cpa16(dbuf + row*SBK + seg*8, g_ew1T + row*288 + (ct+1)*64 + seg*8);
            }
        } else {
            // tail chunk: ew1T k 256..287 (32 cols)
            #pragma unroll
            for (int it = 0; it < 2; it++) {
                int idx = tid + it*256;
                int row = idx >> 2, seg = idx & 3;
                cpa16(dbuf + row*SBK + seg*8, g_ew1T + row*288 + 256 + seg*8);
            }
        }
        CP_COMMIT;
        const __half* bB = s_bb + (ct & 1)*BKB;
        #pragma unroll
        for (int kk = 0; kk < 64; kk += 16) {
            int kg = ct*64 + kk;
            uint32_t afr[4][4];
            #pragma unroll
            for (int mf = 0; mf < 4; mf++) LDSMA(afr[mf], s_a, SAh, wm*64 + mf*16, kg);
            uint32_t bfr[4][2];
            LDSMB2(bfr[0], bB, SBK, wn*32, kk);
            LDSMB2(bfr[2], bB, SBK, wn*32 + 16, kk);
            #pragma unroll
            for (int mf = 0; mf < 4; mf++)
                #pragma unroll
                for (int nf = 0; nf < 4; nf++)
                    mma_f16(acc[mf][nf], afr[mf], bfr[nf]);
        }
        CP_WAIT0;
        __syncthreads();
    }

    // ---- GEMM1 tail: K=32 (k 256..287) in buf0; prefetch ew2 chunk0 -> buf1 ----
    {
        #pragma unroll
        for (int it = 0; it < 4; it++) {
            int idx = tid + it*256;
            int row = idx >> 3, seg = idx & 7;
            cpa16(s_bb + BKB + row*SBK + seg*8, g_ew2T + row*DD + seg*8);
        }
        CP_COMMIT;
        const __half* bB = s_bb;   // buf0
        #pragma unroll
        for (int kk = 0; kk < 32; kk += 16) {
            int kg = 256 + kk;
            uint32_t afr[4][4];
            #pragma unroll
            for (int mf = 0; mf < 4; mf++) LDSMA(afr[mf], s_a, SAh, wm*64 + mf*16, kg);
            uint32_t bfr[4][2];
            LDSMB2(bfr[0], bB, SBK, wn*32, kk);
            LDSMB2(bfr[2], bB, SBK, wn*32 + 16, kk);
            #pragma unroll
            for (int mf = 0; mf < 4; mf++)
                #pragma unroll
                for (int nf = 0; nf < 4; nf++)
                    mma_f16(acc[mf][nf], afr[mf], bfr[nf]);
        }
        CP_WAIT0;
        __syncthreads();
    }

    // hidden = silu(acc + eb1) -> s_a cols 0..127
    #pragma unroll
    for (int mf = 0; mf < 4; mf++) {
        int r0 = wm*64 + mf*16 + (lane >> 2);
        #pragma unroll
        for (int nf = 0; nf < 4; nf++) {
            int n = wn*32 + nf*8 + (lane & 3)*2;
            float b0 = eb1[n], b1 = eb1[n + 1];
            *(__half2*)(s_a + r0*SAh + n) =
                __floats2half2_rn(silu_f(acc[mf][nf][0] + b0), silu_f(acc[mf][nf][1] + b1));
            *(__half2*)(s_a + (r0 + 8)*SAh + n) =
                __floats2half2_rn(silu_f(acc[mf][nf][2] + b0), silu_f(acc[mf][nf][3] + b1));
            #pragma unroll
            for (int u = 0; u < 4; u++) acc[mf][nf][u] = 0.f;
        }
    }
    __syncthreads();

    // ---- GEMM2: 2 rounds of K=64; chunk c in buf[(1+c)&1] ----
    for (int c = 0; c < 2; c++) {
        if (c == 0) {
            #pragma unroll
            for (int it = 0; it < 4; it++) {
                int idx = tid + it*256;
                int row = idx >> 3, seg = idx & 7;
                cpa16(s_bb + row*SBK + seg*8, g_ew2T + row*DD + 64 + seg*8);
            }
            CP_COMMIT;
        }
        const __half* bB = s_bb + ((1 + c) & 1)*BKB;
        #pragma unroll
        for (int kk = 0; kk < 64; kk += 16) {
            int kg = c*64 + kk;
            uint32_t afr[4][4];
            #pragma unroll
            for (int mf = 0; mf < 4; mf++) LDSMA(afr[mf], s_a, SAh, wm*64 + mf*16, kg);
            uint32_t bfr[4][2];
            LDSMB2(bfr[0], bB, SBK, wn*32, kk);
            LDSMB2(bfr[2], bB, SBK, wn*32 + 16, kk);
            #pragma unroll
            for (int mf = 0; mf < 4; mf++)
                #pragma unroll
                for (int nf = 0; nf < 4; nf++)
                    mma_f16(acc[mf][nf], afr[mf], bfr[nf]);
        }
        if (c == 0) { CP_WAIT0; }
        __syncthreads();
    }

    // epilogue: silu + bias, red.v2 scatter into g_agg (fp32)
    #pragma unroll
    for (int mf = 0; mf < 4; mf++) {
        #pragma unroll
        for (int rr = 0; rr < 2; rr++) {
            int m = wm*64 + mf*16 + (lane >> 2) + rr*8;
            float* ap = g_agg + (size_t)s_i[m]*DD;
            #pragma unroll
            for (int nf = 0; nf < 4; nf++) {
                int n = wn*32 + nf*8 + (lane & 3)*2;
                float v0 = silu_f(acc[mf][nf][rr*2 + 0] + eb2[n]);
                float v1 = silu_f(acc[mf][nf][rr*2 + 1] + eb2[n + 1]);
                asm volatile("red.global.add.v2.f32 [%0], {%1, %2};"
                             :: "l"(ap + n), "f"(v0), "f"(v1) : "memory");
            }
        }
    }
}

// ---------------- kernel 5: node MLP, fp16 + ldmatrix, K=64 rounds ----------------
#define TN 128
#define SAn 264

__global__ __launch_bounds__(256, 2)
void node_kernel(const float* __restrict__ nfeat,
                 const float* __restrict__ nb1, const float* __restrict__ nb2,
                 float* __restrict__ out)
{
    extern __shared__ __half smh[];
    __half* s_a  = smh;               // TN*SAn (67,584 B)
    __half* s_bb = smh + TN*SAn;      // 2*BKB  (36,864 B)
    __shared__ float s_cnt[TN];

    int tid  = threadIdx.x, lane = tid & 31, wid = tid >> 5;
    int wm = wid >> 2, wn = wid & 3;
    int n0 = blockIdx.x * TN;

    if (tid < TN) {
        int n = min(n0 + tid, NN - 1);
        s_cnt[tid] = fmaxf((float)g_cnt[n], 1.f);
    }
    #pragma unroll
    for (int it = 0; it < 8; it++) {
        int idx = tid + it*256;
        int r = idx >> 4, seg = idx & 15;
        int n = min(n0 + r, NN - 1);
        cpa16(s_a + r*SAn + seg*8, g_h16 + (size_t)n*DD + seg*8);
    }
    #pragma unroll
    for (int it = 0; it < 4; it++) {
        int idx = tid + it*256;
        int row = idx >> 3, seg = idx & 7;
        cpa16(s_bb + row*SBK + seg*8, g_nw1T + row*256 + seg*8);
    }
    CP_COMMIT;
    __syncthreads();

    #pragma unroll
    for (int it = 0; it < 16; it++) {
        int idx = tid + it*256;
        int r = idx >> 5, c4 = (idx & 31) * 4;
        int n = min(n0 + r, NN - 1);
        float inv = __fdividef(1.f, s_cnt[r]);
        float4 v = *(const float4*)(g_agg + (size_t)n*DD + c4);
        __half* dst = s_a + r*SAn + DD + c4;
        *(__half2*)(dst)     = __floats2half2_rn(v.x * inv, v.y * inv);
        *(__half2*)(dst + 2) = __floats2half2_rn(v.z * inv, v.w * inv);
    }

    float acc[4][4][4];
    #pragma unroll
    for (int mf = 0; mf < 4; mf++)
        #pragma unroll
        for (int nf = 0; nf < 4; nf++)
            #pragma unroll
            for (int u = 0; u < 4; u++) acc[mf][nf][u] = 0.f;

    CP_WAIT0;
    __syncthreads();

    // ---- GEMM1: K=256, 4 rounds of K=64 ----
    for (int ct = 0; ct < 4; ct++) {
        __half* dbuf = s_bb + ((ct+1)&1)*BKB;
        const __half* src; int rstr; int k0;
        if (ct < 3) { src = g_nw1T; rstr = 256; k0 = (ct+1)*64; }
        else        { src = g_nw2T; rstr = 128; k0 = 0; }
        #pragma unroll
        for (int it = 0; it < 4; it++) {
            int idx = tid + it*256;
            int row = idx >> 3, seg = idx & 7;
            cpa16(dbuf + row*SBK + seg*8, src + (size_t)row*rstr + k0 + seg*8);
        }
        CP_COMMIT;
        const __half* bB = s_bb + (ct & 1)*BKB;
        #pragma unroll
        for (int kk = 0; kk < 64; kk += 16) {
            int kg = ct*64 + kk;
            uint32_t afr[4][4];
            #pragma unroll
            for (int mf = 0; mf < 4; mf++) LDSMA(afr[mf], s_a, SAn, wm*64 + mf*16, kg);
            uint32_t bfr[4][2];
            LDSMB2(bfr[0], bB, SBK, wn*32, kk);
            LDSMB2(bfr[2], bB, SBK, wn*32 + 16, kk);
            #pragma unroll
            for (int mf = 0; mf < 4; mf++)
                #pragma unroll
                for (int nf = 0; nf < 4; nf++)
                    mma_f16(acc[mf][nf], afr[mf], bfr[nf]);
        }
        CP_WAIT0;
        __syncthreads();
    }

    // hidden -> s_a cols 0..127
    #pragma unroll
    for (int mf = 0; mf < 4; mf++) {
        int r0 = wm*64 + mf*16 + (lane >> 2);
        #pragma unroll
        for (int nf = 0; nf < 4; nf++) {
            int n = wn*32 + nf*8 + (lane & 3)*2;
            float b0 = nb1[n], b1 = nb1[n + 1];
            *(__half2*)(s_a + r0*SAn + n) =
                __floats2half2_rn(silu_f(acc[mf][nf][0] + b0), silu_f(acc[mf][nf][1] + b1));
            *(__half2*)(s_a + (r0 + 8)*SAn + n) =
                __floats2half2_rn(silu_f(acc[mf][nf][2] + b0), silu_f(acc[mf][nf][3] + b1));
            #pragma unroll
            for (int u = 0; u < 4; u++) acc[mf][nf][u] = 0.f;
        }
    }
    __syncthreads();

    // ---- GEMM2: K=128, 2 rounds of K=64; nw2 chunk0 in buf0 ----
    for (int c = 0; c < 2; c++) {
        if (c == 0) {
            #pragma unroll
            for (int it = 0; it < 4; it++) {
                int idx = tid + it*256;
                int row = idx >> 3, seg = idx & 7;
                cpa16(s_bb + BKB + row*SBK + seg*8, g_nw2T + row*DD + 64 + seg*8);
            }
            CP_COMMIT;
        }
        const __half* bB = s_bb + (c & 1)*BKB;
        #pragma unroll
        for (int kk = 0; kk < 64; kk += 16) {
            int kg = c*64 + kk;
            uint32_t afr[4][4];
            #pragma unroll
            for (int mf = 0; mf < 4; mf++) LDSMA(afr[mf], s_a, SAn, wm*64 + mf*16, kg);
            uint32_t bfr[4][2];
            LDSMB2(bfr[0], bB, SBK, wn*32, kk);
            LDSMB2(bfr[2], bB, SBK, wn*32 + 16, kk);
            #pragma unroll
            for (int mf = 0; mf < 4; mf++)
                #pragma unroll
                for (int nf = 0; nf < 4; nf++)
                    mma_f16(acc[mf][nf], afr[mf], bfr[nf]);
        }
        if (c == 0) { CP_WAIT0; }
        __syncthreads();
    }

    // epilogue: out = nfeat + silu(acc + nb2)
    #pragma unroll
    for (int mf = 0; mf < 4; mf++) {
        #pragma unroll
        for (int rr = 0; rr < 2; rr++) {
            int m = wm*64 + mf*16 + (lane >> 2) + rr*8;
            int n = n0 + m;
            if (n < NN) {
                const float* nfr = nfeat + (size_t)n*DD;
                float* orow = out + (size_t)n*DD;
                #pragma unroll
                for (int nf = 0; nf < 4; nf++) {
                    int col = wn*32 + nf*8 + (lane & 3)*2;
                    orow[col]     = nfr[col]     + silu_f(acc[mf][nf][rr*2 + 0] + nb2[col]);
                    orow[col + 1] = nfr[col + 1] + silu_f(acc[mf][nf][rr*2 + 1] + nb2[col + 1]);
                }
            }
        }
    }
}

// ---------------- launch ----------------
extern "C" void kernel_launch(void* const* d_in, const int* in_sizes, int n_in,
                              void* d_out, int out_size)
{
    const float* node_features = (const float*)d_in[0];
    const float* cond = (const float*)d_in[1];
    const int*   n2g  = (const int*)d_in[2];
    const float* frac = (const float*)d_in[3];
    const float* lat  = (const float*)d_in[4];
    const int*   edges= (const int*)d_in[5];
    const int*   e2g  = (const int*)d_in[6];
    const float* wq = (const float*)d_in[7];
    const float* bq = (const float*)d_in[8];
    const float* wk = (const float*)d_in[9];
    const float* bk = (const float*)d_in[10];
    const float* wv = (const float*)d_in[11];
    const float* bv = (const float*)d_in[12];
    const float* wo = (const float*)d_in[13];
    const float* bo = (const float*)d_in[14];
    const float* sw1= (const float*)d_in[15];
    const float* sb1= (const float*)d_in[16];
    const float* sw2= (const float*)d_in[17];
    const float* sb2= (const float*)d_in[18];
    const float* ew1= (const float*)d_in[19];
    const float* eb1= (const float*)d_in[20];
    const float* ew2= (const float*)d_in[21];
    const float* eb2= (const float*)d_in[22];
    const float* nw1= (const float*)d_in[23];
    const float* nb1= (const float*)d_in[24];
    const float* nw2= (const float*)d_in[25];
    const float* nb2= (const float*)d_in[26];
    float* out = (float*)d_out;

    const int attn_smem = (3*AT*SQh + 128*SBh + 2*BHB + AT*40 + 8*SBW2) * 2
                        + (128 + 8 + AT*8) * 4;
    const int edge_smem = (TM*SAh + 2*BKB) * 2;    // 112,640 B
    const int node_smem = (TN*SAn + 2*BKB) * 2;    // 104,448 B
    cudaFuncSetAttribute(attn_kernel, cudaFuncAttributeMaxDynamicSharedMemorySize, attn_smem);
    cudaFuncSetAttribute(edge_kernel, cudaFuncAttributeMaxDynamicSharedMemorySize, edge_smem);
    cudaFuncSetAttribute(node_kernel, cudaFuncAttributeMaxDynamicSharedMemorySize, node_smem);

    prep_kernel<<<BB*TT + BB, 128>>>(cond, wk, bk, wv, bv, lat);
    convw_kernel<<<549, 256>>>(ew1, ew2, nw1, nw2, wq, wo, sw1, sw2);
    zero_kernel<<<(NN*DD + 255) / 256, 256>>>();
    attn_kernel<<<(NN + AT - 1) / AT, 256, attn_smem>>>(node_features, frac, n2g,
                                                        bq, bo, sb1, sb2);
    edge_kernel<<<EE / TM, 256, edge_smem>>>(frac, edges, e2g, eb1, eb2);
    node_kernel<<<(NN + TN - 1) / TN, 256, node_smem>>>(node_features, nb1, nb2, out);
}

// round 15
// speedup vs baseline: 1.2661x; 1.0182x over previous
#include <cuda_runtime.h>
#include <cuda_fp16.h>
#include <math.h>
#include <stdint.h>

#define NN 50000
#define EE 800000
#define BB 256
#define DD 128
#define TT 8
#define KV_OFF (BB*TT*DD)

// ---------------- scratch (no allocations allowed) ----------------
__device__ __half g_h16[(size_t)NN*DD];     // post-attention node states (fp16)
__device__ __half g_KV16[2*BB*TT*DD];       // Kc then Vc (fp16)
__device__ float  g_lip[BB*9];              // lattice inner products
__device__ float  g_agg[(size_t)NN*DD];     // scatter sums (fp32 atomics)
__device__ int    g_cnt[NN];                // scatter counts
// pre-converted, pre-transposed fp16 weights [N][K]
__device__ __half g_ew1T[DD*288];           // K padded 272->288
__device__ __half g_ew2T[DD*DD];
__device__ __half g_nw1T[DD*256];
__device__ __half g_nw2T[DD*DD];
__device__ __half g_wqT[DD*DD];
__device__ __half g_woT[DD*DD];
__device__ __half g_sw1T[DD*32];            // K padded 24->32
__device__ __half g_sw2h[8*DD];             // sw2 transposed [8][128] fp16

__device__ __forceinline__ float silu_f(float x) {
    return __fdividef(x, 1.f + __expf(-x));
}

// fp16 mma, fp32 accumulate
__device__ __forceinline__ void mma_f16(float* c, const uint32_t* a, const uint32_t* b) {
    asm volatile(
        "mma.sync.aligned.m16n8k16.row.col.f32.f16.f16.f32 "
        "{%0,%1,%2,%3}, {%4,%5,%6,%7}, {%8,%9}, {%0,%1,%2,%3};\n"
        : "+f"(c[0]), "+f"(c[1]), "+f"(c[2]), "+f"(c[3])
        : "r"(a[0]), "r"(a[1]), "r"(a[2]), "r"(a[3]), "r"(b[0]), "r"(b[1]));
}

__device__ __forceinline__ void cpa16(void* dst, const void* src) {
    uint32_t d = (uint32_t)__cvta_generic_to_shared(dst);
    asm volatile("cp.async.cg.shared.global [%0], [%1], 16;" :: "r"(d), "l"(src));
}
#define CP_COMMIT asm volatile("cp.async.commit_group;" ::: "memory")
#define CP_WAIT0  asm volatile("cp.async.wait_group 0;" ::: "memory")

// ldmatrix x4
__device__ __forceinline__ void ldsm4(uint32_t* r, const __half* p) {
    uint32_t a = (uint32_t)__cvta_generic_to_shared(p);
    asm volatile("ldmatrix.sync.aligned.m8n8.x4.shared.b16 {%0,%1,%2,%3}, [%4];"
        : "=r"(r[0]), "=r"(r[1]), "=r"(r[2]), "=r"(r[3]) : "r"(a));
}
#define LDSMA(afr, base, SAx, rowbase, kg)                                        \
    ldsm4(afr, (base) + ((rowbase) + (lane & 15))*(SAx) + (kg) + ((lane >> 4) << 3))
#define LDSMB2(b4, bB, SBx, ncol, kk)                                             \
    ldsm4(b4, (bB) + ((ncol) + (lane & 7) + ((lane >> 4) << 3))*(SBx) + (kk) + (((lane >> 3) & 1) << 3))

// attn B geometry: 128 n-rows x (32 k + 8 pad)
#define SBh 40
#define BHB (128*SBh)
// edge/node B geometry: 128 n-rows x (64 k + 8 pad)
#define SBK 72
#define BKB (128*SBK)

// ---------------- kernel 1: K/V projection + lattice gram ----------------
__global__ void prep_kernel(const float* __restrict__ cond,
                            const float* __restrict__ wk, const float* __restrict__ bk,
                            const float* __restrict__ wv, const float* __restrict__ bv,
                            const float* __restrict__ lat)
{
    int b = blockIdx.x;
    if (b < BB*TT) {
        __shared__ float s_c[DD];
        int d = threadIdx.x;
        s_c[d] = cond[b*DD + d];
        __syncthreads();
        float ka = bk[d], va = bv[d];
        #pragma unroll 8
        for (int k = 0; k < DD; k++) {
            float c = s_c[k];
            ka = fmaf(c, wk[k*DD + d], ka);
            va = fmaf(c, wv[k*DD + d], va);
        }
        g_KV16[b*DD + d] = __float2half(ka);
        g_KV16[KV_OFF + b*DD + d] = __float2half(va);
    } else {
        int bb = b - BB*TT;
        int t = threadIdx.x;
        if (t < 9) {
            int i = t / 3, k2 = t % 3;
            const float* L = lat + bb*9;
            g_lip[bb*9 + t] = L[i*3+0]*L[k2*3+0] + L[i*3+1]*L[k2*3+1] + L[i*3+2]*L[k2*3+2];
        }
    }
}

// ---------------- kernel 1b: convert+transpose weights ----------------
__global__ void convw_kernel(const float* __restrict__ ew1, const float* __restrict__ ew2,
                             const float* __restrict__ nw1, const float* __restrict__ nw2,
                             const float* __restrict__ wq,  const float* __restrict__ wo,
                             const float* __restrict__ sw1, const float* __restrict__ sw2)
{
    int idx = blockIdx.x * 256 + threadIdx.x;
    if (idx < 36864) {
        int n = idx / 288, k = idx % 288;
        g_ew1T[idx] = (k < 268) ? __float2half(ew1[k*DD + n]) : __half(0.f);
    } else if (idx < 53248) {
        int j = idx - 36864; int n = j / DD, k = j % DD;
        g_ew2T[j] = __float2half(ew2[k*DD + n]);
    } else if (idx < 86016) {
        int j = idx - 53248; int n = j / 256, k = j % 256;
        g_nw1T[j] = __float2half(nw1[k*DD + n]);
    } else if (idx < 102400) {
        int j = idx - 86016; int n = j / DD, k = j % DD;
        g_nw2T[j] = __float2half(nw2[k*DD + n]);
    } else if (idx < 118784) {
        int j = idx - 102400; int n = j / DD, k = j % DD;
        g_wqT[j] = __float2half(wq[k*DD + n]);
    } else if (idx < 135168) {
        int j = idx - 118784; int n = j / DD, k = j % DD;
        g_woT[j] = __float2half(wo[k*DD + n]);
    } else if (idx < 139264) {
        int j = idx - 135168; int n = j / 32, k = j % 32;
        g_sw1T[j] = (k < 24) ? __float2half(sw1[k*DD + n]) : __half(0.f);
    } else if (idx < 140288) {
        int j = idx - 139264; int t = j >> 7, k = j & 127;
        g_sw2h[j] = __float2half(sw2[k*8 + t]);
    }
}

// ---------------- kernel 2: zero scatter buffers ----------------
__global__ void zero_kernel()
{
    int idx = blockIdx.x * blockDim.x + threadIdx.x;
    if (idx < NN*DD) g_agg[idx] = 0.f;
    if (idx < NN)    g_cnt[idx] = 0;
}

// ---------------- kernel 3: cross-attention (unchanged from R14) ----------------
#define AT 64
#define SQh 136
#define SBW2 136

__global__ __launch_bounds__(256, 2)
void attn_kernel(const float* __restrict__ nfeat, const float* __restrict__ frac,
                 const int* __restrict__ n2g,
                 const float* __restrict__ bq, const float* __restrict__ bo,
                 const float* __restrict__ sb1, const float* __restrict__ sb2)
{
    extern __shared__ char smraw[];
    __half* s_h    = (__half*)smraw;
    __half* s_hid  = s_h + AT*SQh;
    __half* s_q    = s_hid + AT*SQh;
    __half* s_bsw  = s_q + AT*SQh;
    __half* s_bb   = s_bsw + 128*SBh;
    __half* s_enc  = s_bb + 2*BHB;
    __half* s_sw2h = s_enc + AT*40;
    float*  s_sb1 = (float*)(s_sw2h + 8*SBW2);
    float*  s_sb2 = s_sb1 + 128;
    float*  s_att = s_sb2 + 8;
    __shared__ int s_g[AT];

    int tid = threadIdx.x, lane = tid & 31, wid = tid >> 5;
    int wm = wid >> 2, wn = wid & 3;
    int n0 = blockIdx.x * AT;
    int bn = tid >> 1, bseg = (tid & 1) * 16;

    if (tid < AT) s_g[tid] = n2g[min(n0 + tid, NN - 1)];

    cpa16(s_bsw + bn*SBh + bseg,     g_sw1T + bn*32 + bseg);
    cpa16(s_bsw + bn*SBh + bseg + 8, g_sw1T + bn*32 + bseg + 8);
    if (tid < 128) {
        int row = tid >> 4, seg = (tid & 15) * 8;
        cpa16(s_sw2h + row*SBW2 + seg, g_sw2h + row*DD + seg);
    }
    if (tid < 32) cpa16(s_sb1 + tid*4, sb1 + tid*4);
    if (tid < 2)  cpa16(s_sb2 + tid*4, sb2 + tid*4);
    cpa16(s_bb + bn*SBh + bseg,     g_wqT + bn*DD + bseg);
    cpa16(s_bb + bn*SBh + bseg + 8, g_wqT + bn*DD + bseg + 8);
    CP_COMMIT;

    #pragma unroll
    for (int it = 0; it < 8; it++) {
        int idx = tid + it*256;
        int r = idx >> 5, c4 = (idx & 31) * 4;
        int n = min(n0 + r, NN - 1);
        float4 v = *(const float4*)(nfeat + (size_t)n*DD + c4);
        __half* dst = s_h + r*SQh + c4;
        *(__half2*)(dst)     = __floats2half2_rn(v.x, v.y);
        *(__half2*)(dst + 2) = __floats2half2_rn(v.z, v.w);
    }
    {
        int n = tid >> 2, sub = tid & 3;
        int nn = min(n0 + n, NN - 1);
        float f0 = frac[nn*3+0], f1 = frac[nn*3+1], f2 = frac[nn*3+2];
        #pragma unroll
        for (int k = sub; k < 24; k += 4) {
            int ii = k % 12, c = ii >> 2, j = ii & 3;
            float fv = (c == 0) ? f0 : ((c == 1) ? f1 : f2);
            float ph = fv * ((float)(1 << j) * 3.14159265358979323846f);
            s_enc[n*40 + k] = __float2half((k < 12) ? sinf(ph) : cosf(ph));
        }
        s_enc[n*40 + 24 + sub] = __half(0.f);
        s_enc[n*40 + 28 + sub] = __half(0.f);
    }
    CP_WAIT0;
    __syncthreads();

    float acc[2][4][4];
    #pragma unroll
    for (int mf = 0; mf < 2; mf++)
        #pragma unroll
        for (int nf = 0; nf < 4; nf++)
            #pragma unroll
            for (int u = 0; u < 4; u++) acc[mf][nf][u] = 0.f;

    #pragma unroll
    for (int kk = 0; kk < 32; kk += 16) {
        uint32_t afr[2][4];
        #pragma unroll
        for (int mf = 0; mf < 2; mf++) LDSMA(afr[mf], s_enc, 40, wm*32 + mf*16, kk);
        uint32_t bfr[4][2];
        LDSMB2(bfr[0], s_bsw, SBh, wn*32, kk);
        LDSMB2(bfr[2], s_bsw, SBh, wn*32 + 16, kk);
        #pragma unroll
        for (int mf = 0; mf < 2; mf++)
            #pragma unroll
            for (int nf = 0; nf < 4; nf++)
                mma_f16(acc[mf][nf], afr[mf], bfr[nf]);
    }
    #pragma unroll
    for (int mf = 0; mf < 2; mf++) {
        int r0 = wm*32 + mf*16 + (lane >> 2);
        #pragma unroll
        for (int nf = 0; nf < 4; nf++) {
            int n = wn*32 + nf*8 + (lane & 3)*2;
            float b0 = s_sb1[n], b1 = s_sb1[n + 1];
            *(__half2*)(s_hid + r0*SQh + n) =
                __floats2half2_rn(silu_f(acc[mf][nf][0] + b0), silu_f(acc[mf][nf][1] + b1));
            *(__half2*)(s_hid + (r0 + 8)*SQh + n) =
                __floats2half2_rn(silu_f(acc[mf][nf][2] + b0), silu_f(acc[mf][nf][3] + b1));
            #pragma unroll
            for (int u = 0; u < 4; u++) acc[mf][nf][u] = 0.f;
        }
    }

    for (int ct = 0; ct < 4; ct++) {
        __half* dbuf = s_bb + ((ct+1)&1)*BHB;
        const __half* src = (ct < 3) ? (g_wqT + (ct+1)*32) : g_woT;
        cpa16(dbuf + bn*SBh + bseg,     src + bn*DD + bseg);
        cpa16(dbuf + bn*SBh + bseg + 8, src + bn*DD + bseg + 8);
        CP_COMMIT;
        const __half* bB = s_bb + (ct & 1)*BHB;
        #pragma unroll
        for (int kk = 0; kk < 32; kk += 16) {
            int kg = ct*32 + kk;
            uint32_t afr[2][4];
            #pragma unroll
            for (int mf = 0; mf < 2; mf++) LDSMA(afr[mf], s_h, SQh, wm*32 + mf*16, kg);
            uint32_t bfr[4][2];
            LDSMB2(bfr[0], bB, SBh, wn*32, kk);
            LDSMB2(bfr[2], bB, SBh, wn*32 + 16, kk);
            #pragma unroll
            for (int mf = 0; mf < 2; mf++)
                #pragma unroll
                for (int nf = 0; nf < 4; nf++)
                    mma_f16(acc[mf][nf], afr[mf], bfr[nf]);
        }
        CP_WAIT0;
        __syncthreads();
    }
    #pragma unroll
    for (int mf = 0; mf < 2; mf++) {
        int r0 = wm*32 + mf*16 + (lane >> 2);
        #pragma unroll
        for (int nf = 0; nf < 4; nf++) {
            int n = wn*32 + nf*8 + (lane & 3)*2;
            float b0 = bq[n], b1 = bq[n + 1];
            *(__half2*)(s_q + r0*SQh + n) =
                __floats2half2_rn(acc[mf][nf][0] + b0, acc[mf][nf][1] + b1);
            *(__half2*)(s_q + (r0 + 8)*SQh + n) =
                __floats2half2_rn(acc[mf][nf][2] + b0, acc[mf][nf][3] + b1);
        }
    }
    __syncthreads();

    if (wid < 4) {
        float bacc[4] = {0.f, 0.f, 0.f, 0.f};
        #pragma unroll
        for (int kk = 0; kk < 128; kk += 16) {
            uint32_t afr[4];
            LDSMA(afr, s_hid, SQh, wid*16, kk);
            const __half* bp = s_sw2h + (lane >> 2)*SBW2 + kk + (lane & 3)*2;
            uint32_t bfr[2];
            bfr[0] = *(const uint32_t*)(bp);
            bfr[1] = *(const uint32_t*)(bp + 8);
            mma_f16(bacc, afr, bfr);
        }
        int r0 = wid*16 + (lane >> 2);
        int t = (lane & 3)*2;
        s_att[r0*8 + t]         = bacc[0];
        s_att[r0*8 + t + 1]     = bacc[1];
        s_att[(r0 + 8)*8 + t]     = bacc[2];
        s_att[(r0 + 8)*8 + t + 1] = bacc[3];
    }
    __syncthreads();

    {
        int n = tid >> 2, sub = tid & 3;
        int gg = s_g[n];
        int t0 = sub*2, t1 = t0 + 1;
        const __half2* K0 = (const __half2*)(g_KV16 + (size_t)(gg*TT + t0)*DD);
        const __half2* K1 = (const __half2*)(g_KV16 + (size_t)(gg*TT + t1)*DD);
        const __half2* qq = (const __half2*)(s_q + n*SQh);
        float sc0 = 0.f, sc1 = 0.f;
        #pragma unroll 8
        for (int k2 = 0; k2 < 64; k2++) {
            float2 q = __half22float2(qq[k2]);
            float2 a = __half22float2(K0[k2]);
            float2 b = __half22float2(K1[k2]);
            sc0 = fmaf(q.x, a.x, sc0); sc0 = fmaf(q.y, a.y, sc0);
            sc1 = fmaf(q.x, b.x, sc1); sc1 = fmaf(q.y, b.y, sc1);
        }
        float v0 = sc0 * 0.08838834764831845f + s_att[n*8 + t0] + s_sb2[t0];
        float v1 = sc1 * 0.08838834764831845f + s_att[n*8 + t1] + s_sb2[t1];
        float m = fmaxf(v0, v1);
        m = fmaxf(m, __shfl_xor_sync(0xffffffffu, m, 1, 4));
        m = fmaxf(m, __shfl_xor_sync(0xffffffffu, m, 2, 4));
        float e0 = __expf(v0 - m), e1 = __expf(v1 - m);
        float s = e0 + e1;
        s += __shfl_xor_sync(0xffffffffu, s, 1, 4);
        s += __shfl_xor_sync(0xffffffffu, s, 2, 4);
        float inv = __fdividef(1.f, s);
        s_att[n*8 + t0] = e0 * inv;
        s_att[n*8 + t1] = e1 * inv;
    }
    __syncthreads();

    #pragma unroll
    for (int it = 0; it < 16; it++) {
        int idx = tid + it*256;
        int n = idx >> 6, c = (idx & 63) * 2;
        const __half* Vr = g_KV16 + KV_OFF + (size_t)s_g[n]*TT*DD + c;
        const float* at = s_att + n*8;
        float a0 = 0.f, a1 = 0.f;
        #pragma unroll
        for (int t = 0; t < 8; t++) {
            float2 v = __half22float2(*(const __half2*)(Vr + t*DD));
            a0 = fmaf(at[t], v.x, a0);
            a1 = fmaf(at[t], v.y, a1);
        }
        *(__half2*)(s_q + n*SQh + c) = __floats2half2_rn(a0, a1);
    }
    __syncthreads();

    float acc2[2][4][4];
    #pragma unroll
    for (int mf = 0; mf < 2; mf++)
        #pragma unroll
        for (int nf = 0; nf < 4; nf++)
            #pragma unroll
            for (int u = 0; u < 4; u++) acc2[mf][nf][u] = 0.f;

    for (int c = 0; c < 4; c++) {
        if (c < 3) {
            __half* dbuf = s_bb + ((c+1)&1)*BHB;
            const __half* src = g_woT + (c+1)*32;
            cpa16(dbuf + bn*SBh + bseg,     src + bn*DD + bseg);
            cpa16(dbuf + bn*SBh + bseg + 8, src + bn*DD + bseg + 8);
            CP_COMMIT;
        }
        const __half* bB = s_bb + (c & 1)*BHB;
        #pragma unroll
        for (int kk = 0; kk < 32; kk += 16) {
            int kg = c*32 + kk;
            uint32_t afr[2][4];
            #pragma unroll
            for (int mf = 0; mf < 2; mf++) LDSMA(afr[mf], s_q, SQh, wm*32 + mf*16, kg);
            uint32_t bfr[4][2];
            LDSMB2(bfr[0], bB, SBh, wn*32, kk);
            LDSMB2(bfr[2], bB, SBh, wn*32 + 16, kk);
            #pragma unroll
            for (int mf = 0; mf < 2; mf++)
                #pragma unroll
                for (int nf = 0; nf < 4; nf++)
                    mma_f16(acc2[mf][nf], afr[mf], bfr[nf]);
        }
        if (c < 3) { CP_WAIT0; }
        __syncthreads();
    }

    #pragma unroll
    for (int mf = 0; mf < 2; mf++) {
        #pragma unroll
        for (int rr = 0; rr < 2; rr++) {
            int m = wm*32 + mf*16 + (lane >> 2) + rr*8;
            int n = n0 + m;
            if (n < NN) {
                __half* orow = g_h16 + (size_t)n*DD;
                const __half* hrow = s_h + m*SQh;
                #pragma unroll
                for (int nf = 0; nf < 4; nf++) {
                    int col = wn*32 + nf*8 + (lane & 3)*2;
                    float v0 = __half2float(hrow[col])     + acc2[mf][nf][rr*2 + 0] + bo[col];
                    float v1 = __half2float(hrow[col + 1]) + acc2[mf][nf][rr*2 + 1] + bo[col + 1];
                    *(__half2*)(orow + col) = __floats2half2_rn(v0, v1);
                }
            }
        }
    }
}

// ---------------- kernel 4: edge MLP, fp16 + ldmatrix, K=64 rounds, staged v4 scatter ----------------
#define TM 128
#define SAh 296
#define SOUT 132   // staging row stride (floats)

__global__ __launch_bounds__(256, 2)
void edge_kernel(const float* __restrict__ frac,
                 const int* __restrict__ edges, const int* __restrict__ e2g,
                 const float* __restrict__ eb1, const float* __restrict__ eb2)
{
    extern __shared__ __half smh[];
    __half* s_a  = smh;               // TM*SAh (75,776 B)
    __half* s_bb = smh + TM*SAh;      // 2*BKB  (36,864 B)
    float*  s_out = (float*)smh;      // aliases s_a for staged epilogue (67,584 B)
    __shared__ int s_i[TM], s_j[TM];

    int tid  = threadIdx.x, lane = tid & 31, wid = tid >> 5;
    int wm = wid >> 2, wn = wid & 3;
    int e0 = blockIdx.x * TM;

    if (tid < TM) {
        s_i[tid] = edges[e0 + tid];
        s_j[tid] = edges[EE + e0 + tid];
    }
    __syncthreads();

    // gather A rows + ew1T chunk0 (k 0..63)
    #pragma unroll
    for (int it = 0; it < 16; it++) {
        int idx = tid + it*256;
        int r = idx >> 4, seg = idx & 15;
        int e = r >> 1, p = r & 1;
        int node = p ? s_j[e] : s_i[e];
        cpa16(s_a + e*SAh + p*DD + seg*8, g_h16 + (size_t)node*DD + seg*8);
    }
    #pragma unroll
    for (int it = 0; it < 4; it++) {
        int idx = tid + it*256;
        int row = idx >> 3, seg = idx & 7;
        cpa16(s_bb + row*SBK + seg*8, g_ew1T + row*288 + seg*8);
    }
    CP_COMMIT;

    // tail cols 256..287 + counts
    if (tid < TM) {
        int e = tid;
        const float* lp = g_lip + e2g[e0 + e]*9;
        #pragma unroll
        for (int u = 0; u < 9; u++) s_a[e*SAh + 256 + u] = __float2half(lp[u]);
        int ii = s_i[e], jj = s_j[e];
        #pragma unroll
        for (int c = 0; c < 3; c++) {
            float dd = frac[jj*3 + c] - frac[ii*3 + c];
            dd -= floorf(dd);
            s_a[e*SAh + 265 + c] = __float2half(dd);
        }
        #pragma unroll
        for (int u = 268; u < 288; u++) s_a[e*SAh + u] = __half(0.f);
        atomicAdd(&g_cnt[ii], 1);
    }

    float acc[4][4][4];
    #pragma unroll
    for (int mf = 0; mf < 4; mf++)
        #pragma unroll
        for (int nf = 0; nf < 4; nf++)
            #pragma unroll
            for (int u = 0; u < 4; u++) acc[mf][nf][u] = 0.f;

    CP_WAIT0;
    __syncthreads();

    // ---- GEMM1 main: 4 rounds of K=64 (k 0..255) ----
    for (int ct = 0; ct < 4; ct++) {
        __half* dbuf = s_bb + ((ct+1)&1)*BKB;
        if (ct < 3) {
            #pragma unroll
            for (int it = 0; it < 4; it++) {
                int idx = tid + it*256;
                int row = idx >> 3, seg = idx & 7;
                cpa16(dbuf + row*SBK + seg*8, g_ew1T + row*288 + (ct+1)*64 + seg*8);
            }
        } else {
            #pragma unroll
            for (int it = 0; it < 2; it++) {
                int idx = tid + it*256;
                int row = idx >> 2, seg = idx & 3;
                cpa16(dbuf + row*SBK + seg*8, g_ew1T + row*288 + 256 + seg*8);
            }
        }
        CP_COMMIT;
        const __half* bB = s_bb + (ct & 1)*BKB;
        #pragma unroll
        for (int kk = 0; kk < 64; kk += 16) {
            int kg = ct*64 + kk;
            uint32_t afr[4][4];
            #pragma unroll
            for (int mf = 0; mf < 4; mf++) LDSMA(afr[mf], s_a, SAh, wm*64 + mf*16, kg);
            uint32_t bfr[4][2];
            LDSMB2(bfr[0], bB, SBK, wn*32, kk);
            LDSMB2(bfr[2], bB, SBK, wn*32 + 16, kk);
            #pragma unroll
            for (int mf = 0; mf < 4; mf++)
                #pragma unroll
                for (int nf = 0; nf < 4; nf++)
                    mma_f16(acc[mf][nf], afr[mf], bfr[nf]);
        }
        CP_WAIT0;
        __syncthreads();
    }

    // ---- GEMM1 tail: K=32 (k 256..287) in buf0; prefetch ew2 chunk0 -> buf1 ----
    {
        #pragma unroll
        for (int it = 0; it < 4; it++) {
            int idx = tid + it*256;
            int row = idx >> 3, seg = idx & 7;
            cpa16(s_bb + BKB + row*SBK + seg*8, g_ew2T + row*DD + seg*8);
        }
        CP_COMMIT;
        const __half* bB = s_bb;   // buf0
        #pragma unroll
        for (int kk = 0; kk < 32; kk += 16) {
            int kg = 256 + kk;
            uint32_t afr[4][4];
            #pragma unroll
            for (int mf = 0; mf < 4; mf++) LDSMA(afr[mf], s_a, SAh, wm*64 + mf*16, kg);
            uint32_t bfr[4][2];
            LDSMB2(bfr[0], bB, SBK, wn*32, kk);
            LDSMB2(bfr[2], bB, SBK, wn*32 + 16, kk);
            #pragma unroll
            for (int mf = 0; mf < 4; mf++)
                #pragma unroll
                for (int nf = 0; nf < 4; nf++)
                    mma_f16(acc[mf][nf], afr[mf], bfr[nf]);
        }
        CP_WAIT0;
        __syncthreads();
    }

    // hidden = silu(acc + eb1) -> s_a cols 0..127
    #pragma unroll
    for (int mf = 0; mf < 4; mf++) {
        int r0 = wm*64 + mf*16 + (lane >> 2);
        #pragma unroll
        for (int nf = 0; nf < 4; nf++) {
            int n = wn*32 + nf*8 + (lane & 3)*2;
            float b0 = eb1[n], b1 = eb1[n + 1];
            *(__half2*)(s_a + r0*SAh + n) =
                __floats2half2_rn(silu_f(acc[mf][nf][0] + b0), silu_f(acc[mf][nf][1] + b1));
            *(__half2*)(s_a + (r0 + 8)*SAh + n) =
                __floats2half2_rn(silu_f(acc[mf][nf][2] + b0), silu_f(acc[mf][nf][3] + b1));
            #pragma unroll
            for (int u = 0; u < 4; u++) acc[mf][nf][u] = 0.f;
        }
    }
    __syncthreads();

    // ---- GEMM2: 2 rounds of K=64; chunk c in buf[(1+c)&1] ----
    for (int c = 0; c < 2; c++) {
        if (c == 0) {
            #pragma unroll
            for (int it = 0; it < 4; it++) {
                int idx = tid + it*256;
                int row = idx >> 3, seg = idx & 7;
                cpa16(s_bb + row*SBK + seg*8, g_ew2T + row*DD + 64 + seg*8);
            }
            CP_COMMIT;
        }
        const __half* bB = s_bb + ((1 + c) & 1)*BKB;
        #pragma unroll
        for (int kk = 0; kk < 64; kk += 16) {
            int kg = c*64 + kk;
            uint32_t afr[4][4];
            #pragma unroll
            for (int mf = 0; mf < 4; mf++) LDSMA(afr[mf], s_a, SAh, wm*64 + mf*16, kg);
            uint32_t bfr[4][2];
            LDSMB2(bfr[0], bB, SBK, wn*32, kk);
            LDSMB2(bfr[2], bB, SBK, wn*32 + 16, kk);
            #pragma unroll
            for (int mf = 0; mf < 4; mf++)
                #pragma unroll
                for (int nf = 0; nf < 4; nf++)
                    mma_f16(acc[mf][nf], afr[mf], bfr[nf]);
        }
        if (c == 0) { CP_WAIT0; }
        __syncthreads();
    }

    // ---- staged epilogue: silu+bias -> smem fp32, then row-contiguous red.v4 ----
    #pragma unroll
    for (int mf = 0; mf < 4; mf++) {
        #pragma unroll
        for (int rr = 0; rr < 2; rr++) {
            int m = wm*64 + mf*16 + (lane >> 2) + rr*8;
            float* orow = s_out + m*SOUT;
            #pragma unroll
            for (int nf = 0; nf < 4; nf++) {
                int n = wn*32 + nf*8 + (lane & 3)*2;
                orow[n]     = silu_f(acc[mf][nf][rr*2 + 0] + eb2[n]);
                orow[n + 1] = silu_f(acc[mf][nf][rr*2 + 1] + eb2[n + 1]);
            }
        }
    }
    __syncthreads();

    // warp w scatters rows w, w+8, ...: one red.v4 per lane per row
    for (int r = wid; r < TM; r += 8) {
        float* ap = g_agg + (size_t)s_i[r]*DD + lane*4;
        const float* src = s_out + r*SOUT + lane*4;
        float v0 = src[0], v1 = src[1], v2 = src[2], v3 = src[3];
        asm volatile("red.global.add.v4.f32 [%0], {%1, %2, %3, %4};"
                     :: "l"(ap), "f"(v0), "f"(v1), "f"(v2), "f"(v3) : "memory");
    }
}

// ---------------- kernel 5: node MLP (unchanged from R14) ----------------
#define TN 128
#define SAn 264

__global__ __launch_bounds__(256, 2)
void node_kernel(const float* __restrict__ nfeat,
                 const float* __restrict__ nb1, const float* __restrict__ nb2,
                 float* __restrict__ out)
{
    extern __shared__ __half smh[];
    __half* s_a  = smh;
    __half* s_bb = smh + TN*SAn;
    __shared__ float s_cnt[TN];

    int tid  = threadIdx.x, lane = tid & 31, wid = tid >> 5;
    int wm = wid >> 2, wn = wid & 3;
    int n0 = blockIdx.x * TN;

    if (tid < TN) {
        int n = min(n0 + tid, NN - 1);
        s_cnt[tid] = fmaxf((float)g_cnt[n], 1.f);
    }
    #pragma unroll
    for (int it = 0; it < 8; it++) {
        int idx = tid + it*256;
        int r = idx >> 4, seg = idx & 15;
        int n = min(n0 + r, NN - 1);
        cpa16(s_a + r*SAn + seg*8, g_h16 + (size_t)n*DD + seg*8);
    }
    #pragma unroll
    for (int it = 0; it < 4; it++) {
        int idx = tid + it*256;
        int row = idx >> 3, seg = idx & 7;
        cpa16(s_bb + row*SBK + seg*8, g_nw1T + row*256 + seg*8);
    }
    CP_COMMIT;
    __syncthreads();

    #pragma unroll
    for (int it = 0; it < 16; it++) {
        int idx = tid + it*256;
        int r = idx >> 5, c4 = (idx & 31) * 4;
        int n = min(n0 + r, NN - 1);
        float inv = __fdividef(1.f, s_cnt[r]);
        float4 v = *(const float4*)(g_agg + (size_t)n*DD + c4);
        __half* dst = s_a + r*SAn + DD + c4;
        *(__half2*)(dst)     = __floats2half2_rn(v.x * inv, v.y * inv);
        *(__half2*)(dst + 2) = __floats2half2_rn(v.z * inv, v.w * inv);
    }

    float acc[4][4][4];
    #pragma unroll
    for (int mf = 0; mf < 4; mf++)
        #pragma unroll
        for (int nf = 0; nf < 4; nf++)
            #pragma unroll
            for (int u = 0; u < 4; u++) acc[mf][nf][u] = 0.f;

    CP_WAIT0;
    __syncthreads();

    // ---- GEMM1: K=256, 4 rounds of K=64 ----
    for (int ct = 0; ct < 4; ct++) {
        __half* dbuf = s_bb + ((ct+1)&1)*BKB;
        const __half* src; int rstr; int k0;
        if (ct < 3) { src = g_nw1T; rstr = 256; k0 = (ct+1)*64; }
        else        { src = g_nw2T; rstr = 128; k0 = 0; }
        #pragma unroll
        for (int it = 0; it < 4; it++) {
            int idx = tid + it*256;
            int row = idx >> 3, seg = idx & 7;
            cpa16(dbuf + row*SBK + seg*8, src + (size_t)row*rstr + k0 + seg*8);
        }
        CP_COMMIT;
        const __half* bB = s_bb + (ct & 1)*BKB;
        #pragma unroll
        for (int kk = 0; kk < 64; kk += 16) {
            int kg = ct*64 + kk;
            uint32_t afr[4][4];
            #pragma unroll
            for (int mf = 0; mf < 4; mf++) LDSMA(afr[mf], s_a, SAn, wm*64 + mf*16, kg);
            uint32_t bfr[4][2];
            LDSMB2(bfr[0], bB, SBK, wn*32, kk);
            LDSMB2(bfr[2], bB, SBK, wn*32 + 16, kk);
            #pragma unroll
            for (int mf = 0; mf < 4; mf++)
                #pragma unroll
                for (int nf = 0; nf < 4; nf++)
                    mma_f16(acc[mf][nf], afr[mf], bfr[nf]);
        }
        CP_WAIT0;
        __syncthreads();
    }

    // hidden -> s_a cols 0..127
    #pragma unroll
    for (int mf = 0; mf < 4; mf++) {
        int r0 = wm*64 + mf*16 + (lane >> 2);
        #pragma unroll
        for (int nf = 0; nf < 4; nf++) {
            int n = wn*32 + nf*8 + (lane & 3)*2;
            float b0 = nb1[n], b1 = nb1[n + 1];
            *(__half2*)(s_a + r0*SAn + n) =
                __floats2half2_rn(silu_f(acc[mf][nf][0] + b0), silu_f(acc[mf][nf][1] + b1));
            *(__half2*)(s_a + (r0 + 8)*SAn + n) =
                __floats2half2_rn(silu_f(acc[mf][nf][2] + b0), silu_f(acc[mf][nf][3] + b1));
            #pragma unroll
            for (int u = 0; u < 4; u++) acc[mf][nf][u] = 0.f;
        }
    }
    __syncthreads();

    // ---- GEMM2: K=128, 2 rounds of K=64; nw2 chunk0 in buf0 ----
    for (int c = 0; c < 2; c++) {
        if (c == 0) {
            #pragma unroll
            for (int it = 0; it < 4; it++) {
                int idx = tid + it*256;
                int row = idx >> 3, seg = idx & 7;
                cpa16(s_bb + BKB + row*SBK + seg*8, g_nw2T + row*DD + 64 + seg*8);
            }
            CP_COMMIT;
        }
        const __half* bB = s_bb + (c & 1)*BKB;
        #pragma unroll
        for (int kk = 0; kk < 64; kk += 16) {
            int kg = c*64 + kk;
            uint32_t afr[4][4];
            #pragma unroll
            for (int mf = 0; mf < 4; mf++) LDSMA(afr[mf], s_a, SAn, wm*64 + mf*16, kg);
            uint32_t bfr[4][2];
            LDSMB2(bfr[0], bB, SBK, wn*32, kk);
            LDSMB2(bfr[2], bB, SBK, wn*32 + 16, kk);
            #pragma unroll
            for (int mf = 0; mf < 4; mf++)
                #pragma unroll
                for (int nf = 0; nf < 4; nf++)
                    mma_f16(acc[mf][nf], afr[mf], bfr[nf]);
        }
        if (c == 0) { CP_WAIT0; }
        __syncthreads();
    }

    // epilogue: out = nfeat + silu(acc + nb2)
    #pragma unroll
    for (int mf = 0; mf < 4; mf++) {
        #pragma unroll
        for (int rr = 0; rr < 2; rr++) {
            int m = wm*64 + mf*16 + (lane >> 2) + rr*8;
            int n = n0 + m;
            if (n < NN) {
                const float* nfr = nfeat + (size_t)n*DD;
                float* orow = out + (size_t)n*DD;
                #pragma unroll
                for (int nf = 0; nf < 4; nf++) {
                    int col = wn*32 + nf*8 + (lane & 3)*2;
                    orow[col]     = nfr[col]     + silu_f(acc[mf][nf][rr*2 + 0] + nb2[col]);
                    orow[col + 1] = nfr[col + 1] + silu_f(acc[mf][nf][rr*2 + 1] + nb2[col + 1]);
                }
            }
        }
    }
}

// ---------------- launch ----------------
extern "C" void kernel_launch(void* const* d_in, const int* in_sizes, int n_in,
                              void* d_out, int out_size)
{
    const float* node_features = (const float*)d_in[0];
    const float* cond = (const float*)d_in[1];
    const int*   n2g  = (const int*)d_in[2];
    const float* frac = (const float*)d_in[3];
    const float* lat  = (const float*)d_in[4];
    const int*   edges= (const int*)d_in[5];
    const int*   e2g  = (const int*)d_in[6];
    const float* wq = (const float*)d_in[7];
    const float* bq = (const float*)d_in[8];
    const float* wk = (const float*)d_in[9];
    const float* bk = (const float*)d_in[10];
    const float* wv = (const float*)d_in[11];
    const float* bv = (const float*)d_in[12];
    const float* wo = (const float*)d_in[13];
    const float* bo = (const float*)d_in[14];
    const float* sw1= (const float*)d_in[15];
    const float* sb1= (const float*)d_in[16];
    const float* sw2= (const float*)d_in[17];
    const float* sb2= (const float*)d_in[18];
    const float* ew1= (const float*)d_in[19];
    const float* eb1= (const float*)d_in[20];
    const float* ew2= (const float*)d_in[21];
    const float* eb2= (const float*)d_in[22];
    const float* nw1= (const float*)d_in[23];
    const float* nb1= (const float*)d_in[24];
    const float* nw2= (const float*)d_in[25];
    const float* nb2= (const float*)d_in[26];
    float* out = (float*)d_out;

    const int attn_smem = (3*AT*SQh + 128*SBh + 2*BHB + AT*40 + 8*SBW2) * 2
                        + (128 + 8 + AT*8) * 4;
    const int edge_smem = (TM*SAh + 2*BKB) * 2;    // 112,640 B
    const int node_smem = (TN*SAn + 2*BKB) * 2;    // 104,448 B
    cudaFuncSetAttribute(attn_kernel, cudaFuncAttributeMaxDynamicSharedMemorySize, attn_smem);
    cudaFuncSetAttribute(edge_kernel, cudaFuncAttributeMaxDynamicSharedMemorySize, edge_smem);
    cudaFuncSetAttribute(node_kernel, cudaFuncAttributeMaxDynamicSharedMemorySize, node_smem);

    prep_kernel<<<BB*TT + BB, 128>>>(cond, wk, bk, wv, bv, lat);
    convw_kernel<<<549, 256>>>(ew1, ew2, nw1, nw2, wq, wo, sw1, sw2);
    zero_kernel<<<(NN*DD + 255) / 256, 256>>>();
    attn_kernel<<<(NN + AT - 1) / AT, 256, attn_smem>>>(node_features, frac, n2g,
                                                        bq, bo, sb1, sb2);
    edge_kernel<<<EE / TM, 256, edge_smem>>>(frac, edges, e2g, eb1, eb2);
    node_kernel<<<(NN + TN - 1) / TN, 256, node_smem>>>(node_features, nb1, nb2, out);
}

// round 16
// speedup vs baseline: 1.3030x; 1.0291x over previous
#include <cuda_runtime.h>
#include <cuda_fp16.h>
#include <math.h>
#include <stdint.h>

#define NN 50000
#define EE 800000
#define BB 256
#define DD 128
#define TT 8
#define KV_OFF (BB*TT*DD)

// ---------------- scratch (no allocations allowed) ----------------
__device__ __half g_h16[(size_t)NN*DD];     // post-attention node states (fp16)
__device__ __half g_KV16[2*BB*TT*DD];       // Kc then Vc (fp16)
__device__ float  g_lip[BB*9];              // lattice inner products
__device__ float  g_agg[(size_t)NN*DD];     // scatter sums (fp32 atomics)
__device__ int    g_cnt[NN];                // scatter counts
// pre-converted, pre-transposed fp16 weights [N][K]
__device__ __half g_ew1T[DD*288];           // K padded 272->288
__device__ __half g_ew2T[DD*DD];
__device__ __half g_nw1T[DD*256];
__device__ __half g_nw2T[DD*DD];
__device__ __half g_wqT[DD*DD];
__device__ __half g_woT[DD*DD];
__device__ __half g_sw1T[DD*32];            // K padded 24->32
__device__ __half g_sw2h[8*DD];             // sw2 transposed [8][128] fp16
__device__ __half g_wkT[DD*DD];
__device__ __half g_wvT[DD*DD];

__device__ __forceinline__ float silu_f(float x) {
    return __fdividef(x, 1.f + __expf(-x));
}

// fp16 mma, fp32 accumulate
__device__ __forceinline__ void mma_f16(float* c, const uint32_t* a, const uint32_t* b) {
    asm volatile(
        "mma.sync.aligned.m16n8k16.row.col.f32.f16.f16.f32 "
        "{%0,%1,%2,%3}, {%4,%5,%6,%7}, {%8,%9}, {%0,%1,%2,%3};\n"
        : "+f"(c[0]), "+f"(c[1]), "+f"(c[2]), "+f"(c[3])
        : "r"(a[0]), "r"(a[1]), "r"(a[2]), "r"(a[3]), "r"(b[0]), "r"(b[1]));
}

__device__ __forceinline__ void cpa16(void* dst, const void* src) {
    uint32_t d = (uint32_t)__cvta_generic_to_shared(dst);
    asm volatile("cp.async.cg.shared.global [%0], [%1], 16;" :: "r"(d), "l"(src));
}
#define CP_COMMIT asm volatile("cp.async.commit_group;" ::: "memory")
#define CP_WAIT0  asm volatile("cp.async.wait_group 0;" ::: "memory")

// ldmatrix x4
__device__ __forceinline__ void ldsm4(uint32_t* r, const __half* p) {
    uint32_t a = (uint32_t)__cvta_generic_to_shared(p);
    asm volatile("ldmatrix.sync.aligned.m8n8.x4.shared.b16 {%0,%1,%2,%3}, [%4];"
        : "=r"(r[0]), "=r"(r[1]), "=r"(r[2]), "=r"(r[3]) : "r"(a));
}
#define LDSMA(afr, base, SAx, rowbase, kg)                                        \
    ldsm4(afr, (base) + ((rowbase) + (lane & 15))*(SAx) + (kg) + ((lane >> 4) << 3))
#define LDSMB2(b4, bB, SBx, ncol, kk)                                             \
    ldsm4(b4, (bB) + ((ncol) + (lane & 7) + ((lane >> 4) << 3))*(SBx) + (kk) + (((lane >> 3) & 1) << 3))

// attn B geometry: 128 n-rows x (32 k + 8 pad)
#define SBh 40
#define BHB (128*SBh)
// edge/node/prep B geometry: 128 n-rows x (64 k + 8 pad)
#define SBK 72
#define BKB (128*SBK)

// ---------------- kernel 1: lattice gram ----------------
__global__ void lip_kernel(const float* __restrict__ lat)
{
    int idx = blockIdx.x*256 + threadIdx.x;
    if (idx < BB*9) {
        int b = idx / 9, t = idx - b*9;
        int i = t / 3, k = t - (t/3)*3;
        const float* L = lat + b*9;
        g_lip[idx] = L[i*3+0]*L[k*3+0] + L[i*3+1]*L[k*3+1] + L[i*3+2]*L[k*3+2];
    }
}

// ---------------- kernel 1a: K/V projection via fp16 MMA ----------------
// 16 tiles of 128 (b,t) rows. 8 warps (2 wm x 4 wn), warp tile 64x32.
#define SPh 136

__global__ __launch_bounds__(256, 2)
void prep_kernel(const float* __restrict__ cond,
                 const float* __restrict__ bk, const float* __restrict__ bv)
{
    extern __shared__ __half smh[];
    __half* s_a  = smh;               // 128*SPh
    __half* s_bb = smh + 128*SPh;     // 2*BKB

    int tid = threadIdx.x, lane = tid & 31, wid = tid >> 5;
    int wm = wid >> 2, wn = wid & 3;
    int r0g = blockIdx.x * 128;       // global row base (b*TT+t index)

    // cond tile fp32 -> fp16
    #pragma unroll
    for (int it = 0; it < 16; it++) {
        int idx = tid + it*256;
        int r = idx >> 5, c4 = (idx & 31) * 4;
        float4 v = *(const float4*)(cond + (size_t)(r0g + r)*DD + c4);
        __half* dst = s_a + r*SPh + c4;
        *(__half2*)(dst)     = __floats2half2_rn(v.x, v.y);
        *(__half2*)(dst + 2) = __floats2half2_rn(v.z, v.w);
    }
    // wkT chunk0 (k 0..63)
    #pragma unroll
    for (int it = 0; it < 4; it++) {
        int idx = tid + it*256;
        int row = idx >> 3, seg = idx & 7;
        cpa16(s_bb + row*SBK + seg*8, g_wkT + row*DD + seg*8);
    }
    CP_COMMIT;
    __syncthreads();   // s_a ready (scalar stores)

    float acc[4][4][4];
    #pragma unroll
    for (int mf = 0; mf < 4; mf++)
        #pragma unroll
        for (int nf = 0; nf < 4; nf++)
            #pragma unroll
            for (int u = 0; u < 4; u++) acc[mf][nf][u] = 0.f;

    CP_WAIT0;
    __syncthreads();

    // 4 chunks: wk[0:64], wk[64:128], wv[0:64], wv[64:128]
    for (int ct = 0; ct < 4; ct++) {
        if (ct < 3) {
            const __half* src = (ct == 0) ? (g_wkT + 64)
                              : (ct == 1) ? g_wvT : (g_wvT + 64);
            __half* dbuf = s_bb + ((ct+1)&1)*BKB;
            #pragma unroll
            for (int it = 0; it < 4; it++) {
                int idx = tid + it*256;
                int row = idx >> 3, seg = idx & 7;
                cpa16(dbuf + row*SBK + seg*8, src + row*DD + seg*8);
            }
            CP_COMMIT;
        }
        const __half* bB = s_bb + (ct & 1)*BKB;
        int kg = (ct & 1) * 64;
        #pragma unroll
        for (int kk = 0; kk < 64; kk += 16) {
            uint32_t afr[4][4];
            #pragma unroll
            for (int mf = 0; mf < 4; mf++) LDSMA(afr[mf], s_a, SPh, wm*64 + mf*16, kg + kk);
            uint32_t bfr[4][2];
            LDSMB2(bfr[0], bB, SBK, wn*32, kk);
            LDSMB2(bfr[2], bB, SBK, wn*32 + 16, kk);
            #pragma unroll
            for (int mf = 0; mf < 4; mf++)
                #pragma unroll
                for (int nf = 0; nf < 4; nf++)
                    mma_f16(acc[mf][nf], afr[mf], bfr[nf]);
        }
        if (ct == 1) {
            // K epilogue
            #pragma unroll
            for (int mf = 0; mf < 4; mf++) {
                #pragma unroll
                for (int rr = 0; rr < 2; rr++) {
                    int m = wm*64 + mf*16 + (lane >> 2) + rr*8;
                    __half* orow = g_KV16 + (size_t)(r0g + m)*DD;
                    #pragma unroll
                    for (int nf = 0; nf < 4; nf++) {
                        int col = wn*32 + nf*8 + (lane & 3)*2;
                        *(__half2*)(orow + col) = __floats2half2_rn(
                            acc[mf][nf][rr*2 + 0] + bk[col],
                            acc[mf][nf][rr*2 + 1] + bk[col + 1]);
                        acc[mf][nf][rr*2 + 0] = 0.f;
                        acc[mf][nf][rr*2 + 1] = 0.f;
                    }
                }
            }
        }
        if (ct < 3) { CP_WAIT0; }
        __syncthreads();
    }
    // V epilogue
    #pragma unroll
    for (int mf = 0; mf < 4; mf++) {
        #pragma unroll
        for (int rr = 0; rr < 2; rr++) {
            int m = wm*64 + mf*16 + (lane >> 2) + rr*8;
            __half* orow = g_KV16 + KV_OFF + (size_t)(r0g + m)*DD;
            #pragma unroll
            for (int nf = 0; nf < 4; nf++) {
                int col = wn*32 + nf*8 + (lane & 3)*2;
                *(__half2*)(orow + col) = __floats2half2_rn(
                    acc[mf][nf][rr*2 + 0] + bv[col],
                    acc[mf][nf][rr*2 + 1] + bv[col + 1]);
            }
        }
    }
}

// ---------------- kernel 1b: convert+transpose weights ----------------
__global__ void convw_kernel(const float* __restrict__ ew1, const float* __restrict__ ew2,
                             const float* __restrict__ nw1, const float* __restrict__ nw2,
                             const float* __restrict__ wq,  const float* __restrict__ wo,
                             const float* __restrict__ sw1, const float* __restrict__ sw2,
                             const float* __restrict__ wk,  const float* __restrict__ wv)
{
    int idx = blockIdx.x * 256 + threadIdx.x;
    if (idx < 36864) {
        int n = idx / 288, k = idx % 288;
        g_ew1T[idx] = (k < 268) ? __float2half(ew1[k*DD + n]) : __half(0.f);
    } else if (idx < 53248) {
        int j = idx - 36864; int n = j / DD, k = j % DD;
        g_ew2T[j] = __float2half(ew2[k*DD + n]);
    } else if (idx < 86016) {
        int j = idx - 53248; int n = j / 256, k = j % 256;
        g_nw1T[j] = __float2half(nw1[k*DD + n]);
    } else if (idx < 102400) {
        int j = idx - 86016; int n = j / DD, k = j % DD;
        g_nw2T[j] = __float2half(nw2[k*DD + n]);
    } else if (idx < 118784) {
        int j = idx - 102400; int n = j / DD, k = j % DD;
        g_wqT[j] = __float2half(wq[k*DD + n]);
    } else if (idx < 135168) {
        int j = idx - 118784; int n = j / DD, k = j % DD;
        g_woT[j] = __float2half(wo[k*DD + n]);
    } else if (idx < 139264) {
        int j = idx - 135168; int n = j / 32, k = j % 32;
        g_sw1T[j] = (k < 24) ? __float2half(sw1[k*DD + n]) : __half(0.f);
    } else if (idx < 140288) {
        int j = idx - 139264; int t = j >> 7, k = j & 127;
        g_sw2h[j] = __float2half(sw2[k*8 + t]);
    } else if (idx < 156672) {
        int j = idx - 140288; int n = j / DD, k = j % DD;
        g_wkT[j] = __float2half(wk[k*DD + n]);
    } else if (idx < 173056) {
        int j = idx - 156672; int n = j / DD, k = j % DD;
        g_wvT[j] = __float2half(wv[k*DD + n]);
    }
}

// ---------------- kernel 2: zero scatter buffers ----------------
__global__ void zero_kernel()
{
    int idx = blockIdx.x * blockDim.x + threadIdx.x;
    if (idx < NN*DD) g_agg[idx] = 0.f;
    if (idx < NN)    g_cnt[idx] = 0;
}

// ---------------- kernel 3: cross-attention, smem K/V cache ----------------
#define AT 64
#define SQh 136
#define SBW2 136
#define KVROW 136   // cached K/V row stride (halfs); 16B aligned, conflict-free

__global__ __launch_bounds__(256, 2)
void attn_kernel(const float* __restrict__ nfeat, const float* __restrict__ frac,
                 const int* __restrict__ n2g,
                 const float* __restrict__ bq, const float* __restrict__ bo,
                 const float* __restrict__ sb1, const float* __restrict__ sb2)
{
    extern __shared__ char smraw[];
    __half* s_h    = (__half*)smraw;
    __half* s_hid  = s_h + AT*SQh;
    __half* s_q    = s_hid + AT*SQh;
    __half* s_bsw  = s_q + AT*SQh;
    __half* s_bb   = s_bsw + 128*SBh;
    __half* s_enc  = s_bb + 2*BHB;
    __half* s_sw2h = s_enc + AT*40;
    float*  s_sb1 = (float*)(s_sw2h + 8*SBW2);
    float*  s_sb2 = s_sb1 + 128;
    float*  s_att = s_sb2 + 8;
    __half* s_kv  = (__half*)(s_att + AT*8);   // 3 graphs x 16 rows x 136
    __shared__ int s_g[AT];

    int tid = threadIdx.x, lane = tid & 31, wid = tid >> 5;
    int wm = wid >> 2, wn = wid & 3;
    int n0 = blockIdx.x * AT;
    int bn = tid >> 1, bseg = (tid & 1) * 16;

    if (tid < AT) s_g[tid] = n2g[min(n0 + tid, NN - 1)];

    cpa16(s_bsw + bn*SBh + bseg,     g_sw1T + bn*32 + bseg);
    cpa16(s_bsw + bn*SBh + bseg + 8, g_sw1T + bn*32 + bseg + 8);
    if (tid < 128) {
        int row = tid >> 4, seg = (tid & 15) * 8;
        cpa16(s_sw2h + row*SBW2 + seg, g_sw2h + row*DD + seg);
    }
    if (tid < 32) cpa16(s_sb1 + tid*4, sb1 + tid*4);
    if (tid < 2)  cpa16(s_sb2 + tid*4, sb2 + tid*4);
    cpa16(s_bb + bn*SBh + bseg,     g_wqT + bn*DD + bseg);
    cpa16(s_bb + bn*SBh + bseg + 8, g_wqT + bn*DD + bseg + 8);
    CP_COMMIT;

    #pragma unroll
    for (int it = 0; it < 8; it++) {
        int idx = tid + it*256;
        int r = idx >> 5, c4 = (idx & 31) * 4;
        int n = min(n0 + r, NN - 1);
        float4 v = *(const float4*)(nfeat + (size_t)n*DD + c4);
        __half* dst = s_h + r*SQh + c4;
        *(__half2*)(dst)     = __floats2half2_rn(v.x, v.y);
        *(__half2*)(dst + 2) = __floats2half2_rn(v.z, v.w);
    }
    {
        int n = tid >> 2, sub = tid & 3;
        int nn = min(n0 + n, NN - 1);
        float f0 = frac[nn*3+0], f1 = frac[nn*3+1], f2 = frac[nn*3+2];
        #pragma unroll
        for (int k = sub; k < 24; k += 4) {
            int ii = k % 12, c = ii >> 2, j = ii & 3;
            float fv = (c == 0) ? f0 : ((c == 1) ? f1 : f2);
            float ph = fv * ((float)(1 << j) * 3.14159265358979323846f);
            s_enc[n*40 + k] = __float2half((k < 12) ? sinf(ph) : cosf(ph));
        }
        s_enc[n*40 + 24 + sub] = __half(0.f);
        s_enc[n*40 + 28 + sub] = __half(0.f);
    }
    CP_WAIT0;
    __syncthreads();

    // K/V smem cache for the tile's graphs (n2g sorted -> small span)
    int gmin = s_g[0];
    int span = s_g[AT-1] - gmin + 1;
    bool use_s = (span <= 3);
    if (use_s) {
        for (int i = tid; i < span*256; i += 256) {
            int g = i >> 8, rem = i & 255;
            int r = rem >> 4, seg = rem & 15;
            const __half* src = (r < 8)
                ? g_KV16 + (size_t)(gmin + g)*TT*DD + r*DD + seg*8
                : g_KV16 + KV_OFF + (size_t)(gmin + g)*TT*DD + (r - 8)*DD + seg*8;
            cpa16(s_kv + (g*16 + r)*KVROW + seg*8, src);
        }
        CP_COMMIT;
    }

    float acc[2][4][4];
    #pragma unroll
    for (int mf = 0; mf < 2; mf++)
        #pragma unroll
        for (int nf = 0; nf < 4; nf++)
            #pragma unroll
            for (int u = 0; u < 4; u++) acc[mf][nf][u] = 0.f;

    #pragma unroll
    for (int kk = 0; kk < 32; kk += 16) {
        uint32_t afr[2][4];
        #pragma unroll
        for (int mf = 0; mf < 2; mf++) LDSMA(afr[mf], s_enc, 40, wm*32 + mf*16, kk);
        uint32_t bfr[4][2];
        LDSMB2(bfr[0], s_bsw, SBh, wn*32, kk);
        LDSMB2(bfr[2], s_bsw, SBh, wn*32 + 16, kk);
        #pragma unroll
        for (int mf = 0; mf < 2; mf++)
            #pragma unroll
            for (int nf = 0; nf < 4; nf++)
                mma_f16(acc[mf][nf], afr[mf], bfr[nf]);
    }
    #pragma unroll
    for (int mf = 0; mf < 2; mf++) {
        int r0 = wm*32 + mf*16 + (lane >> 2);
        #pragma unroll
        for (int nf = 0; nf < 4; nf++) {
            int n = wn*32 + nf*8 + (lane & 3)*2;
            float b0 = s_sb1[n], b1 = s_sb1[n + 1];
            *(__half2*)(s_hid + r0*SQh + n) =
                __floats2half2_rn(silu_f(acc[mf][nf][0] + b0), silu_f(acc[mf][nf][1] + b1));
            *(__half2*)(s_hid + (r0 + 8)*SQh + n) =
                __floats2half2_rn(silu_f(acc[mf][nf][2] + b0), silu_f(acc[mf][nf][3] + b1));
            #pragma unroll
            for (int u = 0; u < 4; u++) acc[mf][nf][u] = 0.f;
        }
    }

    for (int ct = 0; ct < 4; ct++) {
        __half* dbuf = s_bb + ((ct+1)&1)*BHB;
        const __half* src = (ct < 3) ? (g_wqT + (ct+1)*32) : g_woT;
        cpa16(dbuf + bn*SBh + bseg,     src + bn*DD + bseg);
        cpa16(dbuf + bn*SBh + bseg + 8, src + bn*DD + bseg + 8);
        CP_COMMIT;
        const __half* bB = s_bb + (ct & 1)*BHB;
        #pragma unroll
        for (int kk = 0; kk < 32; kk += 16) {
            int kg = ct*32 + kk;
            uint32_t afr[2][4];
            #pragma unroll
            for (int mf = 0; mf < 2; mf++) LDSMA(afr[mf], s_h, SQh, wm*32 + mf*16, kg);
            uint32_t bfr[4][2];
            LDSMB2(bfr[0], bB, SBh, wn*32, kk);
            LDSMB2(bfr[2], bB, SBh, wn*32 + 16, kk);
            #pragma unroll
            for (int mf = 0; mf < 2; mf++)
                #pragma unroll
                for (int nf = 0; nf < 4; nf++)
                    mma_f16(acc[mf][nf], afr[mf], bfr[nf]);
        }
        CP_WAIT0;
        __syncthreads();
    }
    #pragma unroll
    for (int mf = 0; mf < 2; mf++) {
        int r0 = wm*32 + mf*16 + (lane >> 2);
        #pragma unroll
        for (int nf = 0; nf < 4; nf++) {
            int n = wn*32 + nf*8 + (lane & 3)*2;
            float b0 = bq[n], b1 = bq[n + 1];
            *(__half2*)(s_q + r0*SQh + n) =
                __floats2half2_rn(acc[mf][nf][0] + b0, acc[mf][nf][1] + b1);
            *(__half2*)(s_q + (r0 + 8)*SQh + n) =
                __floats2half2_rn(acc[mf][nf][2] + b0, acc[mf][nf][3] + b1);
        }
    }
    __syncthreads();

    if (wid < 4) {
        float bacc[4] = {0.f, 0.f, 0.f, 0.f};
        #pragma unroll
        for (int kk = 0; kk < 128; kk += 16) {
            uint32_t afr[4];
            LDSMA(afr, s_hid, SQh, wid*16, kk);
            const __half* bp = s_sw2h + (lane >> 2)*SBW2 + kk + (lane & 3)*2;
            uint32_t bfr[2];
            bfr[0] = *(const uint32_t*)(bp);
            bfr[1] = *(const uint32_t*)(bp + 8);
            mma_f16(bacc, afr, bfr);
        }
        int r0 = wid*16 + (lane >> 2);
        int t = (lane & 3)*2;
        s_att[r0*8 + t]         = bacc[0];
        s_att[r0*8 + t + 1]     = bacc[1];
        s_att[(r0 + 8)*8 + t]     = bacc[2];
        s_att[(r0 + 8)*8 + t + 1] = bacc[3];
    }
    __syncthreads();

    {
        int n = tid >> 2, sub = tid & 3;
        int gg = s_g[n];
        int t0 = sub*2, t1 = t0 + 1;
        const __half* Kb = use_s ? (s_kv + (gg - gmin)*16*KVROW)
                                 : (g_KV16 + (size_t)gg*TT*DD);
        int kstr = use_s ? KVROW : DD;
        const __half2* K0 = (const __half2*)(Kb + t0*kstr);
        const __half2* K1 = (const __half2*)(Kb + t1*kstr);
        const __half2* qq = (const __half2*)(s_q + n*SQh);
        float sc0 = 0.f, sc1 = 0.f;
        #pragma unroll 8
        for (int k2 = 0; k2 < 64; k2++) {
            float2 q = __half22float2(qq[k2]);
            float2 a = __half22float2(K0[k2]);
            float2 b = __half22float2(K1[k2]);
            sc0 = fmaf(q.x, a.x, sc0); sc0 = fmaf(q.y, a.y, sc0);
            sc1 = fmaf(q.x, b.x, sc1); sc1 = fmaf(q.y, b.y, sc1);
        }
        float v0 = sc0 * 0.08838834764831845f + s_att[n*8 + t0] + s_sb2[t0];
        float v1 = sc1 * 0.08838834764831845f + s_att[n*8 + t1] + s_sb2[t1];
        float m = fmaxf(v0, v1);
        m = fmaxf(m, __shfl_xor_sync(0xffffffffu, m, 1, 4));
        m = fmaxf(m, __shfl_xor_sync(0xffffffffu, m, 2, 4));
        float e0 = __expf(v0 - m), e1 = __expf(v1 - m);
        float s = e0 + e1;
        s += __shfl_xor_sync(0xffffffffu, s, 1, 4);
        s += __shfl_xor_sync(0xffffffffu, s, 2, 4);
        float inv = __fdividef(1.f, s);
        s_att[n*8 + t0] = e0 * inv;
        s_att[n*8 + t1] = e1 * inv;
    }
    __syncthreads();

    #pragma unroll
    for (int it = 0; it < 16; it++) {
        int idx = tid + it*256;
        int n = idx >> 6, c = (idx & 63) * 2;
        int gg = s_g[n];
        const __half* Vr;
        int vstr;
        if (use_s) { Vr = s_kv + (gg - gmin)*16*KVROW + 8*KVROW + c; vstr = KVROW; }
        else       { Vr = g_KV16 + KV_OFF + (size_t)gg*TT*DD + c;    vstr = DD; }
        const float* at = s_att + n*8;
        float a0 = 0.f, a1 = 0.f;
        #pragma unroll
        for (int t = 0; t < 8; t++) {
            float2 v = __half22float2(*(const __half2*)(Vr + t*vstr));
            a0 = fmaf(at[t], v.x, a0);
            a1 = fmaf(at[t], v.y, a1);
        }
        *(__half2*)(s_q + n*SQh + c) = __floats2half2_rn(a0, a1);
    }
    __syncthreads();

    float acc2[2][4][4];
    #pragma unroll
    for (int mf = 0; mf < 2; mf++)
        #pragma unroll
        for (int nf = 0; nf < 4; nf++)
            #pragma unroll
            for (int u = 0; u < 4; u++) acc2[mf][nf][u] = 0.f;

    for (int c = 0; c < 4; c++) {
        if (c < 3) {
            __half* dbuf = s_bb + ((c+1)&1)*BHB;
            const __half* src = g_woT + (c+1)*32;
            cpa16(dbuf + bn*SBh + bseg,     src + bn*DD + bseg);
            cpa16(dbuf + bn*SBh + bseg + 8, src + bn*DD + bseg + 8);
            CP_COMMIT;
        }
        const __half* bB = s_bb + (c & 1)*BHB;
        #pragma unroll
        for (int kk = 0; kk < 32; kk += 16) {
            int kg = c*32 + kk;
            uint32_t afr[2][4];
            #pragma unroll
            for (int mf = 0; mf < 2; mf++) LDSMA(afr[mf], s_q, SQh, wm*32 + mf*16, kg);
            uint32_t bfr[4][2];
            LDSMB2(bfr[0], bB, SBh, wn*32, kk);
            LDSMB2(bfr[2], bB, SBh, wn*32 + 16, kk);
            #pragma unroll
            for (int mf = 0; mf < 2; mf++)
                #pragma unroll
                for (int nf = 0; nf < 4; nf++)
                    mma_f16(acc2[mf][nf], afr[mf], bfr[nf]);
        }
        if (c < 3) { CP_WAIT0; }
        __syncthreads();
    }

    #pragma unroll
    for (int mf = 0; mf < 2; mf++) {
        #pragma unroll
        for (int rr = 0; rr < 2; rr++) {
            int m = wm*32 + mf*16 + (lane >> 2) + rr*8;
            int n = n0 + m;
            if (n < NN) {
                __half* orow = g_h16 + (size_t)n*DD;
                const __half* hrow = s_h + m*SQh;
                #pragma unroll
                for (int nf = 0; nf < 4; nf++) {
                    int col = wn*32 + nf*8 + (lane & 3)*2;
                    float v0 = __half2float(hrow[col])     + acc2[mf][nf][rr*2 + 0] + bo[col];
                    float v1 = __half2float(hrow[col + 1]) + acc2[mf][nf][rr*2 + 1] + bo[col + 1];
                    *(__half2*)(orow + col) = __floats2half2_rn(v0, v1);
                }
            }
        }
    }
}

// ---------------- kernel 4: edge MLP (unchanged from R15) ----------------
#define TM 128
#define SAh 296
#define SOUT 132

__global__ __launch_bounds__(256, 2)
void edge_kernel(const float* __restrict__ frac,
                 const int* __restrict__ edges, const int* __restrict__ e2g,
                 const float* __restrict__ eb1, const float* __restrict__ eb2)
{
    extern __shared__ __half smh[];
    __half* s_a  = smh;
    __half* s_bb = smh + TM*SAh;
    float*  s_out = (float*)smh;
    __shared__ int s_i[TM], s_j[TM];

    int tid  = threadIdx.x, lane = tid & 31, wid = tid >> 5;
    int wm = wid >> 2, wn = wid & 3;
    int e0 = blockIdx.x * TM;

    if (tid < TM) {
        s_i[tid] = edges[e0 + tid];
        s_j[tid] = edges[EE + e0 + tid];
    }
    __syncthreads();

    #pragma unroll
    for (int it = 0; it < 16; it++) {
        int idx = tid + it*256;
        int r = idx >> 4, seg = idx & 15;
        int e = r >> 1, p = r & 1;
        int node = p ? s_j[e] : s_i[e];
        cpa16(s_a + e*SAh + p*DD + seg*8, g_h16 + (size_t)node*DD + seg*8);
    }
    #pragma unroll
    for (int it = 0; it < 4; it++) {
        int idx = tid + it*256;
        int row = idx >> 3, seg = idx & 7;
        cpa16(s_bb + row*SBK + seg*8, g_ew1T + row*288 + seg*8);
    }
    CP_COMMIT;

    if (tid < TM) {
        int e = tid;
        const float* lp = g_lip + e2g[e0 + e]*9;
        #pragma unroll
        for (int u = 0; u < 9; u++) s_a[e*SAh + 256 + u] = __float2half(lp[u]);
        int ii = s_i[e], jj = s_j[e];
        #pragma unroll
        for (int c = 0; c < 3; c++) {
            float dd = frac[jj*3 + c] - frac[ii*3 + c];
            dd -= floorf(dd);
            s_a[e*SAh + 265 + c] = __float2half(dd);
        }
        #pragma unroll
        for (int u = 268; u < 288; u++) s_a[e*SAh + u] = __half(0.f);
        atomicAdd(&g_cnt[ii], 1);
    }

    float acc[4][4][4];
    #pragma unroll
    for (int mf = 0; mf < 4; mf++)
        #pragma unroll
        for (int nf = 0; nf < 4; nf++)
            #pragma unroll
            for (int u = 0; u < 4; u++) acc[mf][nf][u] = 0.f;

    CP_WAIT0;
    __syncthreads();

    for (int ct = 0; ct < 4; ct++) {
        __half* dbuf = s_bb + ((ct+1)&1)*BKB;
        if (ct < 3) {
            #pragma unroll
            for (int it = 0; it < 4; it++) {
                int idx = tid + it*256;
                int row = idx >> 3, seg = idx & 7;
                cpa16(dbuf + row*SBK + seg*8, g_ew1T + row*288 + (ct+1)*64 + seg*8);
            }
        } else {
            #pragma unroll
            for (int it = 0; it < 2; it++) {
                int idx = tid + it*256;
                int row = idx >> 2, seg = idx & 3;
                cpa16(dbuf + row*SBK + seg*8, g_ew1T + row*288 + 256 + seg*8);
            }
        }
        CP_COMMIT;
        const __half* bB = s_bb + (ct & 1)*BKB;
        #pragma unroll
        for (int kk = 0; kk < 64; kk += 16) {
            int kg = ct*64 + kk;
            uint32_t afr[4][4];
            #pragma unroll
            for (int mf = 0; mf < 4; mf++) LDSMA(afr[mf], s_a, SAh, wm*64 + mf*16, kg);
            uint32_t bfr[4][2];
            LDSMB2(bfr[0], bB, SBK, wn*32, kk);
            LDSMB2(bfr[2], bB, SBK, wn*32 + 16, kk);
            #pragma unroll
            for (int mf = 0; mf < 4; mf++)
                #pragma unroll
                for (int nf = 0; nf < 4; nf++)
                    mma_f16(acc[mf][nf], afr[mf], bfr[nf]);
        }
        CP_WAIT0;
        __syncthreads();
    }

    {
        #pragma unroll
        for (int it = 0; it < 4; it++) {
            int idx = tid + it*256;
            int row = idx >> 3, seg = idx & 7;
            cpa16(s_bb + BKB + row*SBK + seg*8, g_ew2T + row*DD + seg*8);
        }
        CP_COMMIT;
        const __half* bB = s_bb;
        #pragma unroll
        for (int kk = 0; kk < 32; kk += 16) {
            int kg = 256 + kk;
            uint32_t afr[4][4];
            #pragma unroll
            for (int mf = 0; mf < 4; mf++) LDSMA(afr[mf], s_a, SAh, wm*64 + mf*16, kg);
            uint32_t bfr[4][2];
            LDSMB2(bfr[0], bB, SBK, wn*32, kk);
            LDSMB2(bfr[2], bB, SBK, wn*32 + 16, kk);
            #pragma unroll
            for (int mf = 0; mf < 4; mf++)
                #pragma unroll
                for (int nf = 0; nf < 4; nf++)
                    mma_f16(acc[mf][nf], afr[mf], bfr[nf]);
        }
        CP_WAIT0;
        __syncthreads();
    }

    #pragma unroll
    for (int mf = 0; mf < 4; mf++) {
        int r0 = wm*64 + mf*16 + (lane >> 2);
        #pragma unroll
        for (int nf = 0; nf < 4; nf++) {
            int n = wn*32 + nf*8 + (lane & 3)*2;
            float b0 = eb1[n], b1 = eb1[n + 1];
            *(__half2*)(s_a + r0*SAh + n) =
                __floats2half2_rn(silu_f(acc[mf][nf][0] + b0), silu_f(acc[mf][nf][1] + b1));
            *(__half2*)(s_a + (r0 + 8)*SAh + n) =
                __floats2half2_rn(silu_f(acc[mf][nf][2] + b0), silu_f(acc[mf][nf][3] + b1));
            #pragma unroll
            for (int u = 0; u < 4; u++) acc[mf][nf][u] = 0.f;
        }
    }
    __syncthreads();

    for (int c = 0; c < 2; c++) {
        if (c == 0) {
            #pragma unroll
            for (int it = 0; it < 4; it++) {
                int idx = tid + it*256;
                int row = idx >> 3, seg = idx & 7;
                cpa16(s_bb + row*SBK + seg*8, g_ew2T + row*DD + 64 + seg*8);
            }
            CP_COMMIT;
        }
        const __half* bB = s_bb + ((1 + c) & 1)*BKB;
        #pragma unroll
        for (int kk = 0; kk < 64; kk += 16) {
            int kg = c*64 + kk;
            uint32_t afr[4][4];
            #pragma unroll
            for (int mf = 0; mf < 4; mf++) LDSMA(afr[mf], s_a, SAh, wm*64 + mf*16, kg);
            uint32_t bfr[4][2];
            LDSMB2(bfr[0], bB, SBK, wn*32, kk);
            LDSMB2(bfr[2], bB, SBK, wn*32 + 16, kk);
            #pragma unroll
            for (int mf = 0; mf < 4; mf++)
                #pragma unroll
                for (int nf = 0; nf < 4; nf++)
                    mma_f16(acc[mf][nf], afr[mf], bfr[nf]);
        }
        if (c == 0) { CP_WAIT0; }
        __syncthreads();
    }

    #pragma unroll
    for (int mf = 0; mf < 4; mf++) {
        #pragma unroll
        for (int rr = 0; rr < 2; rr++) {
            int m = wm*64 + mf*16 + (lane >> 2) + rr*8;
            float* orow = s_out + m*SOUT;
            #pragma unroll
            for (int nf = 0; nf < 4; nf++) {
                int n = wn*32 + nf*8 + (lane & 3)*2;
                orow[n]     = silu_f(acc[mf][nf][rr*2 + 0] + eb2[n]);
                orow[n + 1] = silu_f(acc[mf][nf][rr*2 + 1] + eb2[n + 1]);
            }
        }
    }
    __syncthreads();

    for (int r = wid; r < TM; r += 8) {
        float* ap = g_agg + (size_t)s_i[r]*DD + lane*4;
        const float* src = s_out + r*SOUT + lane*4;
        float v0 = src[0], v1 = src[1], v2 = src[2], v3 = src[3];
        asm volatile("red.global.add.v4.f32 [%0], {%1, %2, %3, %4};"
                     :: "l"(ap), "f"(v0), "f"(v1), "f"(v2), "f"(v3) : "memory");
    }
}

// ---------------- kernel 5: node MLP (unchanged from R15) ----------------
#define TN 128
#define SAn 264

__global__ __launch_bounds__(256, 2)
void node_kernel(const float* __restrict__ nfeat,
                 const float* __restrict__ nb1, const float* __restrict__ nb2,
                 float* __restrict__ out)
{
    extern __shared__ __half smh[];
    __half* s_a  = smh;
    __half* s_bb = smh + TN*SAn;
    __shared__ float s_cnt[TN];

    int tid  = threadIdx.x, lane = tid & 31, wid = tid >> 5;
    int wm = wid >> 2, wn = wid & 3;
    int n0 = blockIdx.x * TN;

    if (tid < TN) {
        int n = min(n0 + tid, NN - 1);
        s_cnt[tid] = fmaxf((float)g_cnt[n], 1.f);
    }
    #pragma unroll
    for (int it = 0; it < 8; it++) {
        int idx = tid + it*256;
        int r = idx >> 4, seg = idx & 15;
        int n = min(n0 + r, NN - 1);
        cpa16(s_a + r*SAn + seg*8, g_h16 + (size_t)n*DD + seg*8);
    }
    #pragma unroll
    for (int it = 0; it < 4; it++) {
        int idx = tid + it*256;
        int row = idx >> 3, seg = idx & 7;
        cpa16(s_bb + row*SBK + seg*8, g_nw1T + row*256 + seg*8);
    }
    CP_COMMIT;
    __syncthreads();

    #pragma unroll
    for (int it = 0; it < 16; it++) {
        int idx = tid + it*256;
        int r = idx >> 5, c4 = (idx & 31) * 4;
        int n = min(n0 + r, NN - 1);
        float inv = __fdividef(1.f, s_cnt[r]);
        float4 v = *(const float4*)(g_agg + (size_t)n*DD + c4);
        __half* dst = s_a + r*SAn + DD + c4;
        *(__half2*)(dst)     = __floats2half2_rn(v.x * inv, v.y * inv);
        *(__half2*)(dst + 2) = __floats2half2_rn(v.z * inv, v.w * inv);
    }

    float acc[4][4][4];
    #pragma unroll
    for (int mf = 0; mf < 4; mf++)
        #pragma unroll
        for (int nf = 0; nf < 4; nf++)
            #pragma unroll
            for (int u = 0; u < 4; u++) acc[mf][nf][u] = 0.f;

    CP_WAIT0;
    __syncthreads();

    for (int ct = 0; ct < 4; ct++) {
        __half* dbuf = s_bb + ((ct+1)&1)*BKB;
        const __half* src; int rstr; int k0;
        if (ct < 3) { src = g_nw1T; rstr = 256; k0 = (ct+1)*64; }
        else        { src = g_nw2T; rstr = 128; k0 = 0; }
        #pragma unroll
        for (int it = 0; it < 4; it++) {
            int idx = tid + it*256;
            int row = idx >> 3, seg = idx & 7;
            cpa16(dbuf + row*SBK + seg*8, src + (size_t)row*rstr + k0 + seg*8);
        }
        CP_COMMIT;
        const __half* bB = s_bb + (ct & 1)*BKB;
        #pragma unroll
        for (int kk = 0; kk < 64; kk += 16) {
            int kg = ct*64 + kk;
            uint32_t afr[4][4];
            #pragma unroll
            for (int mf = 0; mf < 4; mf++) LDSMA(afr[mf], s_a, SAn, wm*64 + mf*16, kg);
            uint32_t bfr[4][2];
            LDSMB2(bfr[0], bB, SBK, wn*32, kk);
            LDSMB2(bfr[2], bB, SBK, wn*32 + 16, kk);
            #pragma unroll
            for (int mf = 0; mf < 4; mf++)
                #pragma unroll
                for (int nf = 0; nf < 4; nf++)
                    mma_f16(acc[mf][nf], afr[mf], bfr[nf]);
        }
        CP_WAIT0;
        __syncthreads();
    }

    #pragma unroll
    for (int mf = 0; mf < 4; mf++) {
        int r0 = wm*64 + mf*16 + (lane >> 2);
        #pragma unroll
        for (int nf = 0; nf < 4; nf++) {
            int n = wn*32 + nf*8 + (lane & 3)*2;
            float b0 = nb1[n], b1 = nb1[n + 1];
            *(__half2*)(s_a + r0*SAn + n) =
                __floats2half2_rn(silu_f(acc[mf][nf][0] + b0), silu_f(acc[mf][nf][1] + b1));
            *(__half2*)(s_a + (r0 + 8)*SAn + n) =
                __floats2half2_rn(silu_f(acc[mf][nf][2] + b0), silu_f(acc[mf][nf][3] + b1));
            #pragma unroll
            for (int u = 0; u < 4; u++) acc[mf][nf][u] = 0.f;
        }
    }
    __syncthreads();

    for (int c = 0; c < 2; c++) {
        if (c == 0) {
            #pragma unroll
            for (int it = 0; it < 4; it++) {
                int idx = tid + it*256;
                int row = idx >> 3, seg = idx & 7;
                cpa16(s_bb + BKB + row*SBK + seg*8, g_nw2T + row*DD + 64 + seg*8);
            }
            CP_COMMIT;
        }
        const __half* bB = s_bb + (c & 1)*BKB;
        #pragma unroll
        for (int kk = 0; kk < 64; kk += 16) {
            int kg = c*64 + kk;
            uint32_t afr[4][4];
            #pragma unroll
            for (int mf = 0; mf < 4; mf++) LDSMA(afr[mf], s_a, SAn, wm*64 + mf*16, kg);
            uint32_t bfr[4][2];
            LDSMB2(bfr[0], bB, SBK, wn*32, kk);
            LDSMB2(bfr[2], bB, SBK, wn*32 + 16, kk);
            #pragma unroll
            for (int mf = 0; mf < 4; mf++)
                #pragma unroll
                for (int nf = 0; nf < 4; nf++)
                    mma_f16(acc[mf][nf], afr[mf], bfr[nf]);
        }
        if (c == 0) { CP_WAIT0; }
        __syncthreads();
    }

    #pragma unroll
    for (int mf = 0; mf < 4; mf++) {
        #pragma unroll
        for (int rr = 0; rr < 2; rr++) {
            int m = wm*64 + mf*16 + (lane >> 2) + rr*8;
            int n = n0 + m;
            if (n < NN) {
                const float* nfr = nfeat + (size_t)n*DD;
                float* orow = out + (size_t)n*DD;
                #pragma unroll
                for (int nf = 0; nf < 4; nf++) {
                    int col = wn*32 + nf*8 + (lane & 3)*2;
                    orow[col]     = nfr[col]     + silu_f(acc[mf][nf][rr*2 + 0] + nb2[col]);
                    orow[col + 1] = nfr[col + 1] + silu_f(acc[mf][nf][rr*2 + 1] + nb2[col + 1]);
                }
            }
        }
    }
}

// ---------------- launch ----------------
extern "C" void kernel_launch(void* const* d_in, const int* in_sizes, int n_in,
                              void* d_out, int out_size)
{
    const float* node_features = (const float*)d_in[0];
    const float* cond = (const float*)d_in[1];
    const int*   n2g  = (const int*)d_in[2];
    const float* frac = (const float*)d_in[3];
    const float* lat  = (const float*)d_in[4];
    const int*   edges= (const int*)d_in[5];
    const int*   e2g  = (const int*)d_in[6];
    const float* wq = (const float*)d_in[7];
    const float* bq = (const float*)d_in[8];
    const float* wk = (const float*)d_in[9];
    const float* bk = (const float*)d_in[10];
    const float* wv = (const float*)d_in[11];
    const float* bv = (const float*)d_in[12];
    const float* wo = (const float*)d_in[13];
    const float* bo = (const float*)d_in[14];
    const float* sw1= (const float*)d_in[15];
    const float* sb1= (const float*)d_in[16];
    const float* sw2= (const float*)d_in[17];
    const float* sb2= (const float*)d_in[18];
    const float* ew1= (const float*)d_in[19];
    const float* eb1= (const float*)d_in[20];
    const float* ew2= (const float*)d_in[21];
    const float* eb2= (const float*)d_in[22];
    const float* nw1= (const float*)d_in[23];
    const float* nb1= (const float*)d_in[24];
    const float* nw2= (const float*)d_in[25];
    const float* nb2= (const float*)d_in[26];
    float* out = (float*)d_out;

    const int attn_smem = (3*AT*SQh + 128*SBh + 2*BHB + AT*40 + 8*SBW2 + 3*16*KVROW) * 2
                        + (128 + 8 + AT*8) * 4;                       // ~105.9 KB
    const int prep_smem = (128*SPh + 2*BKB) * 2;                      //  71,680 B
    const int edge_smem = (TM*SAh + 2*BKB) * 2;                       // 112,640 B
    const int node_smem = (TN*SAn + 2*BKB) * 2;                       // 104,448 B
    cudaFuncSetAttribute(attn_kernel, cudaFuncAttributeMaxDynamicSharedMemorySize, attn_smem);
    cudaFuncSetAttribute(prep_kernel, cudaFuncAttributeMaxDynamicSharedMemorySize, prep_smem);
    cudaFuncSetAttribute(edge_kernel, cudaFuncAttributeMaxDynamicSharedMemorySize, edge_smem);
    cudaFuncSetAttribute(node_kernel, cudaFuncAttributeMaxDynamicSharedMemorySize, node_smem);

    convw_kernel<<<676, 256>>>(ew1, ew2, nw1, nw2, wq, wo, sw1, sw2, wk, wv);
    lip_kernel<<<9, 256>>>(lat);
    prep_kernel<<<BB*TT/128, 256, prep_smem>>>(cond, bk, bv);
    zero_kernel<<<(NN*DD + 255) / 256, 256>>>();
    attn_kernel<<<(NN + AT - 1) / AT, 256, attn_smem>>>(node_features, frac, n2g,
                                                        bq, bo, sb1, sb2);
    edge_kernel<<<EE / TM, 256, edge_smem>>>(frac, edges, e2g, eb1, eb2);
    node_kernel<<<(NN + TN - 1) / TN, 256, node_smem>>>(node_features, nb1, nb2, out);
}

// round 17
// speedup vs baseline: 1.3400x; 1.0284x over previous
#include <cuda_runtime.h>
#include <cuda_fp16.h>
#include <math.h>
#include <stdint.h>

#define NN 50000
#define EE 800000
#define BB 256
#define DD 128
#define TT 8
#define KV_OFF (BB*TT*DD)

// ---------------- scratch (no allocations allowed) ----------------
__device__ __half g_h16[(size_t)NN*DD];     // post-attention node states (fp16)
__device__ __half g_KV16[2*BB*TT*DD];       // Kc then Vc (fp16)
__device__ float  g_lip[BB*9];              // lattice inner products
__device__ float  g_agg[(size_t)NN*DD];     // scatter sums (fp32 atomics)
__device__ int    g_cnt[NN];                // scatter counts
// pre-converted, pre-transposed fp16 weights [N][K]
__device__ __half g_ew1T[DD*288];           // K padded 272->288
__device__ __half g_ew2T[DD*DD];
__device__ __half g_nw1T[DD*256];
__device__ __half g_nw2T[DD*DD];
__device__ __half g_wqT[DD*DD];
__device__ __half g_woT[DD*DD];
__device__ __half g_sw1T[DD*32];            // K padded 24->32
__device__ __half g_sw2h[8*DD];             // sw2 transposed [8][128] fp16
__device__ __half g_wkT[DD*DD];
__device__ __half g_wvT[DD*DD];

__device__ __forceinline__ float silu_f(float x) {
    return __fdividef(x, 1.f + __expf(-x));
}

// fp16 mma, fp32 accumulate
__device__ __forceinline__ void mma_f16(float* c, const uint32_t* a, const uint32_t* b) {
    asm volatile(
        "mma.sync.aligned.m16n8k16.row.col.f32.f16.f16.f32 "
        "{%0,%1,%2,%3}, {%4,%5,%6,%7}, {%8,%9}, {%0,%1,%2,%3};\n"
        : "+f"(c[0]), "+f"(c[1]), "+f"(c[2]), "+f"(c[3])
        : "r"(a[0]), "r"(a[1]), "r"(a[2]), "r"(a[3]), "r"(b[0]), "r"(b[1]));
}

__device__ __forceinline__ void cpa16(void* dst, const void* src) {
    uint32_t d = (uint32_t)__cvta_generic_to_shared(dst);
    asm volatile("cp.async.cg.shared.global [%0], [%1], 16;" :: "r"(d), "l"(src));
}
#define CP_COMMIT asm volatile("cp.async.commit_group;" ::: "memory")
#define CP_WAIT0  asm volatile("cp.async.wait_group 0;" ::: "memory")

// ldmatrix x4
__device__ __forceinline__ void ldsm4(uint32_t* r, const __half* p) {
    uint32_t a = (uint32_t)__cvta_generic_to_shared(p);
    asm volatile("ldmatrix.sync.aligned.m8n8.x4.shared.b16 {%0,%1,%2,%3}, [%4];"
        : "=r"(r[0]), "=r"(r[1]), "=r"(r[2]), "=r"(r[3]) : "r"(a));
}
#define LDSMA(afr, base, SAx, rowbase, kg)                                        \
    ldsm4(afr, (base) + ((rowbase) + (lane & 15))*(SAx) + (kg) + ((lane >> 4) << 3))
#define LDSMB2(b4, bB, SBx, ncol, kk)                                             \
    ldsm4(b4, (bB) + ((ncol) + (lane & 7) + ((lane >> 4) << 3))*(SBx) + (kk) + (((lane >> 3) & 1) << 3))

// attn B geometry: 128 n-rows x (32 k + 8 pad)
#define SBh 40
#define BHB (128*SBh)
// edge/node/prep B geometry: 128 n-rows x (64 k + 8 pad)
#define SBK 72
#define BKB (128*SBK)

// ---------------- kernel 1a: K/V projection via fp16 MMA ----------------
#define SPh 136

__global__ __launch_bounds__(256, 2)
void prep_kernel(const float* __restrict__ cond,
                 const float* __restrict__ bk, const float* __restrict__ bv)
{
    extern __shared__ __half smh[];
    __half* s_a  = smh;               // 128*SPh
    __half* s_bb = smh + 128*SPh;     // 2*BKB

    int tid = threadIdx.x, lane = tid & 31, wid = tid >> 5;
    int wm = wid >> 2, wn = wid & 3;
    int r0g = blockIdx.x * 128;

    #pragma unroll
    for (int it = 0; it < 16; it++) {
        int idx = tid + it*256;
        int r = idx >> 5, c4 = (idx & 31) * 4;
        float4 v = *(const float4*)(cond + (size_t)(r0g + r)*DD + c4);
        __half* dst = s_a + r*SPh + c4;
        *(__half2*)(dst)     = __floats2half2_rn(v.x, v.y);
        *(__half2*)(dst + 2) = __floats2half2_rn(v.z, v.w);
    }
    #pragma unroll
    for (int it = 0; it < 4; it++) {
        int idx = tid + it*256;
        int row = idx >> 3, seg = idx & 7;
        cpa16(s_bb + row*SBK + seg*8, g_wkT + row*DD + seg*8);
    }
    CP_COMMIT;
    __syncthreads();

    float acc[4][4][4];
    #pragma unroll
    for (int mf = 0; mf < 4; mf++)
        #pragma unroll
        for (int nf = 0; nf < 4; nf++)
            #pragma unroll
            for (int u = 0; u < 4; u++) acc[mf][nf][u] = 0.f;

    CP_WAIT0;
    __syncthreads();

    for (int ct = 0; ct < 4; ct++) {
        if (ct < 3) {
            const __half* src = (ct == 0) ? (g_wkT + 64)
                              : (ct == 1) ? g_wvT : (g_wvT + 64);
            __half* dbuf = s_bb + ((ct+1)&1)*BKB;
            #pragma unroll
            for (int it = 0; it < 4; it++) {
                int idx = tid + it*256;
                int row = idx >> 3, seg = idx & 7;
                cpa16(dbuf + row*SBK + seg*8, src + row*DD + seg*8);
            }
            CP_COMMIT;
        }
        const __half* bB = s_bb + (ct & 1)*BKB;
        int kg = (ct & 1) * 64;
        #pragma unroll
        for (int kk = 0; kk < 64; kk += 16) {
            uint32_t afr[4][4];
            #pragma unroll
            for (int mf = 0; mf < 4; mf++) LDSMA(afr[mf], s_a, SPh, wm*64 + mf*16, kg + kk);
            uint32_t bfr[4][2];
            LDSMB2(bfr[0], bB, SBK, wn*32, kk);
            LDSMB2(bfr[2], bB, SBK, wn*32 + 16, kk);
            #pragma unroll
            for (int mf = 0; mf < 4; mf++)
                #pragma unroll
                for (int nf = 0; nf < 4; nf++)
                    mma_f16(acc[mf][nf], afr[mf], bfr[nf]);
        }
        if (ct == 1) {
            #pragma unroll
            for (int mf = 0; mf < 4; mf++) {
                #pragma unroll
                for (int rr = 0; rr < 2; rr++) {
                    int m = wm*64 + mf*16 + (lane >> 2) + rr*8;
                    __half* orow = g_KV16 + (size_t)(r0g + m)*DD;
                    #pragma unroll
                    for (int nf = 0; nf < 4; nf++) {
                        int col = wn*32 + nf*8 + (lane & 3)*2;
                        *(__half2*)(orow + col) = __floats2half2_rn(
                            acc[mf][nf][rr*2 + 0] + bk[col],
                            acc[mf][nf][rr*2 + 1] + bk[col + 1]);
                        acc[mf][nf][rr*2 + 0] = 0.f;
                        acc[mf][nf][rr*2 + 1] = 0.f;
                    }
                }
            }
        }
        if (ct < 3) { CP_WAIT0; }
        __syncthreads();
    }
    #pragma unroll
    for (int mf = 0; mf < 4; mf++) {
        #pragma unroll
        for (int rr = 0; rr < 2; rr++) {
            int m = wm*64 + mf*16 + (lane >> 2) + rr*8;
            __half* orow = g_KV16 + KV_OFF + (size_t)(r0g + m)*DD;
            #pragma unroll
            for (int nf = 0; nf < 4; nf++) {
                int col = wn*32 + nf*8 + (lane & 3)*2;
                *(__half2*)(orow + col) = __floats2half2_rn(
                    acc[mf][nf][rr*2 + 0] + bv[col],
                    acc[mf][nf][rr*2 + 1] + bv[col + 1]);
            }
        }
    }
}

// ---------------- kernel 1b: convert+transpose weights + lattice gram ----------------
__global__ void convw_kernel(const float* __restrict__ ew1, const float* __restrict__ ew2,
                             const float* __restrict__ nw1, const float* __restrict__ nw2,
                             const float* __restrict__ wq,  const float* __restrict__ wo,
                             const float* __restrict__ sw1, const float* __restrict__ sw2,
                             const float* __restrict__ wk,  const float* __restrict__ wv,
                             const float* __restrict__ lat)
{
    int idx = blockIdx.x * 256 + threadIdx.x;
    if (idx < 36864) {
        int n = idx / 288, k = idx % 288;
        g_ew1T[idx] = (k < 268) ? __float2half(ew1[k*DD + n]) : __half(0.f);
    } else if (idx < 53248) {
        int j = idx - 36864; int n = j / DD, k = j % DD;
        g_ew2T[j] = __float2half(ew2[k*DD + n]);
    } else if (idx < 86016) {
        int j = idx - 53248; int n = j / 256, k = j % 256;
        g_nw1T[j] = __float2half(nw1[k*DD + n]);
    } else if (idx < 102400) {
        int j = idx - 86016; int n = j / DD, k = j % DD;
        g_nw2T[j] = __float2half(nw2[k*DD + n]);
    } else if (idx < 118784) {
        int j = idx - 102400; int n = j / DD, k = j % DD;
        g_wqT[j] = __float2half(wq[k*DD + n]);
    } else if (idx < 135168) {
        int j = idx - 118784; int n = j / DD, k = j % DD;
        g_woT[j] = __float2half(wo[k*DD + n]);
    } else if (idx < 139264) {
        int j = idx - 135168; int n = j / 32, k = j % 32;
        g_sw1T[j] = (k < 24) ? __float2half(sw1[k*DD + n]) : __half(0.f);
    } else if (idx < 140288) {
        int j = idx - 139264; int t = j >> 7, k = j & 127;
        g_sw2h[j] = __float2half(sw2[k*8 + t]);
    } else if (idx < 156672) {
        int j = idx - 140288; int n = j / DD, k = j % DD;
        g_wkT[j] = __float2half(wk[k*DD + n]);
    } else if (idx < 173056) {
        int j = idx - 156672; int n = j / DD, k = j % DD;
        g_wvT[j] = __float2half(wv[k*DD + n]);
    } else if (idx < 175360) {
        int j = idx - 173056;  // lattice gram: BB*9
        int b = j / 9, t = j - (j/9)*9;
        int i = t / 3, k = t - (t/3)*3;
        const float* L = lat + b*9;
        g_lip[j] = L[i*3+0]*L[k*3+0] + L[i*3+1]*L[k*3+1] + L[i*3+2]*L[k*3+2];
    }
}

// ---------------- kernel 3: cross-attention + fold-in agg/cnt zeroing ----------------
#define AT 64
#define SQh 136
#define SBW2 136
#define KVROW 136

__global__ __launch_bounds__(256, 2)
void attn_kernel(const float* __restrict__ nfeat, const float* __restrict__ frac,
                 const int* __restrict__ n2g,
                 const float* __restrict__ bq, const float* __restrict__ bo,
                 const float* __restrict__ sb1, const float* __restrict__ sb2)
{
    extern __shared__ char smraw[];
    __half* s_h    = (__half*)smraw;
    __half* s_hid  = s_h + AT*SQh;
    __half* s_q    = s_hid + AT*SQh;
    __half* s_bsw  = s_q + AT*SQh;
    __half* s_bb   = s_bsw + 128*SBh;
    __half* s_enc  = s_bb + 2*BHB;
    __half* s_sw2h = s_enc + AT*40;
    float*  s_sb1 = (float*)(s_sw2h + 8*SBW2);
    float*  s_sb2 = s_sb1 + 128;
    float*  s_att = s_sb2 + 8;
    __half* s_kv  = (__half*)(s_att + AT*8);
    __shared__ int s_g[AT];

    int tid = threadIdx.x, lane = tid & 31, wid = tid >> 5;
    int wm = wid >> 2, wn = wid & 3;
    int n0 = blockIdx.x * AT;
    int bn = tid >> 1, bseg = (tid & 1) * 16;

    if (tid < AT) s_g[tid] = n2g[min(n0 + tid, NN - 1)];

    cpa16(s_bsw + bn*SBh + bseg,     g_sw1T + bn*32 + bseg);
    cpa16(s_bsw + bn*SBh + bseg + 8, g_sw1T + bn*32 + bseg + 8);
    if (tid < 128) {
        int row = tid >> 4, seg = (tid & 15) * 8;
        cpa16(s_sw2h + row*SBW2 + seg, g_sw2h + row*DD + seg);
    }
    if (tid < 32) cpa16(s_sb1 + tid*4, sb1 + tid*4);
    if (tid < 2)  cpa16(s_sb2 + tid*4, sb2 + tid*4);
    cpa16(s_bb + bn*SBh + bseg,     g_wqT + bn*DD + bseg);
    cpa16(s_bb + bn*SBh + bseg + 8, g_wqT + bn*DD + bseg + 8);
    CP_COMMIT;

    // ---- folded zeroing: this block owns node rows n0..n0+63 of g_agg / g_cnt ----
    {
        const float4 z4 = make_float4(0.f, 0.f, 0.f, 0.f);
        #pragma unroll
        for (int it = 0; it < 8; it++) {
            int idx = tid + it*256;                 // 2048 float4 = 64 rows x 32
            int r = idx >> 5, c4 = (idx & 31) * 4;
            int n = n0 + r;
            if (n < NN) *(float4*)(g_agg + (size_t)n*DD + c4) = z4;
        }
        if (tid < AT && (n0 + tid) < NN) g_cnt[n0 + tid] = 0;
    }

    #pragma unroll
    for (int it = 0; it < 8; it++) {
        int idx = tid + it*256;
        int r = idx >> 5, c4 = (idx & 31) * 4;
        int n = min(n0 + r, NN - 1);
        float4 v = *(const float4*)(nfeat + (size_t)n*DD + c4);
        __half* dst = s_h + r*SQh + c4;
        *(__half2*)(dst)     = __floats2half2_rn(v.x, v.y);
        *(__half2*)(dst + 2) = __floats2half2_rn(v.z, v.w);
    }
    {
        int n = tid >> 2, sub = tid & 3;
        int nn = min(n0 + n, NN - 1);
        float f0 = frac[nn*3+0], f1 = frac[nn*3+1], f2 = frac[nn*3+2];
        #pragma unroll
        for (int k = sub; k < 24; k += 4) {
            int ii = k % 12, c = ii >> 2, j = ii & 3;
            float fv = (c == 0) ? f0 : ((c == 1) ? f1 : f2);
            float ph = fv * ((float)(1 << j) * 3.14159265358979323846f);
            s_enc[n*40 + k] = __float2half((k < 12) ? sinf(ph) : cosf(ph));
        }
        s_enc[n*40 + 24 + sub] = __half(0.f);
        s_enc[n*40 + 28 + sub] = __half(0.f);
    }
    CP_WAIT0;
    __syncthreads();

    int gmin = s_g[0];
    int span = s_g[AT-1] - gmin + 1;
    bool use_s = (span <= 3);
    if (use_s) {
        for (int i = tid; i < span*256; i += 256) {
            int g = i >> 8, rem = i & 255;
            int r = rem >> 4, seg = rem & 15;
            const __half* src = (r < 8)
                ? g_KV16 + (size_t)(gmin + g)*TT*DD + r*DD + seg*8
                : g_KV16 + KV_OFF + (size_t)(gmin + g)*TT*DD + (r - 8)*DD + seg*8;
            cpa16(s_kv + (g*16 + r)*KVROW + seg*8, src);
        }
        CP_COMMIT;
    }

    float acc[2][4][4];
    #pragma unroll
    for (int mf = 0; mf < 2; mf++)
        #pragma unroll
        for (int nf = 0; nf < 4; nf++)
            #pragma unroll
            for (int u = 0; u < 4; u++) acc[mf][nf][u] = 0.f;

    #pragma unroll
    for (int kk = 0; kk < 32; kk += 16) {
        uint32_t afr[2][4];
        #pragma unroll
        for (int mf = 0; mf < 2; mf++) LDSMA(afr[mf], s_enc, 40, wm*32 + mf*16, kk);
        uint32_t bfr[4][2];
        LDSMB2(bfr[0], s_bsw, SBh, wn*32, kk);
        LDSMB2(bfr[2], s_bsw, SBh, wn*32 + 16, kk);
        #pragma unroll
        for (int mf = 0; mf < 2; mf++)
            #pragma unroll
            for (int nf = 0; nf < 4; nf++)
                mma_f16(acc[mf][nf], afr[mf], bfr[nf]);
    }
    #pragma unroll
    for (int mf = 0; mf < 2; mf++) {
        int r0 = wm*32 + mf*16 + (lane >> 2);
        #pragma unroll
        for (int nf = 0; nf < 4; nf++) {
            int n = wn*32 + nf*8 + (lane & 3)*2;
            float b0 = s_sb1[n], b1 = s_sb1[n + 1];
            *(__half2*)(s_hid + r0*SQh + n) =
                __floats2half2_rn(silu_f(acc[mf][nf][0] + b0), silu_f(acc[mf][nf][1] + b1));
            *(__half2*)(s_hid + (r0 + 8)*SQh + n) =
                __floats2half2_rn(silu_f(acc[mf][nf][2] + b0), silu_f(acc[mf][nf][3] + b1));
            #pragma unroll
            for (int u = 0; u < 4; u++) acc[mf][nf][u] = 0.f;
        }
    }

    for (int ct = 0; ct < 4; ct++) {
        __half* dbuf = s_bb + ((ct+1)&1)*BHB;
        const __half* src = (ct < 3) ? (g_wqT + (ct+1)*32) : g_woT;
        cpa16(dbuf + bn*SBh + bseg,     src + bn*DD + bseg);
        cpa16(dbuf + bn*SBh + bseg + 8, src + bn*DD + bseg + 8);
        CP_COMMIT;
        const __half* bB = s_bb + (ct & 1)*BHB;
        #pragma unroll
        for (int kk = 0; kk < 32; kk += 16) {
            int kg = ct*32 + kk;
            uint32_t afr[2][4];
            #pragma unroll
            for (int mf = 0; mf < 2; mf++) LDSMA(afr[mf], s_h, SQh, wm*32 + mf*16, kg);
            uint32_t bfr[4][2];
            LDSMB2(bfr[0], bB, SBh, wn*32, kk);
            LDSMB2(bfr[2], bB, SBh, wn*32 + 16, kk);
            #pragma unroll
            for (int mf = 0; mf < 2; mf++)
                #pragma unroll
                for (int nf = 0; nf < 4; nf++)
                    mma_f16(acc[mf][nf], afr[mf], bfr[nf]);
        }
        CP_WAIT0;
        __syncthreads();
    }
    #pragma unroll
    for (int mf = 0; mf < 2; mf++) {
        int r0 = wm*32 + mf*16 + (lane >> 2);
        #pragma unroll
        for (int nf = 0; nf < 4; nf++) {
            int n = wn*32 + nf*8 + (lane & 3)*2;
            float b0 = bq[n], b1 = bq[n + 1];
            *(__half2*)(s_q + r0*SQh + n) =
                __floats2half2_rn(acc[mf][nf][0] + b0, acc[mf][nf][1] + b1);
            *(__half2*)(s_q + (r0 + 8)*SQh + n) =
                __floats2half2_rn(acc[mf][nf][2] + b0, acc[mf][nf][3] + b1);
        }
    }
    __syncthreads();

    if (wid < 4) {
        float bacc[4] = {0.f, 0.f, 0.f, 0.f};
        #pragma unroll
        for (int kk = 0; kk < 128; kk += 16) {
            uint32_t afr[4];
            LDSMA(afr, s_hid, SQh, wid*16, kk);
            const __half* bp = s_sw2h + (lane >> 2)*SBW2 + kk + (lane & 3)*2;
            uint32_t bfr[2];
            bfr[0] = *(const uint32_t*)(bp);
            bfr[1] = *(const uint32_t*)(bp + 8);
            mma_f16(bacc, afr, bfr);
        }
        int r0 = wid*16 + (lane >> 2);
        int t = (lane & 3)*2;
        s_att[r0*8 + t]         = bacc[0];
        s_att[r0*8 + t + 1]     = bacc[1];
        s_att[(r0 + 8)*8 + t]     = bacc[2];
        s_att[(r0 + 8)*8 + t + 1] = bacc[3];
    }
    __syncthreads();

    {
        int n = tid >> 2, sub = tid & 3;
        int gg = s_g[n];
        int t0 = sub*2, t1 = t0 + 1;
        const __half* Kb = use_s ? (s_kv + (gg - gmin)*16*KVROW)
                                 : (g_KV16 + (size_t)gg*TT*DD);
        int kstr = use_s ? KVROW : DD;
        const __half2* K0 = (const __half2*)(Kb + t0*kstr);
        const __half2* K1 = (const __half2*)(Kb + t1*kstr);
        const __half2* qq = (const __half2*)(s_q + n*SQh);
        float sc0 = 0.f, sc1 = 0.f;
        #pragma unroll 8
        for (int k2 = 0; k2 < 64; k2++) {
            float2 q = __half22float2(qq[k2]);
            float2 a = __half22float2(K0[k2]);
            float2 b = __half22float2(K1[k2]);
            sc0 = fmaf(q.x, a.x, sc0); sc0 = fmaf(q.y, a.y, sc0);
            sc1 = fmaf(q.x, b.x, sc1); sc1 = fmaf(q.y, b.y, sc1);
        }
        float v0 = sc0 * 0.08838834764831845f + s_att[n*8 + t0] + s_sb2[t0];
        float v1 = sc1 * 0.08838834764831845f + s_att[n*8 + t1] + s_sb2[t1];
        float m = fmaxf(v0, v1);
        m = fmaxf(m, __shfl_xor_sync(0xffffffffu, m, 1, 4));
        m = fmaxf(m, __shfl_xor_sync(0xffffffffu, m, 2, 4));
        float e0 = __expf(v0 - m), e1 = __expf(v1 - m);
        float s = e0 + e1;
        s += __shfl_xor_sync(0xffffffffu, s, 1, 4);
        s += __shfl_xor_sync(0xffffffffu, s, 2, 4);
        float inv = __fdividef(1.f, s);
        s_att[n*8 + t0] = e0 * inv;
        s_att[n*8 + t1] = e1 * inv;
    }
    __syncthreads();

    #pragma unroll
    for (int it = 0; it < 16; it++) {
        int idx = tid + it*256;
        int n = idx >> 6, c = (idx & 63) * 2;
        int gg = s_g[n];
        const __half* Vr;
        int vstr;
        if (use_s) { Vr = s_kv + (gg - gmin)*16*KVROW + 8*KVROW + c; vstr = KVROW; }
        else       { Vr = g_KV16 + KV_OFF + (size_t)gg*TT*DD + c;    vstr = DD; }
        const float* at = s_att + n*8;
        float a0 = 0.f, a1 = 0.f;
        #pragma unroll
        for (int t = 0; t < 8; t++) {
            float2 v = __half22float2(*(const __half2*)(Vr + t*vstr));
            a0 = fmaf(at[t], v.x, a0);
            a1 = fmaf(at[t], v.y, a1);
        }
        *(__half2*)(s_q + n*SQh + c) = __floats2half2_rn(a0, a1);
    }
    __syncthreads();

    float acc2[2][4][4];
    #pragma unroll
    for (int mf = 0; mf < 2; mf++)
        #pragma unroll
        for (int nf = 0; nf < 4; nf++)
            #pragma unroll
            for (int u = 0; u < 4; u++) acc2[mf][nf][u] = 0.f;

    for (int c = 0; c < 4; c++) {
        if (c < 3) {
            __half* dbuf = s_bb + ((c+1)&1)*BHB;
            const __half* src = g_woT + (c+1)*32;
            cpa16(dbuf + bn*SBh + bseg,     src + bn*DD + bseg);
            cpa16(dbuf + bn*SBh + bseg + 8, src + bn*DD + bseg + 8);
            CP_COMMIT;
        }
        const __half* bB = s_bb + (c & 1)*BHB;
        #pragma unroll
        for (int kk = 0; kk < 32; kk += 16) {
            int kg = c*32 + kk;
            uint32_t afr[2][4];
            #pragma unroll
            for (int mf = 0; mf < 2; mf++) LDSMA(afr[mf], s_q, SQh, wm*32 + mf*16, kg);
            uint32_t bfr[4][2];
            LDSMB2(bfr[0], bB, SBh, wn*32, kk);
            LDSMB2(bfr[2], bB, SBh, wn*32 + 16, kk);
            #pragma unroll
            for (int mf = 0; mf < 2; mf++)
                #pragma unroll
                for (int nf = 0; nf < 4; nf++)
                    mma_f16(acc2[mf][nf], afr[mf], bfr[nf]);
        }
        if (c < 3) { CP_WAIT0; }
        __syncthreads();
    }

    #pragma unroll
    for (int mf = 0; mf < 2; mf++) {
        #pragma unroll
        for (int rr = 0; rr < 2; rr++) {
            int m = wm*32 + mf*16 + (lane >> 2) + rr*8;
            int n = n0 + m;
            if (n < NN) {
                __half* orow = g_h16 + (size_t)n*DD;
                const __half* hrow = s_h + m*SQh;
                #pragma unroll
                for (int nf = 0; nf < 4; nf++) {
                    int col = wn*32 + nf*8 + (lane & 3)*2;
                    float v0 = __half2float(hrow[col])     + acc2[mf][nf][rr*2 + 0] + bo[col];
                    float v1 = __half2float(hrow[col + 1]) + acc2[mf][nf][rr*2 + 1] + bo[col + 1];
                    *(__half2*)(orow + col) = __floats2half2_rn(v0, v1);
                }
            }
        }
    }
}

// ---------------- kernel 4: edge MLP (unchanged from R16) ----------------
#define TM 128
#define SAh 296
#define SOUT 132

__global__ __launch_bounds__(256, 2)
void edge_kernel(const float* __restrict__ frac,
                 const int* __restrict__ edges, const int* __restrict__ e2g,
                 const float* __restrict__ eb1, const float* __restrict__ eb2)
{
    extern __shared__ __half smh[];
    __half* s_a  = smh;
    __half* s_bb = smh + TM*SAh;
    float*  s_out = (float*)smh;
    __shared__ int s_i[TM], s_j[TM];

    int tid  = threadIdx.x, lane = tid & 31, wid = tid >> 5;
    int wm = wid >> 2, wn = wid & 3;
    int e0 = blockIdx.x * TM;

    if (tid < TM) {
        s_i[tid] = edges[e0 + tid];
        s_j[tid] = edges[EE + e0 + tid];
    }
    __syncthreads();

    #pragma unroll
    for (int it = 0; it < 16; it++) {
        int idx = tid + it*256;
        int r = idx >> 4, seg = idx & 15;
        int e = r >> 1, p = r & 1;
        int node = p ? s_j[e] : s_i[e];
        cpa16(s_a + e*SAh + p*DD + seg*8, g_h16 + (size_t)node*DD + seg*8);
    }
    #pragma unroll
    for (int it = 0; it < 4; it++) {
        int idx = tid + it*256;
        int row = idx >> 3, seg = idx & 7;
        cpa16(s_bb + row*SBK + seg*8, g_ew1T + row*288 + seg*8);
    }
    CP_COMMIT;

    if (tid < TM) {
        int e = tid;
        const float* lp = g_lip + e2g[e0 + e]*9;
        #pragma unroll
        for (int u = 0; u < 9; u++) s_a[e*SAh + 256 + u] = __float2half(lp[u]);
        int ii = s_i[e], jj = s_j[e];
        #pragma unroll
        for (int c = 0; c < 3; c++) {
            float dd = frac[jj*3 + c] - frac[ii*3 + c];
            dd -= floorf(dd);
            s_a[e*SAh + 265 + c] = __float2half(dd);
        }
        #pragma unroll
        for (int u = 268; u < 288; u++) s_a[e*SAh + u] = __half(0.f);
        atomicAdd(&g_cnt[ii], 1);
    }

    float acc[4][4][4];
    #pragma unroll
    for (int mf = 0; mf < 4; mf++)
        #pragma unroll
        for (int nf = 0; nf < 4; nf++)
            #pragma unroll
            for (int u = 0; u < 4; u++) acc[mf][nf][u] = 0.f;

    CP_WAIT0;
    __syncthreads();

    for (int ct = 0; ct < 4; ct++) {
        __half* dbuf = s_bb + ((ct+1)&1)*BKB;
        if (ct < 3) {
            #pragma unroll
            for (int it = 0; it < 4; it++) {
                int idx = tid + it*256;
                int row = idx >> 3, seg = idx & 7;
                cpa16(dbuf + row*SBK + seg*8, g_ew1T + row*288 + (ct+1)*64 + seg*8);
            }
        } else {
            #pragma unroll
            for (int it = 0; it < 2; it++) {
                int idx = tid + it*256;
                int row = idx >> 2, seg = idx & 3;
                cpa16(dbuf + row*SBK + seg*8, g_ew1T + row*288 + 256 + seg*8);
            }
        }
        CP_COMMIT;
        const __half* bB = s_bb + (ct & 1)*BKB;
        #pragma unroll
        for (int kk = 0; kk < 64; kk += 16) {
            int kg = ct*64 + kk;
            uint32_t afr[4][4];
            #pragma unroll
            for (int mf = 0; mf < 4; mf++) LDSMA(afr[mf], s_a, SAh, wm*64 + mf*16, kg);
            uint32_t bfr[4][2];
            LDSMB2(bfr[0], bB, SBK, wn*32, kk);
            LDSMB2(bfr[2], bB, SBK, wn*32 + 16, kk);
            #pragma unroll
            for (int mf = 0; mf < 4; mf++)
                #pragma unroll
                for (int nf = 0; nf < 4; nf++)
                    mma_f16(acc[mf][nf], afr[mf], bfr[nf]);
        }
        CP_WAIT0;
        __syncthreads();
    }

    {
        #pragma unroll
        for (int it = 0; it < 4; it++) {
            int idx = tid + it*256;
            int row = idx >> 3, seg = idx & 7;
            cpa16(s_bb + BKB + row*SBK + seg*8, g_ew2T + row*DD + seg*8);
        }
        CP_COMMIT;
        const __half* bB = s_bb;
        #pragma unroll
        for (int kk = 0; kk < 32; kk += 16) {
            int kg = 256 + kk;
            uint32_t afr[4][4];
            #pragma unroll
            for (int mf = 0; mf < 4; mf++) LDSMA(afr[mf], s_a, SAh, wm*64 + mf*16, kg);
            uint32_t bfr[4][2];
            LDSMB2(bfr[0], bB, SBK, wn*32, kk);
            LDSMB2(bfr[2], bB, SBK, wn*32 + 16, kk);
            #pragma unroll
            for (int mf = 0; mf < 4; mf++)
                #pragma unroll
                for (int nf = 0; nf < 4; nf++)
                    mma_f16(acc[mf][nf], afr[mf], bfr[nf]);
        }
        CP_WAIT0;
        __syncthreads();
    }

    #pragma unroll
    for (int mf = 0; mf < 4; mf++) {
        int r0 = wm*64 + mf*16 + (lane >> 2);
        #pragma unroll
        for (int nf = 0; nf < 4; nf++) {
            int n = wn*32 + nf*8 + (lane & 3)*2;
            float b0 = eb1[n], b1 = eb1[n + 1];
            *(__half2*)(s_a + r0*SAh + n) =
                __floats2half2_rn(silu_f(acc[mf][nf][0] + b0), silu_f(acc[mf][nf][1] + b1));
            *(__half2*)(s_a + (r0 + 8)*SAh + n) =
                __floats2half2_rn(silu_f(acc[mf][nf][2] + b0), silu_f(acc[mf][nf][3] + b1));
            #pragma unroll
            for (int u = 0; u < 4; u++) acc[mf][nf][u] = 0.f;
        }
    }
    __syncthreads();

    for (int c = 0; c < 2; c++) {
        if (c == 0) {
            #pragma unroll
            for (int it = 0; it < 4; it++) {
                int idx = tid + it*256;
                int row = idx >> 3, seg = idx & 7;
                cpa16(s_bb + row*SBK + seg*8, g_ew2T + row*DD + 64 + seg*8);
            }
            CP_COMMIT;
        }
        const __half* bB = s_bb + ((1 + c) & 1)*BKB;
        #pragma unroll
        for (int kk = 0; kk < 64; kk += 16) {
            int kg = c*64 + kk;
            uint32_t afr[4][4];
            #pragma unroll
            for (int mf = 0; mf < 4; mf++) LDSMA(afr[mf], s_a, SAh, wm*64 + mf*16, kg);
            uint32_t bfr[4][2];
            LDSMB2(bfr[0], bB, SBK, wn*32, kk);
            LDSMB2(bfr[2], bB, SBK, wn*32 + 16, kk);
            #pragma unroll
            for (int mf = 0; mf < 4; mf++)
                #pragma unroll
                for (int nf = 0; nf < 4; nf++)
                    mma_f16(acc[mf][nf], afr[mf], bfr[nf]);
        }
        if (c == 0) { CP_WAIT0; }
        __syncthreads();
    }

    #pragma unroll
    for (int mf = 0; mf < 4; mf++) {
        #pragma unroll
        for (int rr = 0; rr < 2; rr++) {
            int m = wm*64 + mf*16 + (lane >> 2) + rr*8;
            float* orow = s_out + m*SOUT;
            #pragma unroll
            for (int nf = 0; nf < 4; nf++) {
                int n = wn*32 + nf*8 + (lane & 3)*2;
                orow[n]     = silu_f(acc[mf][nf][rr*2 + 0] + eb2[n]);
                orow[n + 1] = silu_f(acc[mf][nf][rr*2 + 1] + eb2[n + 1]);
            }
        }
    }
    __syncthreads();

    for (int r = wid; r < TM; r += 8) {
        float* ap = g_agg + (size_t)s_i[r]*DD + lane*4;
        const float* src = s_out + r*SOUT + lane*4;
        float v0 = src[0], v1 = src[1], v2 = src[2], v3 = src[3];
        asm volatile("red.global.add.v4.f32 [%0], {%1, %2, %3, %4};"
                     :: "l"(ap), "f"(v0), "f"(v1), "f"(v2), "f"(v3) : "memory");
    }
}

// ---------------- kernel 5: node MLP (unchanged from R16) ----------------
#define TN 128
#define SAn 264

__global__ __launch_bounds__(256, 2)
void node_kernel(const float* __restrict__ nfeat,
                 const float* __restrict__ nb1, const float* __restrict__ nb2,
                 float* __restrict__ out)
{
    extern __shared__ __half smh[];
    __half* s_a  = smh;
    __half* s_bb = smh + TN*SAn;
    __shared__ float s_cnt[TN];

    int tid  = threadIdx.x, lane = tid & 31, wid = tid >> 5;
    int wm = wid >> 2, wn = wid & 3;
    int n0 = blockIdx.x * TN;

    if (tid < TN) {
        int n = min(n0 + tid, NN - 1);
        s_cnt[tid] = fmaxf((float)g_cnt[n], 1.f);
    }
    #pragma unroll
    for (int it = 0; it < 8; it++) {
        int idx = tid + it*256;
        int r = idx >> 4, seg = idx & 15;
        int n = min(n0 + r, NN - 1);
        cpa16(s_a + r*SAn + seg*8, g_h16 + (size_t)n*DD + seg*8);
    }
    #pragma unroll
    for (int it = 0; it < 4; it++) {
        int idx = tid + it*256;
        int row = idx >> 3, seg = idx & 7;
        cpa16(s_bb + row*SBK + seg*8, g_nw1T + row*256 + seg*8);
    }
    CP_COMMIT;
    __syncthreads();

    #pragma unroll
    for (int it = 0; it < 16; it++) {
        int idx = tid + it*256;
        int r = idx >> 5, c4 = (idx & 31) * 4;
        int n = min(n0 + r, NN - 1);
        float inv = __fdividef(1.f, s_cnt[r]);
        float4 v = *(const float4*)(g_agg + (size_t)n*DD + c4);
        __half* dst = s_a + r*SAn + DD + c4;
        *(__half2*)(dst)     = __floats2half2_rn(v.x * inv, v.y * inv);
        *(__half2*)(dst + 2) = __floats2half2_rn(v.z * inv, v.w * inv);
    }

    float acc[4][4][4];
    #pragma unroll
    for (int mf = 0; mf < 4; mf++)
        #pragma unroll
        for (int nf = 0; nf < 4; nf++)
            #pragma unroll
            for (int u = 0; u < 4; u++) acc[mf][nf][u] = 0.f;

    CP_WAIT0;
    __syncthreads();

    for (int ct = 0; ct < 4; ct++) {
        __half* dbuf = s_bb + ((ct+1)&1)*BKB;
        const __half* src; int rstr; int k0;
        if (ct < 3) { src = g_nw1T; rstr = 256; k0 = (ct+1)*64; }
        else        { src = g_nw2T; rstr = 128; k0 = 0; }
        #pragma unroll
        for (int it = 0; it < 4; it++) {
            int idx = tid + it*256;
            int row = idx >> 3, seg = idx & 7;
            cpa16(dbuf + row*SBK + seg*8, src + (size_t)row*rstr + k0 + seg*8);
        }
        CP_COMMIT;
        const __half* bB = s_bb + (ct & 1)*BKB;
        #pragma unroll
        for (int kk = 0; kk < 64; kk += 16) {
            int kg = ct*64 + kk;
            uint32_t afr[4][4];
            #pragma unroll
            for (int mf = 0; mf < 4; mf++) LDSMA(afr[mf], s_a, SAn, wm*64 + mf*16, kg);
            uint32_t bfr[4][2];
            LDSMB2(bfr[0], bB, SBK, wn*32, kk);
            LDSMB2(bfr[2], bB, SBK, wn*32 + 16, kk);
            #pragma unroll
            for (int mf = 0; mf < 4; mf++)
                #pragma unroll
                for (int nf = 0; nf < 4; nf++)
                    mma_f16(acc[mf][nf], afr[mf], bfr[nf]);
        }
        CP_WAIT0;
        __syncthreads();
    }

    #pragma unroll
    for (int mf = 0; mf < 4; mf++) {
        int r0 = wm*64 + mf*16 + (lane >> 2);
        #pragma unroll
        for (int nf = 0; nf < 4; nf++) {
            int n = wn*32 + nf*8 + (lane & 3)*2;
            float b0 = nb1[n], b1 = nb1[n + 1];
            *(__half2*)(s_a + r0*SAn + n) =
                __floats2half2_rn(silu_f(acc[mf][nf][0] + b0), silu_f(acc[mf][nf][1] + b1));
            *(__half2*)(s_a + (r0 + 8)*SAn + n) =
                __floats2half2_rn(silu_f(acc[mf][nf][2] + b0), silu_f(acc[mf][nf][3] + b1));
            #pragma unroll
            for (int u = 0; u < 4; u++) acc[mf][nf][u] = 0.f;
        }
    }
    __syncthreads();

    for (int c = 0; c < 2; c++) {
        if (c == 0) {
            #pragma unroll
            for (int it = 0; it < 4; it++) {
                int idx = tid + it*256;
                int row = idx >> 3, seg = idx & 7;
                cpa16(s_bb + BKB + row*SBK + seg*8, g_nw2T + row*DD + 64 + seg*8);
            }
            CP_COMMIT;
        }
        const __half* bB = s_bb + (c & 1)*BKB;
        #pragma unroll
        for (int kk = 0; kk < 64; kk += 16) {
            int kg = c*64 + kk;
            uint32_t afr[4][4];
            #pragma unroll
            for (int mf = 0; mf < 4; mf++) LDSMA(afr[mf], s_a, SAn, wm*64 + mf*16, kg);
            uint32_t bfr[4][2];
            LDSMB2(bfr[0], bB, SBK, wn*32, kk);
            LDSMB2(bfr[2], bB, SBK, wn*32 + 16, kk);
            #pragma unroll
            for (int mf = 0; mf < 4; mf++)
                #pragma unroll
                for (int nf = 0; nf < 4; nf++)
                    mma_f16(acc[mf][nf], afr[mf], bfr[nf]);
        }
        if (c == 0) { CP_WAIT0; }
        __syncthreads();
    }

    #pragma unroll
    for (int mf = 0; mf < 4; mf++) {
        #pragma unroll
        for (int rr = 0; rr < 2; rr++) {
            int m = wm*64 + mf*16 + (lane >> 2) + rr*8;
            int n = n0 + m;
            if (n < NN) {
                const float* nfr = nfeat + (size_t)n*DD;
                float* orow = out + (size_t)n*DD;
                #pragma unroll
                for (int nf = 0; nf < 4; nf++) {
                    int col = wn*32 + nf*8 + (lane & 3)*2;
                    orow[col]     = nfr[col]     + silu_f(acc[mf][nf][rr*2 + 0] + nb2[col]);
                    orow[col + 1] = nfr[col + 1] + silu_f(acc[mf][nf][rr*2 + 1] + nb2[col + 1]);
                }
            }
        }
    }
}

// ---------------- launch ----------------
extern "C" void kernel_launch(void* const* d_in, const int* in_sizes, int n_in,
                              void* d_out, int out_size)
{
    const float* node_features = (const float*)d_in[0];
    const float* cond = (const float*)d_in[1];
    const int*   n2g  = (const int*)d_in[2];
    const float* frac = (const float*)d_in[3];
    const float* lat  = (const float*)d_in[4];
    const int*   edges= (const int*)d_in[5];
    const int*   e2g  = (const int*)d_in[6];
    const float* wq = (const float*)d_in[7];
    const float* bq = (const float*)d_in[8];
    const float* wk = (const float*)d_in[9];
    const float* bk = (const float*)d_in[10];
    const float* wv = (const float*)d_in[11];
    const float* bv = (const float*)d_in[12];
    const float* wo = (const float*)d_in[13];
    const float* bo = (const float*)d_in[14];
    const float* sw1= (const float*)d_in[15];
    const float* sb1= (const float*)d_in[16];
    const float* sw2= (const float*)d_in[17];
    const float* sb2= (const float*)d_in[18];
    const float* ew1= (const float*)d_in[19];
    const float* eb1= (const float*)d_in[20];
    const float* ew2= (const float*)d_in[21];
    const float* eb2= (const float*)d_in[22];
    const float* nw1= (const float*)d_in[23];
    const float* nb1= (const float*)d_in[24];
    const float* nw2= (const float*)d_in[25];
    const float* nb2= (const float*)d_in[26];
    float* out = (float*)d_out;

    const int attn_smem = (3*AT*SQh + 128*SBh + 2*BHB + AT*40 + 8*SBW2 + 3*16*KVROW) * 2
                        + (128 + 8 + AT*8) * 4;
    const int prep_smem = (128*SPh + 2*BKB) * 2;
    const int edge_smem = (TM*SAh + 2*BKB) * 2;
    const int node_smem = (TN*SAn + 2*BKB) * 2;
    cudaFuncSetAttribute(attn_kernel, cudaFuncAttributeMaxDynamicSharedMemorySize, attn_smem);
    cudaFuncSetAttribute(prep_kernel, cudaFuncAttributeMaxDynamicSharedMemorySize, prep_smem);
    cudaFuncSetAttribute(edge_kernel, cudaFuncAttributeMaxDynamicSharedMemorySize, edge_smem);
    cudaFuncSetAttribute(node_kernel, cudaFuncAttributeMaxDynamicSharedMemorySize, node_smem);

    convw_kernel<<<685, 256>>>(ew1, ew2, nw1, nw2, wq, wo, sw1, sw2, wk, wv, lat);
    prep_kernel<<<BB*TT/128, 256, prep_smem>>>(cond, bk, bv);
    attn_kernel<<<(NN + AT - 1) / AT, 256, attn_smem>>>(node_features, frac, n2g,
                                                        bq, bo, sb1, sb2);
    edge_kernel<<<EE / TM, 256, edge_smem>>>(frac, edges, e2g, eb1, eb2);
    node_kernel<<<(NN + TN - 1) / TN, 256, node_smem>>>(node_features, nb1, nb2, out);
}